// round 5
// baseline (speedup 1.0000x reference)
#include <cuda_runtime.h>
#include <cuda_bf16.h>
#include <math.h>

#define NN   50000
#define FIN  128
#define HIDD 256
#define NHD  4
#define DH   64
#define NE   400000
#define CATF 384
#define TTYP 2

// ---------------- scratch (device globals; no allocation allowed) ----------
static __device__ float g_z  [(size_t)NN*HIDD];
static __device__ float g_h  [(size_t)NN*HIDD];
static __device__ float g_x  [(size_t)NN*CATF];
static __device__ float g_scr[(size_t)NN*CATF];   // rst (256-wide) / agg (F-wide)
static __device__ float g_el [NN*NHD];
static __device__ float g_er [NN*NHD];
static __device__ float g_m  [NN*NHD];
static __device__ float g_den[NN*NHD];
static __device__ float g_e  [(size_t)NE*NHD];
static __device__ float g_ex [(size_t)NE*NHD];
static __device__ float g_stats[2*HIDD];
static __device__ float g_scale[HIDD];
static __device__ float g_shift[HIDD];
// packed bf16 hi/lo operand buffers
static __device__ unsigned int g_ah[(size_t)NN*(CATF/2)];   // A hi (max K=384)
static __device__ unsigned int g_al[(size_t)NN*(CATF/2)];   // A lo
static __device__ unsigned int g_fh[(size_t)NN*(FIN/2)];    // feats hi
static __device__ unsigned int g_fl[(size_t)NN*(FIN/2)];    // feats lo
static __device__ unsigned int g_wh[HIDD*(CATF/2)];         // W hi (transposed [N][K/2])
static __device__ unsigned int g_wl[HIDD*(CATF/2)];         // W lo

// ---------------- helpers --------------------------------------------------
__device__ __forceinline__ void red4(float* p, float a, float b, float c, float d) {
    asm volatile("red.global.add.v4.f32 [%0], {%1,%2,%3,%4};"
                 :: "l"(p), "f"(a), "f"(b), "f"(c), "f"(d) : "memory");
}

__device__ __forceinline__ void atomicMaxF(float* addr, float value) {
    if (value >= 0.f) atomicMax((int*)addr, __float_as_int(value));
    else              atomicMin((unsigned int*)addr, __float_as_uint(value));
}

__device__ __forceinline__ float lrelu(float v) { return v >= 0.f ? v : 0.2f * v; }

__device__ __forceinline__ unsigned int pack2(__nv_bfloat16 a, __nv_bfloat16 b) {
    return (unsigned int)__bfloat16_as_ushort(a) |
           ((unsigned int)__bfloat16_as_ushort(b) << 16);
}

__device__ __forceinline__ void split_bf(float v, __nv_bfloat16& h, __nv_bfloat16& l) {
    h = __float2bfloat16_rn(v);
    l = __float2bfloat16_rn(v - __bfloat162float(h));
}

// split 4 floats -> 2 packed hi uints + 2 packed lo uints
__device__ __forceinline__ void split4(float4 v, unsigned int* hp, unsigned int* lp) {
    __nv_bfloat16 h0, h1, h2, h3, l0, l1, l2, l3;
    split_bf(v.x, h0, l0); split_bf(v.y, h1, l1);
    split_bf(v.z, h2, l2); split_bf(v.w, h3, l3);
    hp[0] = pack2(h0, h1); hp[1] = pack2(h2, h3);
    lp[0] = pack2(l0, l1); lp[1] = pack2(l2, l3);
}

__device__ __forceinline__ void mma16816(float* c, const unsigned int* a, const unsigned int* b) {
    asm volatile(
        "mma.sync.aligned.m16n8k16.row.col.f32.bf16.bf16.f32 "
        "{%0,%1,%2,%3}, {%4,%5,%6,%7}, {%8,%9}, {%0,%1,%2,%3};"
        : "+f"(c[0]), "+f"(c[1]), "+f"(c[2]), "+f"(c[3])
        : "r"(a[0]), "r"(a[1]), "r"(a[2]), "r"(a[3]), "r"(b[0]), "r"(b[1]));
}

// ---------------- converters ----------------------------------------------
// A convert: fp32[n] -> packed hi/lo (pairs along last dim). n4 = elements/4.
__global__ void aconv_kernel(const float* __restrict__ A, unsigned int* __restrict__ H,
                             unsigned int* __restrict__ L, int n4) {
    int idx = blockIdx.x * blockDim.x + threadIdx.x;
    if (idx >= n4) return;
    float4 v = *(const float4*)(A + (size_t)idx * 4);
    unsigned int hp[2], lp[2];
    split4(v, hp, lp);
    *(uint2*)(H + (size_t)idx * 2) = make_uint2(hp[0], hp[1]);
    *(uint2*)(L + (size_t)idx * 2) = make_uint2(lp[0], lp[1]);
}

// W convert + transpose: W[K][256] -> WH/WL [256][K/2] packed pairs along K.
__global__ void wconv_kernel(const float* __restrict__ W, int K) {
    int idx = blockIdx.x * blockDim.x + threadIdx.x;
    int Kw = K / 2;
    if (idx >= HIDD * Kw) return;
    int n = idx / Kw;
    int kp = idx - n * Kw;
    float v0 = W[(size_t)(2 * kp) * HIDD + n];
    float v1 = W[(size_t)(2 * kp + 1) * HIDD + n];
    __nv_bfloat16 h0, h1, l0, l1;
    split_bf(v0, h0, l0); split_bf(v1, h1, l1);
    g_wh[idx] = pack2(h0, h1);
    g_wl[idx] = pack2(l0, l1);
}

// ---------------- tensor-core GEMM (preconverted operands) -----------------
// C = act(A @ W + bias); A as packed bf16 hi/lo [M][Kw], W as [256][Kw].
// Block 128x128, 8 warps of 64x32, K-tile 32 (16 uints).
#define SSTR 20
__global__ __launch_bounds__(256, 2)
void gemm_tc_kernel(const unsigned int* __restrict__ AHg, const unsigned int* __restrict__ ALg,
                    const unsigned int* __restrict__ BHg, const unsigned int* __restrict__ BLg,
                    const float* __restrict__ bias, float* __restrict__ C,
                    int M, int Kw, int ldc, int coff, int relu_flag) {
    __shared__ unsigned int AH[128 * SSTR];
    __shared__ unsigned int AL[128 * SSTR];
    __shared__ unsigned int BH[128 * SSTR];
    __shared__ unsigned int BL[128 * SSTR];

    int tid = threadIdx.x;
    int lane = tid & 31, wid = tid >> 5;
    int lm = lane >> 2, lc = lane & 3;
    int m0 = (wid >> 2) * 64;
    int n0w = (wid & 3) * 32;
    int rowBase = blockIdx.y * 128;
    int colBase = blockIdx.x * 128;

    float acc[16][4];
#pragma unroll
    for (int i = 0; i < 16; i++)
#pragma unroll
        for (int j = 0; j < 4; j++) acc[i][j] = 0.f;

    int nkt = Kw / 16;
    for (int kt = 0; kt < nkt; kt++) {
        int k0w = kt * 16;
        // ---- stage tiles: 512 uint4 per buffer, 2 per thread ----
#pragma unroll
        for (int i = 0; i < 2; i++) {
            int p = tid + i * 256;
            int m = p >> 2;
            int c = (p & 3) * 4;
            int row = rowBase + m;
            uint4 va = make_uint4(0u, 0u, 0u, 0u), vb = va;
            if (row < M) {
                va = *(const uint4*)(AHg + (size_t)row * Kw + k0w + c);
                vb = *(const uint4*)(ALg + (size_t)row * Kw + k0w + c);
            }
            *(uint4*)&AH[m * SSTR + c] = va;
            *(uint4*)&AL[m * SSTR + c] = vb;
            int n = colBase + m;
            *(uint4*)&BH[m * SSTR + c] = *(const uint4*)(BHg + (size_t)n * Kw + k0w + c);
            *(uint4*)&BL[m * SSTR + c] = *(const uint4*)(BLg + (size_t)n * Kw + k0w + c);
        }
        __syncthreads();
        // ---- compute: two k16 steps ----
#pragma unroll
        for (int kk = 0; kk < 2; kk++) {
            int kw = kk * 8;
            unsigned int ah[4][4], al[4][4], bh[4][2], bl[4][2];
#pragma unroll
            for (int mi = 0; mi < 4; mi++) {
                int r = m0 + mi * 16 + lm;
                int w0 = r * SSTR + kw + lc;
                int w1 = (r + 8) * SSTR + kw + lc;
                ah[mi][0] = AH[w0]; ah[mi][1] = AH[w1];
                ah[mi][2] = AH[w0 + 4]; ah[mi][3] = AH[w1 + 4];
                al[mi][0] = AL[w0]; al[mi][1] = AL[w1];
                al[mi][2] = AL[w0 + 4]; al[mi][3] = AL[w1 + 4];
            }
#pragma unroll
            for (int ni = 0; ni < 4; ni++) {
                int n = n0w + ni * 8 + lm;
                int w0 = n * SSTR + kw + lc;
                bh[ni][0] = BH[w0]; bh[ni][1] = BH[w0 + 4];
                bl[ni][0] = BL[w0]; bl[ni][1] = BL[w0 + 4];
            }
#pragma unroll
            for (int mi = 0; mi < 4; mi++)
#pragma unroll
                for (int ni = 0; ni < 4; ni++) {
                    float* c = acc[mi * 4 + ni];
                    mma16816(c, ah[mi], bh[ni]);
                    mma16816(c, ah[mi], bl[ni]);
                    mma16816(c, al[mi], bh[ni]);
                }
        }
        __syncthreads();
    }

    // ---- epilogue ----
#pragma unroll
    for (int mi = 0; mi < 4; mi++) {
#pragma unroll
        for (int ni = 0; ni < 4; ni++) {
            float* c = acc[mi * 4 + ni];
            int r0 = rowBase + m0 + mi * 16 + lm;
            int r1 = r0 + 8;
            int col = colBase + n0w + ni * 8 + lc * 2;
            float b0 = bias ? bias[col] : 0.f;
            float b1 = bias ? bias[col + 1] : 0.f;
            float v0 = c[0] + b0, v1 = c[1] + b1;
            float v2 = c[2] + b0, v3 = c[3] + b1;
            if (relu_flag) {
                v0 = fmaxf(v0, 0.f); v1 = fmaxf(v1, 0.f);
                v2 = fmaxf(v2, 0.f); v3 = fmaxf(v3, 0.f);
            }
            if (r0 < M) *(float2*)(C + (size_t)r0 * ldc + coff + col) = make_float2(v0, v1);
            if (r1 < M) *(float2*)(C + (size_t)r1 * ldc + coff + col) = make_float2(v2, v3);
        }
    }
}

// ---------------- GAT pieces -----------------------------------------------
__global__ void elz_kernel(const float* __restrict__ z,
                           const float* __restrict__ al, const float* __restrict__ ar) {
    int n = blockIdx.x;
    int w = threadIdx.x >> 5;
    int lane = threadIdx.x & 31;
    const float* zp = z + (size_t)n * HIDD + w * DH;
    float z0 = zp[lane], z1 = zp[lane + 32];
    float a0 = al[w * DH + lane], a1 = al[w * DH + lane + 32];
    float b0 = ar[w * DH + lane], b1 = ar[w * DH + lane + 32];
    float el = z0 * a0 + z1 * a1;
    float er = z0 * b0 + z1 * b1;
#pragma unroll
    for (int off = 16; off; off >>= 1) {
        el += __shfl_down_sync(0xffffffffu, el, off);
        er += __shfl_down_sync(0xffffffffu, er, off);
    }
    if (lane == 0) { g_el[n * NHD + w] = el; g_er[n * NHD + w] = er; }
}

__global__ void init_nh_kernel() {
    int i = blockIdx.x * blockDim.x + threadIdx.x;
    if (i < NN * NHD) { g_m[i] = -INFINITY; g_den[i] = 0.f; }
}

__global__ void edge_max_kernel(const int* __restrict__ src, const int* __restrict__ dst) {
    int e = blockIdx.x * blockDim.x + threadIdx.x;
    if (e >= NE) return;
    int s = src[e], d = dst[e];
    float4 elv = *(const float4*)(g_el + s * NHD);
    float4 erv = *(const float4*)(g_er + d * NHD);
    float4 ev;
    ev.x = lrelu(elv.x + erv.x);
    ev.y = lrelu(elv.y + erv.y);
    ev.z = lrelu(elv.z + erv.z);
    ev.w = lrelu(elv.w + erv.w);
    *(float4*)(g_e + (size_t)e * NHD) = ev;
    float* mp = g_m + d * NHD;
    atomicMaxF(mp + 0, ev.x);
    atomicMaxF(mp + 1, ev.y);
    atomicMaxF(mp + 2, ev.z);
    atomicMaxF(mp + 3, ev.w);
}

__global__ void edge_exp_kernel(const int* __restrict__ dst) {
    int e = blockIdx.x * blockDim.x + threadIdx.x;
    if (e >= NE) return;
    int d = dst[e];
    float4 ev = *(const float4*)(g_e + (size_t)e * NHD);
    float4 mv = *(const float4*)(g_m + d * NHD);
    float4 xv = make_float4(__expf(ev.x - mv.x), __expf(ev.y - mv.y),
                            __expf(ev.z - mv.z), __expf(ev.w - mv.w));
    *(float4*)(g_ex + (size_t)e * NHD) = xv;
    red4(g_den + d * NHD, xv.x, xv.y, xv.z, xv.w);
}

// warp per edge: scatter a * z[src] into rst[dst]
__global__ void edge_msg_kernel(const int* __restrict__ src, const int* __restrict__ dst,
                                const float* __restrict__ zin, float* __restrict__ rst) {
    int gt = blockIdx.x * blockDim.x + threadIdx.x;
    int e = gt >> 5;
    if (e >= NE) return;
    int lane = threadIdx.x & 31;
    int s = src[e], d = dst[e];
    float4 xv = *(const float4*)(g_ex + (size_t)e * NHD);
    float4 dv = *(const float4*)(g_den + d * NHD);
    float ax = xv.x / fmaxf(dv.x, 1e-9f);
    float ay = xv.y / fmaxf(dv.y, 1e-9f);
    float az = xv.z / fmaxf(dv.z, 1e-9f);
    float aw = xv.w / fmaxf(dv.w, 1e-9f);
    float a = (lane < 16) ? (lane < 8 ? ax : ay) : (lane < 24 ? az : aw);
    const float* zp = zin + (size_t)s * HIDD + lane * 8;
    float* rp = rst + (size_t)d * HIDD + lane * 8;
    float4 z0 = *(const float4*)zp;
    float4 z1 = *(const float4*)(zp + 4);
    red4(rp,     a * z0.x, a * z0.y, a * z0.z, a * z0.w);
    red4(rp + 4, a * z1.x, a * z1.y, a * z1.z, a * z1.w);
}

// GAT finalize: h = relu(rst + b); also emit packed bf16 hi/lo for next GEMM
__global__ void gat_fin_kernel(const float* __restrict__ rst, const float* __restrict__ b,
                               float* __restrict__ hout) {
    int idx = blockIdx.x * blockDim.x + threadIdx.x;
    int i4 = idx * 4;
    if (i4 >= NN * HIDD) return;
    int c = i4 & (HIDD - 1);
    float4 r = *(const float4*)(rst + i4);
    float4 bb = *(const float4*)(b + c);
    float4 v;
    v.x = fmaxf(r.x + bb.x, 0.f);
    v.y = fmaxf(r.y + bb.y, 0.f);
    v.z = fmaxf(r.z + bb.z, 0.f);
    v.w = fmaxf(r.w + bb.w, 0.f);
    *(float4*)(hout + i4) = v;
    unsigned int hp[2], lp[2];
    split4(v, hp, lp);
    *(uint2*)(g_ah + (size_t)idx * 2) = make_uint2(hp[0], hp[1]);
    *(uint2*)(g_al + (size_t)idx * 2) = make_uint2(lp[0], lp[1]);
}

// ---------------- concat + GIN pieces --------------------------------------
__global__ void concat_kernel(const float* __restrict__ h, const float* __restrict__ feats,
                              float* __restrict__ x) {
    int idx = blockIdx.x * blockDim.x + threadIdx.x;
    int i4 = idx * 4;
    if (i4 >= NN * CATF) return;
    int n = i4 / CATF;
    int c = i4 % CATF;
    float4 v = (c < HIDD) ? *(const float4*)(h + (size_t)n * HIDD + c)
                          : *(const float4*)(feats + (size_t)n * FIN + (c - HIDD));
    *(float4*)(x + i4) = v;
}

__global__ void edge_agg_kernel(const float* __restrict__ hin, const int* __restrict__ src,
                                const int* __restrict__ dst, float* __restrict__ agg, int F) {
    int gt = blockIdx.x * blockDim.x + threadIdx.x;
    int e = gt >> 5;
    if (e >= NE) return;
    int lane = threadIdx.x & 31;
    int s = src[e], d = dst[e];
    const float* hp = hin + (size_t)s * F;
    float* ap = agg + (size_t)d * F;
    for (int f = lane * 4; f < F; f += 128) {
        float4 v = *(const float4*)(hp + f);
        red4(ap + f, v.x, v.y, v.z, v.w);
    }
}

// x = (1+eps)h + agg; also emit packed bf16 hi/lo
__global__ void combine_kernel(const float* __restrict__ hin, const float* __restrict__ agg,
                               const float* __restrict__ epsp, float* __restrict__ xout, int n) {
    int idx = blockIdx.x * blockDim.x + threadIdx.x;
    int i4 = idx * 4;
    if (i4 >= n) return;
    float e = 1.f + epsp[0];
    float4 hv = *(const float4*)(hin + i4);
    float4 av = *(const float4*)(agg + i4);
    float4 v = make_float4(e * hv.x + av.x, e * hv.y + av.y, e * hv.z + av.z, e * hv.w + av.w);
    *(float4*)(xout + i4) = v;
    unsigned int hp[2], lp[2];
    split4(v, hp, lp);
    *(uint2*)(g_ah + (size_t)idx * 2) = make_uint2(hp[0], hp[1]);
    *(uint2*)(g_al + (size_t)idx * 2) = make_uint2(lp[0], lp[1]);
}

__global__ void stats_kernel(const float* __restrict__ y) {
    int col = threadIdx.x;
    float s = 0.f, s2 = 0.f;
    for (int r = blockIdx.x; r < NN; r += gridDim.x) {
        float v = y[(size_t)r * HIDD + col];
        s += v; s2 += v * v;
    }
    atomicAdd(&g_stats[col], s);
    atomicAdd(&g_stats[HIDD + col], s2);
}

__global__ void bnfin_kernel(const float* __restrict__ g1, const float* __restrict__ be1) {
    int c = threadIdx.x;
    float inv = 1.f / (float)NN;
    float mu = g_stats[c] * inv;
    float var = g_stats[HIDD + c] * inv - mu * mu;
    float rstd = rsqrtf(var + 1e-5f);
    float sc = g1[c] * rstd;
    g_scale[c] = sc;
    g_shift[c] = be1[c] - mu * sc;
}

// y = relu(y*scale + shift); also emit packed bf16 hi/lo
__global__ void bnrelu_kernel(float* __restrict__ y) {
    int idx = blockIdx.x * blockDim.x + threadIdx.x;
    int i4 = idx * 4;
    if (i4 >= NN * HIDD) return;
    int c = i4 & (HIDD - 1);
    float4 v = *(const float4*)(y + i4);
    float4 sc = *(const float4*)(g_scale + c);
    float4 sh = *(const float4*)(g_shift + c);
    v.x = fmaxf(v.x * sc.x + sh.x, 0.f);
    v.y = fmaxf(v.y * sc.y + sh.y, 0.f);
    v.z = fmaxf(v.z * sc.z + sh.z, 0.f);
    v.w = fmaxf(v.w * sc.w + sh.w, 0.f);
    *(float4*)(y + i4) = v;
    unsigned int hp[2], lp[2];
    split4(v, hp, lp);
    *(uint2*)(g_ah + (size_t)idx * 2) = make_uint2(hp[0], hp[1]);
    *(uint2*)(g_al + (size_t)idx * 2) = make_uint2(lp[0], lp[1]);
}

__global__ void zero_kernel(float* __restrict__ p, int n) {
    int idx = blockIdx.x * blockDim.x + threadIdx.x;
    int i4 = idx * 4;
    if (i4 >= n) return;
    *(float4*)(p + i4) = make_float4(0.f, 0.f, 0.f, 0.f);
}

// ---------------- host orchestration ---------------------------------------
static inline int blk4(int n) { return (n / 4 + 255) / 256; }

static void gemm(const unsigned int* AH, const unsigned int* AL,
                 const float* Wsrc, const float* b, float* C,
                 int K, int relu, int ldc = HIDD, int coff = 0) {
    unsigned int *wh, *wl;
    cudaGetSymbolAddress((void**)&wh, g_wh);
    cudaGetSymbolAddress((void**)&wl, g_wl);
    int wtot = HIDD * (K / 2);
    wconv_kernel<<<(wtot + 255) / 256, 256>>>(Wsrc, K);
    dim3 grid(HIDD / 128, (NN + 127) / 128);
    gemm_tc_kernel<<<grid, 256>>>(AH, AL, wh, wl, b, C, NN, K / 2, ldc, coff, relu);
}

static void run_gat(const float* z, const float* al, const float* ar, const float* b,
                    const int* s, const int* d, float* rst, float* hout) {
    elz_kernel<<<NN, 128>>>(z, al, ar);
    init_nh_kernel<<<(NN * NHD + 255) / 256, 256>>>();
    edge_max_kernel<<<(NE + 255) / 256, 256>>>(s, d);
    edge_exp_kernel<<<(NE + 255) / 256, 256>>>(d);
    zero_kernel<<<blk4(NN * HIDD), 256>>>(rst, NN * HIDD);
    edge_msg_kernel<<<(NE * 32 + 255) / 256, 256>>>(s, d, z, rst);
    gat_fin_kernel<<<blk4(NN * HIDD), 256>>>(rst, b, hout);
}

static void run_gin(const float* hin, int F, const int* s, const int* d,
                    const float* eps, const float* W1, const float* b1,
                    const float* g1, const float* be1, const float* W2, const float* b2,
                    float* agg, float* xbuf, float* ybuf, float* hout, float* statsp,
                    const unsigned int* ah, const unsigned int* al,
                    int ldc, int coff) {
    zero_kernel<<<blk4(NN * F), 256>>>(agg, NN * F);
    edge_agg_kernel<<<(NE * 32 + 255) / 256, 256>>>(hin, s, d, agg, F);
    combine_kernel<<<blk4(NN * F), 256>>>(hin, agg, eps, xbuf, NN * F);
    gemm(ah, al, W1, b1, ybuf, F, 0);
    zero_kernel<<<1, 128>>>(statsp, 2 * HIDD);
    stats_kernel<<<512, HIDD>>>(ybuf);
    bnfin_kernel<<<1, HIDD>>>(g1, be1);
    bnrelu_kernel<<<blk4(NN * HIDD), 256>>>(ybuf);
    gemm(ah, al, W2, b2, hout, HIDD, 1, ldc, coff);
}

extern "C" void kernel_launch(void* const* d_in, const int* in_sizes, int n_in,
                              void* d_out, int out_size) {
    const float* feats = (const float*)d_in[0];
    const int* src[2] = { (const int*)d_in[1], (const int*)d_in[3] };
    const int* dst[2] = { (const int*)d_in[2], (const int*)d_in[4] };
    const float* gat0_W   = (const float*)d_in[5];
    const float* gat0_al  = (const float*)d_in[6];
    const float* gat0_ar  = (const float*)d_in[7];
    const float* gat0_b   = (const float*)d_in[8];
    const float* gat1_W   = (const float*)d_in[9];
    const float* gat1_al  = (const float*)d_in[10];
    const float* gat1_ar  = (const float*)d_in[11];
    const float* gat1_b   = (const float*)d_in[12];
    const float* gin0_eps = (const float*)d_in[13];
    const float* gin0_W1  = (const float*)d_in[14];
    const float* gin0_b1  = (const float*)d_in[15];
    const float* gin0_g1  = (const float*)d_in[16];
    const float* gin0_be1 = (const float*)d_in[17];
    const float* gin0_W2  = (const float*)d_in[18];
    const float* gin0_b2  = (const float*)d_in[19];
    const float* gin1_eps = (const float*)d_in[20];
    const float* gin1_W1  = (const float*)d_in[21];
    const float* gin1_b1  = (const float*)d_in[22];
    const float* gin1_g1  = (const float*)d_in[23];
    const float* gin1_be1 = (const float*)d_in[24];
    const float* gin1_W2  = (const float*)d_in[25];
    const float* gin1_b2  = (const float*)d_in[26];
    float* out = (float*)d_out;

    float *z, *h, *x, *scr, *statsp;
    unsigned int *ah, *al, *fh, *fl;
    cudaGetSymbolAddress((void**)&z, g_z);
    cudaGetSymbolAddress((void**)&h, g_h);
    cudaGetSymbolAddress((void**)&x, g_x);
    cudaGetSymbolAddress((void**)&scr, g_scr);
    cudaGetSymbolAddress((void**)&statsp, g_stats);
    cudaGetSymbolAddress((void**)&ah, g_ah);
    cudaGetSymbolAddress((void**)&al, g_al);
    cudaGetSymbolAddress((void**)&fh, g_fh);
    cudaGetSymbolAddress((void**)&fl, g_fl);

    // convert feats once
    aconv_kernel<<<blk4(NN * FIN), 256>>>(feats, fh, fl, NN * FIN / 4);

    for (int t = 0; t < TTYP; t++) {
        // GAT layer 0: z = feats @ W
        gemm(fh, fl, gat0_W + (size_t)t * FIN * HIDD, nullptr, z, FIN, 0);
        run_gat(z, gat0_al + t * NHD * DH, gat0_ar + t * NHD * DH,
                gat0_b + t * HIDD, src[t], dst[t], scr, h);   // emits h hi/lo
        // GAT layer 1
        gemm(ah, al, gat1_W + (size_t)t * HIDD * HIDD, nullptr, z, HIDD, 0);
        run_gat(z, gat1_al + t * NHD * DH, gat1_ar + t * NHD * DH,
                gat1_b + t * HIDD, src[t], dst[t], scr, h);   // emits h hi/lo
        // skip-concat (fp32 only; combine will emit hi/lo of its output)
        concat_kernel<<<blk4(NN * CATF), 256>>>(h, feats, x);
        // GIN layer 0 (F = 384)
        run_gin(x, CATF, src[t], dst[t], gin0_eps + t,
                gin0_W1 + (size_t)t * CATF * HIDD, gin0_b1 + t * HIDD,
                gin0_g1 + t * HIDD, gin0_be1 + t * HIDD,
                gin0_W2 + (size_t)t * CATF * 0 + (size_t)t * HIDD * HIDD, gin0_b2 + t * HIDD,
                scr, x, z, h, statsp, ah, al, HIDD, 0);
        // GIN layer 1 (F = 256) — final GEMM writes into the strided output
        run_gin(h, HIDD, src[t], dst[t], gin1_eps + t,
                gin1_W1 + (size_t)t * HIDD * HIDD, gin1_b1 + t * HIDD,
                gin1_g1 + t * HIDD, gin1_be1 + t * HIDD,
                gin1_W2 + (size_t)t * HIDD * HIDD, gin1_b2 + t * HIDD,
                scr, x, z, out, statsp, ah, al, TTYP * HIDD, t * HIDD);
    }
}

// round 6
// speedup vs baseline: 1.1053x; 1.1053x over previous
#include <cuda_runtime.h>
#include <cuda_bf16.h>
#include <math.h>

#define NN   50000
#define FIN  128
#define HIDD 256
#define NHD  4
#define DH   64
#define NE   400000
#define CATF 384
#define TTYP 2
#define KWMAX (CATF/2)

// ---------------- per-type scratch (device globals) ------------------------
static __device__ float g_z  [TTYP][(size_t)NN*HIDD];
static __device__ float g_h  [TTYP][(size_t)NN*HIDD];
static __device__ float g_x  [TTYP][(size_t)NN*CATF];
static __device__ float g_scr[TTYP][(size_t)NN*CATF];
static __device__ float g_el [TTYP][NN*NHD];
static __device__ float g_er [TTYP][NN*NHD];
static __device__ float g_m  [TTYP][NN*NHD];
static __device__ float g_den[TTYP][NN*NHD];
static __device__ float g_e  [TTYP][(size_t)NE*NHD];
static __device__ float g_ex [TTYP][(size_t)NE*NHD];
static __device__ float g_stats[TTYP][2*HIDD];
static __device__ float g_scale[TTYP][HIDD];
static __device__ float g_shift[TTYP][HIDD];
static __device__ unsigned int g_wh[TTYP][HIDD*KWMAX];  // W hi, transposed [256][K/2]
static __device__ unsigned int g_wl[TTYP][HIDD*KWMAX];  // W lo

// ---------------- streams/events (created once, statically) ----------------
namespace {
struct SI {
    cudaStream_t s[TTYP];
    cudaEvent_t e0, e1, e2;
    SI() {
        cudaStreamCreateWithFlags(&s[0], cudaStreamNonBlocking);
        cudaStreamCreateWithFlags(&s[1], cudaStreamNonBlocking);
        cudaEventCreateWithFlags(&e0, cudaEventDisableTiming);
        cudaEventCreateWithFlags(&e1, cudaEventDisableTiming);
        cudaEventCreateWithFlags(&e2, cudaEventDisableTiming);
    }
};
SI g_si;
}

// ---------------- helpers --------------------------------------------------
__device__ __forceinline__ void red4(float* p, float a, float b, float c, float d) {
    asm volatile("red.global.add.v4.f32 [%0], {%1,%2,%3,%4};"
                 :: "l"(p), "f"(a), "f"(b), "f"(c), "f"(d) : "memory");
}

__device__ __forceinline__ void atomicMaxF(float* addr, float value) {
    if (value >= 0.f) atomicMax((int*)addr, __float_as_int(value));
    else              atomicMin((unsigned int*)addr, __float_as_uint(value));
}

__device__ __forceinline__ float lrelu(float v) { return v >= 0.f ? v : 0.2f * v; }

__device__ __forceinline__ unsigned int pack2(__nv_bfloat16 a, __nv_bfloat16 b) {
    return (unsigned int)__bfloat16_as_ushort(a) |
           ((unsigned int)__bfloat16_as_ushort(b) << 16);
}

__device__ __forceinline__ void split_bf(float v, __nv_bfloat16& h, __nv_bfloat16& l) {
    h = __float2bfloat16_rn(v);
    l = __float2bfloat16_rn(v - __bfloat162float(h));
}

__device__ __forceinline__ void mma16816(float* c, const unsigned int* a, const unsigned int* b) {
    asm volatile(
        "mma.sync.aligned.m16n8k16.row.col.f32.bf16.bf16.f32 "
        "{%0,%1,%2,%3}, {%4,%5,%6,%7}, {%8,%9}, {%0,%1,%2,%3};"
        : "+f"(c[0]), "+f"(c[1]), "+f"(c[2]), "+f"(c[3])
        : "r"(a[0]), "r"(a[1]), "r"(a[2]), "r"(a[3]), "r"(b[0]), "r"(b[1]));
}

// W convert + transpose: W[K][256] -> wh/wl [256][K/2] packed pairs along K.
__global__ void wconv_kernel(const float* __restrict__ W, int K,
                             unsigned int* __restrict__ wh, unsigned int* __restrict__ wl) {
    int idx = blockIdx.x * blockDim.x + threadIdx.x;
    int Kw = K / 2;
    if (idx >= HIDD * Kw) return;
    int n = idx / Kw;
    int kp = idx - n * Kw;
    float v0 = W[(size_t)(2 * kp) * HIDD + n];
    float v1 = W[(size_t)(2 * kp + 1) * HIDD + n];
    __nv_bfloat16 h0, h1, l0, l1;
    split_bf(v0, h0, l0); split_bf(v1, h1, l1);
    wh[idx] = pack2(h0, h1);
    wl[idx] = pack2(l0, l1);
}

// ---------------- tensor-core GEMM -----------------------------------------
// C = act(A[M,K] @ W + bias); A fp32 (converted in-kernel), W preconverted.
// Block 128x128, 8 warps of 64x32, K-tile 32.
#define SSTR 20
__global__ __launch_bounds__(256, 2)
void gemm_tc_kernel(const float* __restrict__ A,
                    const unsigned int* __restrict__ BHg, const unsigned int* __restrict__ BLg,
                    const float* __restrict__ bias, float* __restrict__ C,
                    int M, int K, int ldc, int coff, int relu_flag) {
    __shared__ unsigned int AH[128 * SSTR];
    __shared__ unsigned int AL[128 * SSTR];
    __shared__ unsigned int BH[128 * SSTR];
    __shared__ unsigned int BL[128 * SSTR];

    int tid = threadIdx.x;
    int lane = tid & 31, wid = tid >> 5;
    int lm = lane >> 2, lc = lane & 3;
    int m0 = (wid >> 2) * 64;
    int n0w = (wid & 3) * 32;
    int rowBase = blockIdx.y * 128;
    int colBase = blockIdx.x * 128;
    int Kw = K / 2;

    float acc[16][4];
#pragma unroll
    for (int i = 0; i < 16; i++)
#pragma unroll
        for (int j = 0; j < 4; j++) acc[i][j] = 0.f;

    int nkt = K / 32;
    for (int kt = 0; kt < nkt; kt++) {
        int k0 = kt * 32;
        int k0w = kt * 16;
        // ---- stage A tile (128 x 32 fp32 -> bf16 hi/lo split in-kernel) ----
#pragma unroll
        for (int i = 0; i < 4; i++) {
            int pos = tid + i * 256;
            int m = pos >> 3;
            int k = (pos & 7) * 4;
            int row = rowBase + m;
            float4 v = make_float4(0.f, 0.f, 0.f, 0.f);
            if (row < M) v = *(const float4*)(A + (size_t)row * K + k0 + k);
            __nv_bfloat16 h0, h1, h2, h3, l0, l1, l2, l3;
            split_bf(v.x, h0, l0); split_bf(v.y, h1, l1);
            split_bf(v.z, h2, l2); split_bf(v.w, h3, l3);
            int w = m * SSTR + (k >> 1);
            AH[w]     = pack2(h0, h1);
            AH[w + 1] = pack2(h2, h3);
            AL[w]     = pack2(l0, l1);
            AL[w + 1] = pack2(l2, l3);
        }
        // ---- stage B tiles: straight uint4 copy of preconverted W ----
#pragma unroll
        for (int i = 0; i < 2; i++) {
            int p = tid + i * 256;
            int n = p >> 2;
            int c = (p & 3) * 4;
            *(uint4*)&BH[n * SSTR + c] = *(const uint4*)(BHg + (size_t)(colBase + n) * Kw + k0w + c);
            *(uint4*)&BL[n * SSTR + c] = *(const uint4*)(BLg + (size_t)(colBase + n) * Kw + k0w + c);
        }
        __syncthreads();
        // ---- compute: two k16 steps ----
#pragma unroll
        for (int kk = 0; kk < 2; kk++) {
            int kw = kk * 8;
            unsigned int ah[4][4], al[4][4], bh[4][2], bl[4][2];
#pragma unroll
            for (int mi = 0; mi < 4; mi++) {
                int r = m0 + mi * 16 + lm;
                int w0 = r * SSTR + kw + lc;
                int w1 = (r + 8) * SSTR + kw + lc;
                ah[mi][0] = AH[w0]; ah[mi][1] = AH[w1];
                ah[mi][2] = AH[w0 + 4]; ah[mi][3] = AH[w1 + 4];
                al[mi][0] = AL[w0]; al[mi][1] = AL[w1];
                al[mi][2] = AL[w0 + 4]; al[mi][3] = AL[w1 + 4];
            }
#pragma unroll
            for (int ni = 0; ni < 4; ni++) {
                int n = n0w + ni * 8 + lm;
                int w0 = n * SSTR + kw + lc;
                bh[ni][0] = BH[w0]; bh[ni][1] = BH[w0 + 4];
                bl[ni][0] = BL[w0]; bl[ni][1] = BL[w0 + 4];
            }
#pragma unroll
            for (int mi = 0; mi < 4; mi++)
#pragma unroll
                for (int ni = 0; ni < 4; ni++) {
                    float* c = acc[mi * 4 + ni];
                    mma16816(c, ah[mi], bh[ni]);
                    mma16816(c, ah[mi], bl[ni]);
                    mma16816(c, al[mi], bh[ni]);
                }
        }
        __syncthreads();
    }

    // ---- epilogue ----
#pragma unroll
    for (int mi = 0; mi < 4; mi++) {
#pragma unroll
        for (int ni = 0; ni < 4; ni++) {
            float* c = acc[mi * 4 + ni];
            int r0 = rowBase + m0 + mi * 16 + lm;
            int r1 = r0 + 8;
            int col = colBase + n0w + ni * 8 + lc * 2;
            float b0 = bias ? bias[col] : 0.f;
            float b1 = bias ? bias[col + 1] : 0.f;
            float v0 = c[0] + b0, v1 = c[1] + b1;
            float v2 = c[2] + b0, v3 = c[3] + b1;
            if (relu_flag) {
                v0 = fmaxf(v0, 0.f); v1 = fmaxf(v1, 0.f);
                v2 = fmaxf(v2, 0.f); v3 = fmaxf(v3, 0.f);
            }
            if (r0 < M) *(float2*)(C + (size_t)r0 * ldc + coff + col) = make_float2(v0, v1);
            if (r1 < M) *(float2*)(C + (size_t)r1 * ldc + coff + col) = make_float2(v2, v3);
        }
    }
}

// ---------------- GAT pieces -----------------------------------------------
__global__ void elz_kernel(const float* __restrict__ z,
                           const float* __restrict__ al, const float* __restrict__ ar,
                           float* __restrict__ elp, float* __restrict__ erp) {
    int n = blockIdx.x;
    int w = threadIdx.x >> 5;
    int lane = threadIdx.x & 31;
    const float* zp = z + (size_t)n * HIDD + w * DH;
    float z0 = zp[lane], z1 = zp[lane + 32];
    float a0 = al[w * DH + lane], a1 = al[w * DH + lane + 32];
    float b0 = ar[w * DH + lane], b1 = ar[w * DH + lane + 32];
    float el = z0 * a0 + z1 * a1;
    float er = z0 * b0 + z1 * b1;
#pragma unroll
    for (int off = 16; off; off >>= 1) {
        el += __shfl_down_sync(0xffffffffu, el, off);
        er += __shfl_down_sync(0xffffffffu, er, off);
    }
    if (lane == 0) { elp[n * NHD + w] = el; erp[n * NHD + w] = er; }
}

__global__ void init_nh_kernel(float* __restrict__ m, float* __restrict__ den) {
    int i = blockIdx.x * blockDim.x + threadIdx.x;
    if (i < NN * NHD) { m[i] = -INFINITY; den[i] = 0.f; }
}

__global__ void edge_max_kernel(const int* __restrict__ src, const int* __restrict__ dst,
                                const float* __restrict__ elp, const float* __restrict__ erp,
                                float* __restrict__ e, float* __restrict__ m) {
    int ei = blockIdx.x * blockDim.x + threadIdx.x;
    if (ei >= NE) return;
    int s = src[ei], d = dst[ei];
    float4 elv = *(const float4*)(elp + s * NHD);
    float4 erv = *(const float4*)(erp + d * NHD);
    float4 ev;
    ev.x = lrelu(elv.x + erv.x);
    ev.y = lrelu(elv.y + erv.y);
    ev.z = lrelu(elv.z + erv.z);
    ev.w = lrelu(elv.w + erv.w);
    *(float4*)(e + (size_t)ei * NHD) = ev;
    float* mp = m + d * NHD;
    atomicMaxF(mp + 0, ev.x);
    atomicMaxF(mp + 1, ev.y);
    atomicMaxF(mp + 2, ev.z);
    atomicMaxF(mp + 3, ev.w);
}

__global__ void edge_exp_kernel(const int* __restrict__ dst,
                                const float* __restrict__ e, const float* __restrict__ m,
                                float* __restrict__ ex, float* __restrict__ den) {
    int ei = blockIdx.x * blockDim.x + threadIdx.x;
    if (ei >= NE) return;
    int d = dst[ei];
    float4 ev = *(const float4*)(e + (size_t)ei * NHD);
    float4 mv = *(const float4*)(m + d * NHD);
    float4 xv = make_float4(__expf(ev.x - mv.x), __expf(ev.y - mv.y),
                            __expf(ev.z - mv.z), __expf(ev.w - mv.w));
    *(float4*)(ex + (size_t)ei * NHD) = xv;
    red4(den + d * NHD, xv.x, xv.y, xv.z, xv.w);
}

__global__ void edge_msg_kernel(const int* __restrict__ src, const int* __restrict__ dst,
                                const float* __restrict__ zin,
                                const float* __restrict__ ex, const float* __restrict__ den,
                                float* __restrict__ rst) {
    int gt = blockIdx.x * blockDim.x + threadIdx.x;
    int e = gt >> 5;
    if (e >= NE) return;
    int lane = threadIdx.x & 31;
    int s = src[e], d = dst[e];
    float4 xv = *(const float4*)(ex + (size_t)e * NHD);
    float4 dv = *(const float4*)(den + d * NHD);
    float ax = xv.x / fmaxf(dv.x, 1e-9f);
    float ay = xv.y / fmaxf(dv.y, 1e-9f);
    float az = xv.z / fmaxf(dv.z, 1e-9f);
    float aw = xv.w / fmaxf(dv.w, 1e-9f);
    float a = (lane < 16) ? (lane < 8 ? ax : ay) : (lane < 24 ? az : aw);
    const float* zp = zin + (size_t)s * HIDD + lane * 8;
    float* rp = rst + (size_t)d * HIDD + lane * 8;
    float4 z0 = *(const float4*)zp;
    float4 z1 = *(const float4*)(zp + 4);
    red4(rp,     a * z0.x, a * z0.y, a * z0.z, a * z0.w);
    red4(rp + 4, a * z1.x, a * z1.y, a * z1.z, a * z1.w);
}

__global__ void gat_fin_kernel(const float* __restrict__ rst, const float* __restrict__ b,
                               float* __restrict__ hout) {
    int idx = blockIdx.x * blockDim.x + threadIdx.x;
    int i4 = idx * 4;
    if (i4 >= NN * HIDD) return;
    int c = i4 & (HIDD - 1);
    float4 r = *(const float4*)(rst + i4);
    float4 bb = *(const float4*)(b + c);
    float4 v;
    v.x = fmaxf(r.x + bb.x, 0.f);
    v.y = fmaxf(r.y + bb.y, 0.f);
    v.z = fmaxf(r.z + bb.z, 0.f);
    v.w = fmaxf(r.w + bb.w, 0.f);
    *(float4*)(hout + i4) = v;
}

// ---------------- concat + GIN pieces --------------------------------------
__global__ void concat_kernel(const float* __restrict__ h, const float* __restrict__ feats,
                              float* __restrict__ x) {
    int idx = blockIdx.x * blockDim.x + threadIdx.x;
    int i4 = idx * 4;
    if (i4 >= NN * CATF) return;
    int n = i4 / CATF;
    int c = i4 % CATF;
    float4 v = (c < HIDD) ? *(const float4*)(h + (size_t)n * HIDD + c)
                          : *(const float4*)(feats + (size_t)n * FIN + (c - HIDD));
    *(float4*)(x + i4) = v;
}

__global__ void edge_agg_kernel(const float* __restrict__ hin, const int* __restrict__ src,
                                const int* __restrict__ dst, float* __restrict__ agg, int F) {
    int gt = blockIdx.x * blockDim.x + threadIdx.x;
    int e = gt >> 5;
    if (e >= NE) return;
    int lane = threadIdx.x & 31;
    int s = src[e], d = dst[e];
    const float* hp = hin + (size_t)s * F;
    float* ap = agg + (size_t)d * F;
    for (int f = lane * 4; f < F; f += 128) {
        float4 v = *(const float4*)(hp + f);
        red4(ap + f, v.x, v.y, v.z, v.w);
    }
}

__global__ void combine_kernel(const float* __restrict__ hin, const float* __restrict__ agg,
                               const float* __restrict__ epsp, float* __restrict__ xout, int n) {
    int idx = blockIdx.x * blockDim.x + threadIdx.x;
    int i4 = idx * 4;
    if (i4 >= n) return;
    float e = 1.f + epsp[0];
    float4 hv = *(const float4*)(hin + i4);
    float4 av = *(const float4*)(agg + i4);
    float4 v = make_float4(e * hv.x + av.x, e * hv.y + av.y, e * hv.z + av.z, e * hv.w + av.w);
    *(float4*)(xout + i4) = v;
}

__global__ void stats_kernel(const float* __restrict__ y, float* __restrict__ stats) {
    int col = threadIdx.x;
    float s = 0.f, s2 = 0.f;
    for (int r = blockIdx.x; r < NN; r += gridDim.x) {
        float v = y[(size_t)r * HIDD + col];
        s += v; s2 += v * v;
    }
    atomicAdd(&stats[col], s);
    atomicAdd(&stats[HIDD + col], s2);
}

__global__ void bnfin_kernel(const float* __restrict__ g1, const float* __restrict__ be1,
                             const float* __restrict__ stats,
                             float* __restrict__ scale, float* __restrict__ shift) {
    int c = threadIdx.x;
    float inv = 1.f / (float)NN;
    float mu = stats[c] * inv;
    float var = stats[HIDD + c] * inv - mu * mu;
    float rstd = rsqrtf(var + 1e-5f);
    float sc = g1[c] * rstd;
    scale[c] = sc;
    shift[c] = be1[c] - mu * sc;
}

__global__ void bnrelu_kernel(float* __restrict__ y, const float* __restrict__ scale,
                              const float* __restrict__ shift) {
    int idx = blockIdx.x * blockDim.x + threadIdx.x;
    int i4 = idx * 4;
    if (i4 >= NN * HIDD) return;
    int c = i4 & (HIDD - 1);
    float4 v = *(const float4*)(y + i4);
    float4 sc = *(const float4*)(scale + c);
    float4 sh = *(const float4*)(shift + c);
    v.x = fmaxf(v.x * sc.x + sh.x, 0.f);
    v.y = fmaxf(v.y * sc.y + sh.y, 0.f);
    v.z = fmaxf(v.z * sc.z + sh.z, 0.f);
    v.w = fmaxf(v.w * sc.w + sh.w, 0.f);
    *(float4*)(y + i4) = v;
}

__global__ void zero_kernel(float* __restrict__ p, int n) {
    int idx = blockIdx.x * blockDim.x + threadIdx.x;
    int i4 = idx * 4;
    if (i4 >= n) return;
    *(float4*)(p + i4) = make_float4(0.f, 0.f, 0.f, 0.f);
}

// ---------------- host orchestration ---------------------------------------
static inline int blk4(int n) { return (n / 4 + 255) / 256; }

struct TypeCtx {
    float *z, *h, *x, *scr, *el, *er, *m, *den, *e, *ex, *stats, *scale, *shift;
    unsigned int *wh, *wl;
    cudaStream_t st;
};

static void gemm(const TypeCtx& c, const float* A, const float* Wsrc, const float* b,
                 float* C, int K, int relu, int ldc = HIDD, int coff = 0) {
    int wtot = HIDD * (K / 2);
    wconv_kernel<<<(wtot + 255) / 256, 256, 0, c.st>>>(Wsrc, K, c.wh, c.wl);
    dim3 grid(HIDD / 128, (NN + 127) / 128);
    gemm_tc_kernel<<<grid, 256, 0, c.st>>>(A, c.wh, c.wl, b, C, NN, K, ldc, coff, relu);
}

static void run_gat(const TypeCtx& c, const float* z, const float* al, const float* ar,
                    const float* b, const int* s, const int* d, float* rst, float* hout) {
    elz_kernel<<<NN, 128, 0, c.st>>>(z, al, ar, c.el, c.er);
    init_nh_kernel<<<(NN * NHD + 255) / 256, 256, 0, c.st>>>(c.m, c.den);
    edge_max_kernel<<<(NE + 255) / 256, 256, 0, c.st>>>(s, d, c.el, c.er, c.e, c.m);
    edge_exp_kernel<<<(NE + 255) / 256, 256, 0, c.st>>>(d, c.e, c.m, c.ex, c.den);
    zero_kernel<<<blk4(NN * HIDD), 256, 0, c.st>>>(rst, NN * HIDD);
    edge_msg_kernel<<<(NE * 32 + 255) / 256, 256, 0, c.st>>>(s, d, z, c.ex, c.den, rst);
    gat_fin_kernel<<<blk4(NN * HIDD), 256, 0, c.st>>>(rst, b, hout);
}

static void run_gin(const TypeCtx& c, const float* hin, int F, const int* s, const int* d,
                    const float* eps, const float* W1, const float* b1,
                    const float* g1, const float* be1, const float* W2, const float* b2,
                    float* agg, float* xbuf, float* ybuf, float* hout,
                    int ldc, int coff) {
    zero_kernel<<<blk4(NN * F), 256, 0, c.st>>>(agg, NN * F);
    edge_agg_kernel<<<(NE * 32 + 255) / 256, 256, 0, c.st>>>(hin, s, d, agg, F);
    combine_kernel<<<blk4(NN * F), 256, 0, c.st>>>(hin, agg, eps, xbuf, NN * F);
    gemm(c, xbuf, W1, b1, ybuf, F, 0);
    zero_kernel<<<1, 128, 0, c.st>>>(c.stats, 2 * HIDD);
    stats_kernel<<<512, HIDD, 0, c.st>>>(ybuf, c.stats);
    bnfin_kernel<<<1, HIDD, 0, c.st>>>(g1, be1, c.stats, c.scale, c.shift);
    bnrelu_kernel<<<blk4(NN * HIDD), 256, 0, c.st>>>(ybuf, c.scale, c.shift);
    gemm(c, ybuf, W2, b2, hout, HIDD, 1, ldc, coff);
}

extern "C" void kernel_launch(void* const* d_in, const int* in_sizes, int n_in,
                              void* d_out, int out_size) {
    const float* feats = (const float*)d_in[0];
    const int* src[2] = { (const int*)d_in[1], (const int*)d_in[3] };
    const int* dst[2] = { (const int*)d_in[2], (const int*)d_in[4] };
    const float* gat0_W   = (const float*)d_in[5];
    const float* gat0_al  = (const float*)d_in[6];
    const float* gat0_ar  = (const float*)d_in[7];
    const float* gat0_b   = (const float*)d_in[8];
    const float* gat1_W   = (const float*)d_in[9];
    const float* gat1_al  = (const float*)d_in[10];
    const float* gat1_ar  = (const float*)d_in[11];
    const float* gat1_b   = (const float*)d_in[12];
    const float* gin0_eps = (const float*)d_in[13];
    const float* gin0_W1  = (const float*)d_in[14];
    const float* gin0_b1  = (const float*)d_in[15];
    const float* gin0_g1  = (const float*)d_in[16];
    const float* gin0_be1 = (const float*)d_in[17];
    const float* gin0_W2  = (const float*)d_in[18];
    const float* gin0_b2  = (const float*)d_in[19];
    const float* gin1_eps = (const float*)d_in[20];
    const float* gin1_W1  = (const float*)d_in[21];
    const float* gin1_b1  = (const float*)d_in[22];
    const float* gin1_g1  = (const float*)d_in[23];
    const float* gin1_be1 = (const float*)d_in[24];
    const float* gin1_W2  = (const float*)d_in[25];
    const float* gin1_b2  = (const float*)d_in[26];
    float* out = (float*)d_out;

    float *zb, *hb, *xb, *scrb, *elb, *erb, *mb, *denb, *eb, *exb, *stb, *scb, *shb;
    unsigned int *whb, *wlb;
    cudaGetSymbolAddress((void**)&zb, g_z);
    cudaGetSymbolAddress((void**)&hb, g_h);
    cudaGetSymbolAddress((void**)&xb, g_x);
    cudaGetSymbolAddress((void**)&scrb, g_scr);
    cudaGetSymbolAddress((void**)&elb, g_el);
    cudaGetSymbolAddress((void**)&erb, g_er);
    cudaGetSymbolAddress((void**)&mb, g_m);
    cudaGetSymbolAddress((void**)&denb, g_den);
    cudaGetSymbolAddress((void**)&eb, g_e);
    cudaGetSymbolAddress((void**)&exb, g_ex);
    cudaGetSymbolAddress((void**)&stb, g_stats);
    cudaGetSymbolAddress((void**)&scb, g_scale);
    cudaGetSymbolAddress((void**)&shb, g_shift);
    cudaGetSymbolAddress((void**)&whb, g_wh);
    cudaGetSymbolAddress((void**)&wlb, g_wl);

    // fork: both type-chains branch off the capture (default) stream
    cudaEventRecord(g_si.e0, 0);
    cudaStreamWaitEvent(g_si.s[0], g_si.e0, 0);
    cudaStreamWaitEvent(g_si.s[1], g_si.e0, 0);

    for (int t = 0; t < TTYP; t++) {
        TypeCtx c;
        c.z   = zb   + (size_t)t * NN * HIDD;
        c.h   = hb   + (size_t)t * NN * HIDD;
        c.x   = xb   + (size_t)t * NN * CATF;
        c.scr = scrb + (size_t)t * NN * CATF;
        c.el  = elb  + (size_t)t * NN * NHD;
        c.er  = erb  + (size_t)t * NN * NHD;
        c.m   = mb   + (size_t)t * NN * NHD;
        c.den = denb + (size_t)t * NN * NHD;
        c.e   = eb   + (size_t)t * NE * NHD;
        c.ex  = exb  + (size_t)t * NE * NHD;
        c.stats = stb + (size_t)t * 2 * HIDD;
        c.scale = scb + (size_t)t * HIDD;
        c.shift = shb + (size_t)t * HIDD;
        c.wh  = whb  + (size_t)t * HIDD * KWMAX;
        c.wl  = wlb  + (size_t)t * HIDD * KWMAX;
        c.st  = g_si.s[t];

        // GAT layer 0
        gemm(c, feats, gat0_W + (size_t)t * FIN * HIDD, nullptr, c.z, FIN, 0);
        run_gat(c, c.z, gat0_al + t * NHD * DH, gat0_ar + t * NHD * DH,
                gat0_b + t * HIDD, src[t], dst[t], c.scr, c.h);
        // GAT layer 1
        gemm(c, c.h, gat1_W + (size_t)t * HIDD * HIDD, nullptr, c.z, HIDD, 0);
        run_gat(c, c.z, gat1_al + t * NHD * DH, gat1_ar + t * NHD * DH,
                gat1_b + t * HIDD, src[t], dst[t], c.scr, c.h);
        // skip-concat
        concat_kernel<<<blk4(NN * CATF), 256, 0, c.st>>>(c.h, feats, c.x);
        // GIN layer 0 (F = 384)
        run_gin(c, c.x, CATF, src[t], dst[t], gin0_eps + t,
                gin0_W1 + (size_t)t * CATF * HIDD, gin0_b1 + t * HIDD,
                gin0_g1 + t * HIDD, gin0_be1 + t * HIDD,
                gin0_W2 + (size_t)t * HIDD * HIDD, gin0_b2 + t * HIDD,
                c.scr, c.x, c.z, c.h, HIDD, 0);
        // GIN layer 1 (F = 256) — final GEMM writes into the strided output
        run_gin(c, c.h, HIDD, src[t], dst[t], gin1_eps + t,
                gin1_W1 + (size_t)t * HIDD * HIDD, gin1_b1 + t * HIDD,
                gin1_g1 + t * HIDD, gin1_be1 + t * HIDD,
                gin1_W2 + (size_t)t * HIDD * HIDD, gin1_b2 + t * HIDD,
                c.scr, c.x, c.z, out, TTYP * HIDD, t * HIDD);
    }

    // join
    cudaEventRecord(g_si.e1, g_si.s[0]);
    cudaEventRecord(g_si.e2, g_si.s[1]);
    cudaStreamWaitEvent((cudaStream_t)0, g_si.e1, 0);
    cudaStreamWaitEvent((cudaStream_t)0, g_si.e2, 0);
}

// round 7
// speedup vs baseline: 1.6867x; 1.5260x over previous
#include <cuda_runtime.h>
#include <cuda_bf16.h>
#include <math.h>

#define NN   50000
#define FIN  128
#define HIDD 256
#define NHD  4
#define DH   64
#define NE   400000
#define CATF 384
#define TTYP 2
#define KWMAX (CATF/2)
#define SCANT 1024

// ---------------- per-type scratch (device globals) ------------------------
static __device__ float g_z  [TTYP][(size_t)NN*HIDD];
static __device__ float g_h  [TTYP][(size_t)NN*HIDD];
static __device__ float g_x  [TTYP][(size_t)NN*CATF];
static __device__ float g_scr[TTYP][(size_t)NN*CATF];
static __device__ float g_el [TTYP][NN*NHD];
static __device__ float g_er [TTYP][NN*NHD];
static __device__ float g_stats[TTYP][2*HIDD];
static __device__ float g_scale[TTYP][HIDD];
static __device__ float g_shift[TTYP][HIDD];
static __device__ unsigned int g_wh[TTYP][HIDD*KWMAX];
static __device__ unsigned int g_wl[TTYP][HIDD*KWMAX];
// CSR (dst-sorted) graph
static __device__ int g_cnt[TTYP][NN];
static __device__ int g_rowptr[TTYP][NN+1];
static __device__ int g_cur[TTYP][NN];
static __device__ int g_csrc[TTYP][NE];

// ---------------- streams/events (created once, statically) ----------------
namespace {
struct SI {
    cudaStream_t s[TTYP];
    cudaEvent_t e0, e1, e2;
    SI() {
        cudaStreamCreateWithFlags(&s[0], cudaStreamNonBlocking);
        cudaStreamCreateWithFlags(&s[1], cudaStreamNonBlocking);
        cudaEventCreateWithFlags(&e0, cudaEventDisableTiming);
        cudaEventCreateWithFlags(&e1, cudaEventDisableTiming);
        cudaEventCreateWithFlags(&e2, cudaEventDisableTiming);
    }
};
SI g_si;
}

// ---------------- helpers --------------------------------------------------
__device__ __forceinline__ float lrelu(float v) { return v >= 0.f ? v : 0.2f * v; }

__device__ __forceinline__ unsigned int pack2(__nv_bfloat16 a, __nv_bfloat16 b) {
    return (unsigned int)__bfloat16_as_ushort(a) |
           ((unsigned int)__bfloat16_as_ushort(b) << 16);
}

__device__ __forceinline__ void split_bf(float v, __nv_bfloat16& h, __nv_bfloat16& l) {
    h = __float2bfloat16_rn(v);
    l = __float2bfloat16_rn(v - __bfloat162float(h));
}

__device__ __forceinline__ void mma16816(float* c, const unsigned int* a, const unsigned int* b) {
    asm volatile(
        "mma.sync.aligned.m16n8k16.row.col.f32.bf16.bf16.f32 "
        "{%0,%1,%2,%3}, {%4,%5,%6,%7}, {%8,%9}, {%0,%1,%2,%3};"
        : "+f"(c[0]), "+f"(c[1]), "+f"(c[2]), "+f"(c[3])
        : "r"(a[0]), "r"(a[1]), "r"(a[2]), "r"(a[3]), "r"(b[0]), "r"(b[1]));
}

// ---------------- CSR build -------------------------------------------------
__global__ void zero_int_kernel(int* __restrict__ p, int n) {
    int i = blockIdx.x * blockDim.x + threadIdx.x;
    if (i < n) p[i] = 0;
}

__global__ void count_kernel(const int* __restrict__ dst, int* __restrict__ cnt) {
    int e = blockIdx.x * blockDim.x + threadIdx.x;
    if (e < NE) atomicAdd(&cnt[dst[e]], 1);
}

__global__ void scan_kernel(const int* __restrict__ cnt, int* __restrict__ rowptr,
                            int* __restrict__ cur) {
    __shared__ int sums[SCANT];
    int tid = threadIdx.x;
    int chunk = (NN + SCANT - 1) / SCANT;
    int start = tid * chunk;
    int end = start + chunk; if (end > NN) end = NN;
    int s = 0;
    for (int i = start; i < end; i++) s += cnt[i];
    sums[tid] = s;
    __syncthreads();
    for (int off = 1; off < SCANT; off <<= 1) {
        int v = (tid >= off) ? sums[tid - off] : 0;
        __syncthreads();
        sums[tid] += v;
        __syncthreads();
    }
    int run = (tid > 0) ? sums[tid - 1] : 0;
    for (int i = start; i < end; i++) {
        rowptr[i] = run; cur[i] = run; run += cnt[i];
    }
    if (tid == SCANT - 1) rowptr[NN] = run;
}

__global__ void fill_kernel(const int* __restrict__ src, const int* __restrict__ dst,
                            int* __restrict__ cur, int* __restrict__ csrc) {
    int e = blockIdx.x * blockDim.x + threadIdx.x;
    if (e >= NE) return;
    int pos = atomicAdd(&cur[dst[e]], 1);
    csrc[pos] = src[e];
}

// W convert + transpose: W[K][256] -> wh/wl [256][K/2] packed pairs along K.
__global__ void wconv_kernel(const float* __restrict__ W, int K,
                             unsigned int* __restrict__ wh, unsigned int* __restrict__ wl) {
    int idx = blockIdx.x * blockDim.x + threadIdx.x;
    int Kw = K / 2;
    if (idx >= HIDD * Kw) return;
    int n = idx / Kw;
    int kp = idx - n * Kw;
    float v0 = W[(size_t)(2 * kp) * HIDD + n];
    float v1 = W[(size_t)(2 * kp + 1) * HIDD + n];
    __nv_bfloat16 h0, h1, l0, l1;
    split_bf(v0, h0, l0); split_bf(v1, h1, l1);
    wh[idx] = pack2(h0, h1);
    wl[idx] = pack2(l0, l1);
}

// ---------------- tensor-core GEMM -----------------------------------------
#define SSTR 20
__global__ __launch_bounds__(256, 2)
void gemm_tc_kernel(const float* __restrict__ A,
                    const unsigned int* __restrict__ BHg, const unsigned int* __restrict__ BLg,
                    const float* __restrict__ bias, float* __restrict__ C,
                    int M, int K, int ldc, int coff, int relu_flag) {
    __shared__ unsigned int AH[128 * SSTR];
    __shared__ unsigned int AL[128 * SSTR];
    __shared__ unsigned int BH[128 * SSTR];
    __shared__ unsigned int BL[128 * SSTR];

    int tid = threadIdx.x;
    int lane = tid & 31, wid = tid >> 5;
    int lm = lane >> 2, lc = lane & 3;
    int m0 = (wid >> 2) * 64;
    int n0w = (wid & 3) * 32;
    int rowBase = blockIdx.y * 128;
    int colBase = blockIdx.x * 128;
    int Kw = K / 2;

    float acc[16][4];
#pragma unroll
    for (int i = 0; i < 16; i++)
#pragma unroll
        for (int j = 0; j < 4; j++) acc[i][j] = 0.f;

    int nkt = K / 32;
    for (int kt = 0; kt < nkt; kt++) {
        int k0 = kt * 32;
        int k0w = kt * 16;
#pragma unroll
        for (int i = 0; i < 4; i++) {
            int pos = tid + i * 256;
            int m = pos >> 3;
            int k = (pos & 7) * 4;
            int row = rowBase + m;
            float4 v = make_float4(0.f, 0.f, 0.f, 0.f);
            if (row < M) v = *(const float4*)(A + (size_t)row * K + k0 + k);
            __nv_bfloat16 h0, h1, h2, h3, l0, l1, l2, l3;
            split_bf(v.x, h0, l0); split_bf(v.y, h1, l1);
            split_bf(v.z, h2, l2); split_bf(v.w, h3, l3);
            int w = m * SSTR + (k >> 1);
            AH[w]     = pack2(h0, h1);
            AH[w + 1] = pack2(h2, h3);
            AL[w]     = pack2(l0, l1);
            AL[w + 1] = pack2(l2, l3);
        }
#pragma unroll
        for (int i = 0; i < 2; i++) {
            int p = tid + i * 256;
            int n = p >> 2;
            int c = (p & 3) * 4;
            *(uint4*)&BH[n * SSTR + c] = *(const uint4*)(BHg + (size_t)(colBase + n) * Kw + k0w + c);
            *(uint4*)&BL[n * SSTR + c] = *(const uint4*)(BLg + (size_t)(colBase + n) * Kw + k0w + c);
        }
        __syncthreads();
#pragma unroll
        for (int kk = 0; kk < 2; kk++) {
            int kw = kk * 8;
            unsigned int ah[4][4], al[4][4], bh[4][2], bl[4][2];
#pragma unroll
            for (int mi = 0; mi < 4; mi++) {
                int r = m0 + mi * 16 + lm;
                int w0 = r * SSTR + kw + lc;
                int w1 = (r + 8) * SSTR + kw + lc;
                ah[mi][0] = AH[w0]; ah[mi][1] = AH[w1];
                ah[mi][2] = AH[w0 + 4]; ah[mi][3] = AH[w1 + 4];
                al[mi][0] = AL[w0]; al[mi][1] = AL[w1];
                al[mi][2] = AL[w0 + 4]; al[mi][3] = AL[w1 + 4];
            }
#pragma unroll
            for (int ni = 0; ni < 4; ni++) {
                int n = n0w + ni * 8 + lm;
                int w0 = n * SSTR + kw + lc;
                bh[ni][0] = BH[w0]; bh[ni][1] = BH[w0 + 4];
                bl[ni][0] = BL[w0]; bl[ni][1] = BL[w0 + 4];
            }
#pragma unroll
            for (int mi = 0; mi < 4; mi++)
#pragma unroll
                for (int ni = 0; ni < 4; ni++) {
                    float* c = acc[mi * 4 + ni];
                    mma16816(c, ah[mi], bh[ni]);
                    mma16816(c, ah[mi], bl[ni]);
                    mma16816(c, al[mi], bh[ni]);
                }
        }
        __syncthreads();
    }

#pragma unroll
    for (int mi = 0; mi < 4; mi++) {
#pragma unroll
        for (int ni = 0; ni < 4; ni++) {
            float* c = acc[mi * 4 + ni];
            int r0 = rowBase + m0 + mi * 16 + lm;
            int r1 = r0 + 8;
            int col = colBase + n0w + ni * 8 + lc * 2;
            float b0 = bias ? bias[col] : 0.f;
            float b1 = bias ? bias[col + 1] : 0.f;
            float v0 = c[0] + b0, v1 = c[1] + b1;
            float v2 = c[2] + b0, v3 = c[3] + b1;
            if (relu_flag) {
                v0 = fmaxf(v0, 0.f); v1 = fmaxf(v1, 0.f);
                v2 = fmaxf(v2, 0.f); v3 = fmaxf(v3, 0.f);
            }
            if (r0 < M) *(float2*)(C + (size_t)r0 * ldc + coff + col) = make_float2(v0, v1);
            if (r1 < M) *(float2*)(C + (size_t)r1 * ldc + coff + col) = make_float2(v2, v3);
        }
    }
}

// ---------------- GAT: el/er projection -------------------------------------
__global__ void elz_kernel(const float* __restrict__ z,
                           const float* __restrict__ al, const float* __restrict__ ar,
                           float* __restrict__ elp, float* __restrict__ erp) {
    int n = blockIdx.x;
    int w = threadIdx.x >> 5;
    int lane = threadIdx.x & 31;
    const float* zp = z + (size_t)n * HIDD + w * DH;
    float z0 = zp[lane], z1 = zp[lane + 32];
    float a0 = al[w * DH + lane], a1 = al[w * DH + lane + 32];
    float b0 = ar[w * DH + lane], b1 = ar[w * DH + lane + 32];
    float el = z0 * a0 + z1 * a1;
    float er = z0 * b0 + z1 * b1;
#pragma unroll
    for (int off = 16; off; off >>= 1) {
        el += __shfl_down_sync(0xffffffffu, el, off);
        er += __shfl_down_sync(0xffffffffu, er, off);
    }
    if (lane == 0) { elp[n * NHD + w] = el; erp[n * NHD + w] = er; }
}

// ---------------- fused GAT gather: softmax + message + bias + relu ---------
// warp per dst node; lane owns 8 contiguous output floats (head = lane>>3).
__global__ __launch_bounds__(256)
void gat_gather_kernel(const int* __restrict__ csrc, const int* __restrict__ rowptr,
                       const float* __restrict__ elp, const float* __restrict__ erp,
                       const float* __restrict__ z, const float* __restrict__ bias,
                       float* __restrict__ hout) {
    int warp = (blockIdx.x * blockDim.x + threadIdx.x) >> 5;
    if (warp >= NN) return;
    int lane = threadIdx.x & 31;
    int head = lane >> 3;
    int beg = rowptr[warp], end = rowptr[warp + 1];
    float erh = erp[warp * NHD + head];

    // pass A: per-head max (identical across the 8 lanes of a head)
    float m = -INFINITY;
    for (int i = beg; i < end; i++) {
        int s = csrc[i];
        m = fmaxf(m, lrelu(elp[s * NHD + head] + erh));
    }
    if (m < -3.0e38f) m = 0.f;

    // pass B: unnormalized message + denominator
    float den = 0.f;
    float msg[8] = {0.f, 0.f, 0.f, 0.f, 0.f, 0.f, 0.f, 0.f};
    for (int i = beg; i < end; i++) {
        int s = csrc[i];
        float p = __expf(lrelu(elp[s * NHD + head] + erh) - m);
        den += p;
        const float4* zp = (const float4*)(z + (size_t)s * HIDD + lane * 8);
        float4 a = zp[0], b = zp[1];
        msg[0] += p * a.x; msg[1] += p * a.y; msg[2] += p * a.z; msg[3] += p * a.w;
        msg[4] += p * b.x; msg[5] += p * b.y; msg[6] += p * b.z; msg[7] += p * b.w;
    }
    float inv = 1.f / fmaxf(den, 1e-9f);
    const float4* bp = (const float4*)(bias + lane * 8);
    float4 b0 = bp[0], b1 = bp[1];
    float4 o0, o1;
    o0.x = fmaxf(msg[0] * inv + b0.x, 0.f);
    o0.y = fmaxf(msg[1] * inv + b0.y, 0.f);
    o0.z = fmaxf(msg[2] * inv + b0.z, 0.f);
    o0.w = fmaxf(msg[3] * inv + b0.w, 0.f);
    o1.x = fmaxf(msg[4] * inv + b1.x, 0.f);
    o1.y = fmaxf(msg[5] * inv + b1.y, 0.f);
    o1.z = fmaxf(msg[6] * inv + b1.z, 0.f);
    o1.w = fmaxf(msg[7] * inv + b1.w, 0.f);
    float4* op = (float4*)(hout + (size_t)warp * HIDD + lane * 8);
    op[0] = o0; op[1] = o1;
}

// ---------------- fused GIN gather: x = (1+eps)h + sum_in h[src] ------------
// warp per dst node; lane strides float4 chunks of width F.
__global__ __launch_bounds__(256)
void gin_gather_kernel(const int* __restrict__ csrc, const int* __restrict__ rowptr,
                       const float* __restrict__ hin, const float* __restrict__ epsp,
                       float* __restrict__ xout, int F) {
    int warp = (blockIdx.x * blockDim.x + threadIdx.x) >> 5;
    if (warp >= NN) return;
    int lane = threadIdx.x & 31;
    int beg = rowptr[warp], end = rowptr[warp + 1];
    float e = 1.f + epsp[0];
    for (int f = lane * 4; f < F; f += 128) {
        float4 hv = *(const float4*)(hin + (size_t)warp * F + f);
        float4 a = make_float4(e * hv.x, e * hv.y, e * hv.z, e * hv.w);
        for (int i = beg; i < end; i++) {
            int s = csrc[i];
            float4 v = *(const float4*)(hin + (size_t)s * F + f);
            a.x += v.x; a.y += v.y; a.z += v.z; a.w += v.w;
        }
        *(float4*)(xout + (size_t)warp * F + f) = a;
    }
}

// ---------------- misc elementwise ------------------------------------------
__global__ void concat_kernel(const float* __restrict__ h, const float* __restrict__ feats,
                              float* __restrict__ x) {
    int idx = blockIdx.x * blockDim.x + threadIdx.x;
    int i4 = idx * 4;
    if (i4 >= NN * CATF) return;
    int n = i4 / CATF;
    int c = i4 % CATF;
    float4 v = (c < HIDD) ? *(const float4*)(h + (size_t)n * HIDD + c)
                          : *(const float4*)(feats + (size_t)n * FIN + (c - HIDD));
    *(float4*)(x + i4) = v;
}

__global__ void stats_kernel(const float* __restrict__ y, float* __restrict__ stats) {
    int col = threadIdx.x;
    float s = 0.f, s2 = 0.f;
    for (int r = blockIdx.x; r < NN; r += gridDim.x) {
        float v = y[(size_t)r * HIDD + col];
        s += v; s2 += v * v;
    }
    atomicAdd(&stats[col], s);
    atomicAdd(&stats[HIDD + col], s2);
}

__global__ void bnfin_kernel(const float* __restrict__ g1, const float* __restrict__ be1,
                             const float* __restrict__ stats,
                             float* __restrict__ scale, float* __restrict__ shift) {
    int c = threadIdx.x;
    float inv = 1.f / (float)NN;
    float mu = stats[c] * inv;
    float var = stats[HIDD + c] * inv - mu * mu;
    float rstd = rsqrtf(var + 1e-5f);
    float sc = g1[c] * rstd;
    scale[c] = sc;
    shift[c] = be1[c] - mu * sc;
}

__global__ void bnrelu_kernel(float* __restrict__ y, const float* __restrict__ scale,
                              const float* __restrict__ shift) {
    int idx = blockIdx.x * blockDim.x + threadIdx.x;
    int i4 = idx * 4;
    if (i4 >= NN * HIDD) return;
    int c = i4 & (HIDD - 1);
    float4 v = *(const float4*)(y + i4);
    float4 sc = *(const float4*)(scale + c);
    float4 sh = *(const float4*)(shift + c);
    v.x = fmaxf(v.x * sc.x + sh.x, 0.f);
    v.y = fmaxf(v.y * sc.y + sh.y, 0.f);
    v.z = fmaxf(v.z * sc.z + sh.z, 0.f);
    v.w = fmaxf(v.w * sc.w + sh.w, 0.f);
    *(float4*)(y + i4) = v;
}

__global__ void zero_kernel(float* __restrict__ p, int n) {
    int idx = blockIdx.x * blockDim.x + threadIdx.x;
    int i4 = idx * 4;
    if (i4 >= n) return;
    *(float4*)(p + i4) = make_float4(0.f, 0.f, 0.f, 0.f);
}

// ---------------- host orchestration ---------------------------------------
static inline int blk4(int n) { return (n / 4 + 255) / 256; }
#define NODE_WARP_BLOCKS ((NN * 32 + 255) / 256)

struct TypeCtx {
    float *z, *h, *x, *scr, *el, *er, *stats, *scale, *shift;
    unsigned int *wh, *wl;
    int *cnt, *rowptr, *cur, *csrc;
    cudaStream_t st;
};

static void gemm(const TypeCtx& c, const float* A, const float* Wsrc, const float* b,
                 float* C, int K, int relu, int ldc = HIDD, int coff = 0) {
    int wtot = HIDD * (K / 2);
    wconv_kernel<<<(wtot + 255) / 256, 256, 0, c.st>>>(Wsrc, K, c.wh, c.wl);
    dim3 grid(HIDD / 128, (NN + 127) / 128);
    gemm_tc_kernel<<<grid, 256, 0, c.st>>>(A, c.wh, c.wl, b, C, NN, K, ldc, coff, relu);
}

static void run_gat(const TypeCtx& c, const float* z, const float* al, const float* ar,
                    const float* b, float* hout) {
    elz_kernel<<<NN, 128, 0, c.st>>>(z, al, ar, c.el, c.er);
    gat_gather_kernel<<<NODE_WARP_BLOCKS, 256, 0, c.st>>>(c.csrc, c.rowptr, c.el, c.er,
                                                          z, b, hout);
}

static void run_gin(const TypeCtx& c, const float* hin, float* xbuf, int F,
                    const float* eps, const float* W1, const float* b1,
                    const float* g1, const float* be1, const float* W2, const float* b2,
                    float* ybuf, float* hout, int ldc, int coff) {
    gin_gather_kernel<<<NODE_WARP_BLOCKS, 256, 0, c.st>>>(c.csrc, c.rowptr, hin, eps, xbuf, F);
    gemm(c, xbuf, W1, b1, ybuf, F, 0);
    zero_kernel<<<1, 128, 0, c.st>>>(c.stats, 2 * HIDD);
    stats_kernel<<<512, HIDD, 0, c.st>>>(ybuf, c.stats);
    bnfin_kernel<<<1, HIDD, 0, c.st>>>(g1, be1, c.stats, c.scale, c.shift);
    bnrelu_kernel<<<blk4(NN * HIDD), 256, 0, c.st>>>(ybuf, c.scale, c.shift);
    gemm(c, ybuf, W2, b2, hout, HIDD, 1, ldc, coff);
}

extern "C" void kernel_launch(void* const* d_in, const int* in_sizes, int n_in,
                              void* d_out, int out_size) {
    const float* feats = (const float*)d_in[0];
    const int* src[2] = { (const int*)d_in[1], (const int*)d_in[3] };
    const int* dst[2] = { (const int*)d_in[2], (const int*)d_in[4] };
    const float* gat0_W   = (const float*)d_in[5];
    const float* gat0_al  = (const float*)d_in[6];
    const float* gat0_ar  = (const float*)d_in[7];
    const float* gat0_b   = (const float*)d_in[8];
    const float* gat1_W   = (const float*)d_in[9];
    const float* gat1_al  = (const float*)d_in[10];
    const float* gat1_ar  = (const float*)d_in[11];
    const float* gat1_b   = (const float*)d_in[12];
    const float* gin0_eps = (const float*)d_in[13];
    const float* gin0_W1  = (const float*)d_in[14];
    const float* gin0_b1  = (const float*)d_in[15];
    const float* gin0_g1  = (const float*)d_in[16];
    const float* gin0_be1 = (const float*)d_in[17];
    const float* gin0_W2  = (const float*)d_in[18];
    const float* gin0_b2  = (const float*)d_in[19];
    const float* gin1_eps = (const float*)d_in[20];
    const float* gin1_W1  = (const float*)d_in[21];
    const float* gin1_b1  = (const float*)d_in[22];
    const float* gin1_g1  = (const float*)d_in[23];
    const float* gin1_be1 = (const float*)d_in[24];
    const float* gin1_W2  = (const float*)d_in[25];
    const float* gin1_b2  = (const float*)d_in[26];
    float* out = (float*)d_out;

    float *zb, *hb, *xb, *scrb, *elb, *erb, *stb, *scb, *shb;
    unsigned int *whb, *wlb;
    int *cntb, *rpb, *curb, *csb;
    cudaGetSymbolAddress((void**)&zb, g_z);
    cudaGetSymbolAddress((void**)&hb, g_h);
    cudaGetSymbolAddress((void**)&xb, g_x);
    cudaGetSymbolAddress((void**)&scrb, g_scr);
    cudaGetSymbolAddress((void**)&elb, g_el);
    cudaGetSymbolAddress((void**)&erb, g_er);
    cudaGetSymbolAddress((void**)&stb, g_stats);
    cudaGetSymbolAddress((void**)&scb, g_scale);
    cudaGetSymbolAddress((void**)&shb, g_shift);
    cudaGetSymbolAddress((void**)&whb, g_wh);
    cudaGetSymbolAddress((void**)&wlb, g_wl);
    cudaGetSymbolAddress((void**)&cntb, g_cnt);
    cudaGetSymbolAddress((void**)&rpb, g_rowptr);
    cudaGetSymbolAddress((void**)&curb, g_cur);
    cudaGetSymbolAddress((void**)&csb, g_csrc);

    // fork
    cudaEventRecord(g_si.e0, 0);
    cudaStreamWaitEvent(g_si.s[0], g_si.e0, 0);
    cudaStreamWaitEvent(g_si.s[1], g_si.e0, 0);

    for (int t = 0; t < TTYP; t++) {
        TypeCtx c;
        c.z   = zb   + (size_t)t * NN * HIDD;
        c.h   = hb   + (size_t)t * NN * HIDD;
        c.x   = xb   + (size_t)t * NN * CATF;
        c.scr = scrb + (size_t)t * NN * CATF;
        c.el  = elb  + (size_t)t * NN * NHD;
        c.er  = erb  + (size_t)t * NN * NHD;
        c.stats = stb + (size_t)t * 2 * HIDD;
        c.scale = scb + (size_t)t * HIDD;
        c.shift = shb + (size_t)t * HIDD;
        c.wh  = whb  + (size_t)t * HIDD * KWMAX;
        c.wl  = wlb  + (size_t)t * HIDD * KWMAX;
        c.cnt = cntb + (size_t)t * NN;
        c.rowptr = rpb + (size_t)t * (NN + 1);
        c.cur = curb + (size_t)t * NN;
        c.csrc = csb + (size_t)t * NE;
        c.st  = g_si.s[t];

        // ---- CSR build (dst-sorted src list) ----
        zero_int_kernel<<<(NN + 255) / 256, 256, 0, c.st>>>(c.cnt, NN);
        count_kernel<<<(NE + 255) / 256, 256, 0, c.st>>>(dst[t], c.cnt);
        scan_kernel<<<1, SCANT, 0, c.st>>>(c.cnt, c.rowptr, c.cur);
        fill_kernel<<<(NE + 255) / 256, 256, 0, c.st>>>(src[t], dst[t], c.cur, c.csrc);

        // ---- GAT layer 0 ----
        gemm(c, feats, gat0_W + (size_t)t * FIN * HIDD, nullptr, c.z, FIN, 0);
        run_gat(c, c.z, gat0_al + t * NHD * DH, gat0_ar + t * NHD * DH,
                gat0_b + t * HIDD, c.h);
        // ---- GAT layer 1 ----
        gemm(c, c.h, gat1_W + (size_t)t * HIDD * HIDD, nullptr, c.z, HIDD, 0);
        run_gat(c, c.z, gat1_al + t * NHD * DH, gat1_ar + t * NHD * DH,
                gat1_b + t * HIDD, c.h);
        // ---- skip-concat ----
        concat_kernel<<<blk4(NN * CATF), 256, 0, c.st>>>(c.h, feats, c.x);
        // ---- GIN layer 0 (F = 384): gather from c.x into c.scr ----
        run_gin(c, c.x, c.scr, CATF, gin0_eps + t,
                gin0_W1 + (size_t)t * CATF * HIDD, gin0_b1 + t * HIDD,
                gin0_g1 + t * HIDD, gin0_be1 + t * HIDD,
                gin0_W2 + (size_t)t * HIDD * HIDD, gin0_b2 + t * HIDD,
                c.z, c.h, HIDD, 0);
        // ---- GIN layer 1 (F = 256): gather from c.h into c.scr ----
        run_gin(c, c.h, c.scr, HIDD, gin1_eps + t,
                gin1_W1 + (size_t)t * HIDD * HIDD, gin1_b1 + t * HIDD,
                gin1_g1 + t * HIDD, gin1_be1 + t * HIDD,
                gin1_W2 + (size_t)t * HIDD * HIDD, gin1_b2 + t * HIDD,
                c.z, out, TTYP * HIDD, t * HIDD);
    }

    // join
    cudaEventRecord(g_si.e1, g_si.s[0]);
    cudaEventRecord(g_si.e2, g_si.s[1]);
    cudaStreamWaitEvent((cudaStream_t)0, g_si.e1, 0);
    cudaStreamWaitEvent((cudaStream_t)0, g_si.e2, 0);
}

// round 8
// speedup vs baseline: 1.7443x; 1.0342x over previous
#include <cuda_runtime.h>
#include <cuda_bf16.h>
#include <math.h>

#define NN   50000
#define FIN  128
#define HIDD 256
#define NHD  4
#define DH   64
#define NE   400000
#define CATF 384
#define TTYP 2
#define KWMAX (CATF/2)
#define PKW   (CATF/2)      /* max packed-A width per row (uints) = 192 */
#define SCANT 1024

// ---------------- per-type scratch (device globals) ------------------------
static __device__ float g_z  [TTYP][(size_t)NN*HIDD];
static __device__ float g_h  [TTYP][(size_t)NN*HIDD];
static __device__ float g_el [TTYP][NN*NHD];
static __device__ float g_er [TTYP][NN*NHD];
static __device__ float g_stats[TTYP][2*HIDD];
static __device__ float g_scale[TTYP][HIDD];
static __device__ float g_shift[TTYP][HIDD];
static __device__ unsigned int g_wh[TTYP][HIDD*KWMAX];
static __device__ unsigned int g_wl[TTYP][HIDD*KWMAX];
static __device__ unsigned int g_pah[TTYP][(size_t)NN*PKW];  // packed A hi
static __device__ unsigned int g_pal[TTYP][(size_t)NN*PKW];  // packed A lo
static __device__ unsigned int g_fh[(size_t)NN*(FIN/2)];     // feats hi (shared)
static __device__ unsigned int g_fl[(size_t)NN*(FIN/2)];     // feats lo
// CSR (dst-sorted) graph
static __device__ int g_cnt[TTYP][NN];
static __device__ int g_rowptr[TTYP][NN+1];
static __device__ int g_cur[TTYP][NN];
static __device__ int g_csrc[TTYP][NE];

// ---------------- streams/events (created once, statically) ----------------
namespace {
struct SI {
    cudaStream_t s[TTYP];
    cudaEvent_t e0, e1, e2;
    SI() {
        cudaStreamCreateWithFlags(&s[0], cudaStreamNonBlocking);
        cudaStreamCreateWithFlags(&s[1], cudaStreamNonBlocking);
        cudaEventCreateWithFlags(&e0, cudaEventDisableTiming);
        cudaEventCreateWithFlags(&e1, cudaEventDisableTiming);
        cudaEventCreateWithFlags(&e2, cudaEventDisableTiming);
    }
};
SI g_si;
}

// ---------------- helpers --------------------------------------------------
__device__ __forceinline__ float lrelu(float v) { return v >= 0.f ? v : 0.2f * v; }

__device__ __forceinline__ unsigned int pack2(__nv_bfloat16 a, __nv_bfloat16 b) {
    return (unsigned int)__bfloat16_as_ushort(a) |
           ((unsigned int)__bfloat16_as_ushort(b) << 16);
}

__device__ __forceinline__ void split_bf(float v, __nv_bfloat16& h, __nv_bfloat16& l) {
    h = __float2bfloat16_rn(v);
    l = __float2bfloat16_rn(v - __bfloat162float(h));
}

__device__ __forceinline__ void split4(float4 v, unsigned int* hp, unsigned int* lp) {
    __nv_bfloat16 h0, h1, h2, h3, l0, l1, l2, l3;
    split_bf(v.x, h0, l0); split_bf(v.y, h1, l1);
    split_bf(v.z, h2, l2); split_bf(v.w, h3, l3);
    hp[0] = pack2(h0, h1); hp[1] = pack2(h2, h3);
    lp[0] = pack2(l0, l1); lp[1] = pack2(l2, l3);
}

__device__ __forceinline__ void mma16816(float* c, const unsigned int* a, const unsigned int* b) {
    asm volatile(
        "mma.sync.aligned.m16n8k16.row.col.f32.bf16.bf16.f32 "
        "{%0,%1,%2,%3}, {%4,%5,%6,%7}, {%8,%9}, {%0,%1,%2,%3};"
        : "+f"(c[0]), "+f"(c[1]), "+f"(c[2]), "+f"(c[3])
        : "r"(a[0]), "r"(a[1]), "r"(a[2]), "r"(a[3]), "r"(b[0]), "r"(b[1]));
}

// ---------------- CSR build -------------------------------------------------
__global__ void zero_int_kernel(int* __restrict__ p, int n) {
    int i = blockIdx.x * blockDim.x + threadIdx.x;
    if (i < n) p[i] = 0;
}

__global__ void count_kernel(const int* __restrict__ dst, int* __restrict__ cnt) {
    int e = blockIdx.x * blockDim.x + threadIdx.x;
    if (e < NE) atomicAdd(&cnt[dst[e]], 1);
}

__global__ void scan_kernel(const int* __restrict__ cnt, int* __restrict__ rowptr,
                            int* __restrict__ cur) {
    __shared__ int sums[SCANT];
    int tid = threadIdx.x;
    int chunk = (NN + SCANT - 1) / SCANT;
    int start = tid * chunk;
    int end = start + chunk; if (end > NN) end = NN;
    int s = 0;
    for (int i = start; i < end; i++) s += cnt[i];
    sums[tid] = s;
    __syncthreads();
    for (int off = 1; off < SCANT; off <<= 1) {
        int v = (tid >= off) ? sums[tid - off] : 0;
        __syncthreads();
        sums[tid] += v;
        __syncthreads();
    }
    int run = (tid > 0) ? sums[tid - 1] : 0;
    for (int i = start; i < end; i++) {
        rowptr[i] = run; cur[i] = run; run += cnt[i];
    }
    if (tid == SCANT - 1) rowptr[NN] = run;
}

__global__ void fill_kernel(const int* __restrict__ src, const int* __restrict__ dst,
                            int* __restrict__ cur, int* __restrict__ csrc) {
    int e = blockIdx.x * blockDim.x + threadIdx.x;
    if (e >= NE) return;
    int pos = atomicAdd(&cur[dst[e]], 1);
    csrc[pos] = src[e];
}

// ---------------- converters ------------------------------------------------
// feats fp32 -> packed hi/lo pairs along feature dim
__global__ void aconv_kernel(const float* __restrict__ A, unsigned int* __restrict__ H,
                             unsigned int* __restrict__ L, int n4) {
    int idx = blockIdx.x * blockDim.x + threadIdx.x;
    if (idx >= n4) return;
    float4 v = *(const float4*)(A + (size_t)idx * 4);
    unsigned int hp[2], lp[2];
    split4(v, hp, lp);
    *(uint2*)(H + (size_t)idx * 2) = make_uint2(hp[0], hp[1]);
    *(uint2*)(L + (size_t)idx * 2) = make_uint2(lp[0], lp[1]);
}

// W convert + transpose: W[K][256] -> wh/wl [256][K/2]
__global__ void wconv_kernel(const float* __restrict__ W, int K,
                             unsigned int* __restrict__ wh, unsigned int* __restrict__ wl) {
    int idx = blockIdx.x * blockDim.x + threadIdx.x;
    int Kw = K / 2;
    if (idx >= HIDD * Kw) return;
    int n = idx / Kw;
    int kp = idx - n * Kw;
    float v0 = W[(size_t)(2 * kp) * HIDD + n];
    float v1 = W[(size_t)(2 * kp + 1) * HIDD + n];
    __nv_bfloat16 h0, h1, l0, l1;
    split_bf(v0, h0, l0); split_bf(v1, h1, l1);
    wh[idx] = pack2(h0, h1);
    wl[idx] = pack2(l0, l1);
}

// ---------------- tensor-core GEMM (all operands preconverted) --------------
#define SSTR 20
__global__ __launch_bounds__(256, 2)
void gemm_tc_kernel(const unsigned int* __restrict__ AHg, const unsigned int* __restrict__ ALg,
                    const unsigned int* __restrict__ BHg, const unsigned int* __restrict__ BLg,
                    const float* __restrict__ bias, float* __restrict__ C,
                    int M, int Kw, int ldc, int coff, int relu_flag) {
    __shared__ unsigned int AH[128 * SSTR];
    __shared__ unsigned int AL[128 * SSTR];
    __shared__ unsigned int BH[128 * SSTR];
    __shared__ unsigned int BL[128 * SSTR];

    int tid = threadIdx.x;
    int lane = tid & 31, wid = tid >> 5;
    int lm = lane >> 2, lc = lane & 3;
    int m0 = (wid >> 2) * 64;
    int n0w = (wid & 3) * 32;
    int rowBase = blockIdx.y * 128;
    int colBase = blockIdx.x * 128;

    float acc[16][4];
#pragma unroll
    for (int i = 0; i < 16; i++)
#pragma unroll
        for (int j = 0; j < 4; j++) acc[i][j] = 0.f;

    int nkt = Kw / 16;
    for (int kt = 0; kt < nkt; kt++) {
        int k0w = kt * 16;
#pragma unroll
        for (int i = 0; i < 2; i++) {
            int p = tid + i * 256;
            int m = p >> 2;
            int c = (p & 3) * 4;
            int row = rowBase + m;
            uint4 va = make_uint4(0u, 0u, 0u, 0u), vb = va;
            if (row < M) {
                va = *(const uint4*)(AHg + (size_t)row * Kw + k0w + c);
                vb = *(const uint4*)(ALg + (size_t)row * Kw + k0w + c);
            }
            *(uint4*)&AH[m * SSTR + c] = va;
            *(uint4*)&AL[m * SSTR + c] = vb;
            int n = colBase + m;
            *(uint4*)&BH[m * SSTR + c] = *(const uint4*)(BHg + (size_t)n * Kw + k0w + c);
            *(uint4*)&BL[m * SSTR + c] = *(const uint4*)(BLg + (size_t)n * Kw + k0w + c);
        }
        __syncthreads();
#pragma unroll
        for (int kk = 0; kk < 2; kk++) {
            int kw = kk * 8;
            unsigned int ah[4][4], al[4][4], bh[4][2], bl[4][2];
#pragma unroll
            for (int mi = 0; mi < 4; mi++) {
                int r = m0 + mi * 16 + lm;
                int w0 = r * SSTR + kw + lc;
                int w1 = (r + 8) * SSTR + kw + lc;
                ah[mi][0] = AH[w0]; ah[mi][1] = AH[w1];
                ah[mi][2] = AH[w0 + 4]; ah[mi][3] = AH[w1 + 4];
                al[mi][0] = AL[w0]; al[mi][1] = AL[w1];
                al[mi][2] = AL[w0 + 4]; al[mi][3] = AL[w1 + 4];
            }
#pragma unroll
            for (int ni = 0; ni < 4; ni++) {
                int n = n0w + ni * 8 + lm;
                int w0 = n * SSTR + kw + lc;
                bh[ni][0] = BH[w0]; bh[ni][1] = BH[w0 + 4];
                bl[ni][0] = BL[w0]; bl[ni][1] = BL[w0 + 4];
            }
#pragma unroll
            for (int mi = 0; mi < 4; mi++)
#pragma unroll
                for (int ni = 0; ni < 4; ni++) {
                    float* c = acc[mi * 4 + ni];
                    mma16816(c, ah[mi], bh[ni]);
                    mma16816(c, ah[mi], bl[ni]);
                    mma16816(c, al[mi], bh[ni]);
                }
        }
        __syncthreads();
    }

#pragma unroll
    for (int mi = 0; mi < 4; mi++) {
#pragma unroll
        for (int ni = 0; ni < 4; ni++) {
            float* c = acc[mi * 4 + ni];
            int r0 = rowBase + m0 + mi * 16 + lm;
            int r1 = r0 + 8;
            int col = colBase + n0w + ni * 8 + lc * 2;
            float b0 = bias ? bias[col] : 0.f;
            float b1 = bias ? bias[col + 1] : 0.f;
            float v0 = c[0] + b0, v1 = c[1] + b1;
            float v2 = c[2] + b0, v3 = c[3] + b1;
            if (relu_flag) {
                v0 = fmaxf(v0, 0.f); v1 = fmaxf(v1, 0.f);
                v2 = fmaxf(v2, 0.f); v3 = fmaxf(v3, 0.f);
            }
            if (r0 < M) *(float2*)(C + (size_t)r0 * ldc + coff + col) = make_float2(v0, v1);
            if (r1 < M) *(float2*)(C + (size_t)r1 * ldc + coff + col) = make_float2(v2, v3);
        }
    }
}

// ---------------- GAT: el/er projection (warp per node) ---------------------
__global__ __launch_bounds__(256)
void elz_kernel(const float* __restrict__ z,
                const float* __restrict__ al, const float* __restrict__ ar,
                float* __restrict__ elp, float* __restrict__ erp) {
    int warp = (blockIdx.x * blockDim.x + threadIdx.x) >> 5;
    if (warp >= NN) return;
    int lane = threadIdx.x & 31;
    const float4* zp = (const float4*)(z + (size_t)warp * HIDD + lane * 8);
    float4 z0 = zp[0], z1 = zp[1];
    const float4* ap = (const float4*)(al + lane * 8);
    float4 a0 = ap[0], a1 = ap[1];
    const float4* bp = (const float4*)(ar + lane * 8);
    float4 b0 = bp[0], b1 = bp[1];
    float el = z0.x*a0.x + z0.y*a0.y + z0.z*a0.z + z0.w*a0.w
             + z1.x*a1.x + z1.y*a1.y + z1.z*a1.z + z1.w*a1.w;
    float er = z0.x*b0.x + z0.y*b0.y + z0.z*b0.z + z0.w*b0.w
             + z1.x*b1.x + z1.y*b1.y + z1.z*b1.z + z1.w*b1.w;
#pragma unroll
    for (int off = 4; off; off >>= 1) {   // reduce within each 8-lane head group
        el += __shfl_xor_sync(0xffffffffu, el, off);
        er += __shfl_xor_sync(0xffffffffu, er, off);
    }
    if ((lane & 7) == 0) {
        int head = lane >> 3;
        elp[warp * NHD + head] = el;
        erp[warp * NHD + head] = er;
    }
}

// ---------------- fused GAT gather ------------------------------------------
// warp per dst node; lane owns 8 output floats (head = lane>>3).
// PACKED=1: write only bf16 hi/lo packed (for next GEMM). PACKED=0: write fp32.
template <int PACKED>
__global__ __launch_bounds__(256)
void gat_gather_kernel(const int* __restrict__ csrc, const int* __restrict__ rowptr,
                       const float* __restrict__ elp, const float* __restrict__ erp,
                       const float* __restrict__ z, const float* __restrict__ bias,
                       float* __restrict__ hout,
                       unsigned int* __restrict__ pah, unsigned int* __restrict__ pal) {
    int warp = (blockIdx.x * blockDim.x + threadIdx.x) >> 5;
    if (warp >= NN) return;
    int lane = threadIdx.x & 31;
    int head = lane >> 3;
    int beg = rowptr[warp], end = rowptr[warp + 1];
    float erh = erp[warp * NHD + head];

    float m = -INFINITY;
    for (int i = beg; i < end; i++) {
        int s = csrc[i];
        m = fmaxf(m, lrelu(elp[s * NHD + head] + erh));
    }
    if (m < -3.0e38f) m = 0.f;

    float den = 0.f;
    float msg[8] = {0.f, 0.f, 0.f, 0.f, 0.f, 0.f, 0.f, 0.f};
    for (int i = beg; i < end; i++) {
        int s = csrc[i];
        float p = __expf(lrelu(elp[s * NHD + head] + erh) - m);
        den += p;
        const float4* zp = (const float4*)(z + (size_t)s * HIDD + lane * 8);
        float4 a = zp[0], b = zp[1];
        msg[0] += p * a.x; msg[1] += p * a.y; msg[2] += p * a.z; msg[3] += p * a.w;
        msg[4] += p * b.x; msg[5] += p * b.y; msg[6] += p * b.z; msg[7] += p * b.w;
    }
    float inv = 1.f / fmaxf(den, 1e-9f);
    const float4* bp = (const float4*)(bias + lane * 8);
    float4 b0 = bp[0], b1 = bp[1];
    float4 o0, o1;
    o0.x = fmaxf(msg[0] * inv + b0.x, 0.f);
    o0.y = fmaxf(msg[1] * inv + b0.y, 0.f);
    o0.z = fmaxf(msg[2] * inv + b0.z, 0.f);
    o0.w = fmaxf(msg[3] * inv + b0.w, 0.f);
    o1.x = fmaxf(msg[4] * inv + b1.x, 0.f);
    o1.y = fmaxf(msg[5] * inv + b1.y, 0.f);
    o1.z = fmaxf(msg[6] * inv + b1.z, 0.f);
    o1.w = fmaxf(msg[7] * inv + b1.w, 0.f);
    if (PACKED) {
        unsigned int hp[4], lp[4];
        split4(o0, hp, lp);
        split4(o1, hp + 2, lp + 2);
        *(uint4*)(pah + (size_t)warp * (HIDD / 2) + lane * 4) = make_uint4(hp[0], hp[1], hp[2], hp[3]);
        *(uint4*)(pal + (size_t)warp * (HIDD / 2) + lane * 4) = make_uint4(lp[0], lp[1], lp[2], lp[3]);
    } else {
        float4* op = (float4*)(hout + (size_t)warp * HIDD + lane * 8);
        op[0] = o0; op[1] = o1;
    }
}

// ---------------- fused GIN gather (+implicit concat), packed output --------
// x = (1+eps)*row(dst) + sum_in row(src); row = [hA | hB] (hB may be null).
__global__ __launch_bounds__(256)
void gin_gather_kernel(const int* __restrict__ csrc, const int* __restrict__ rowptr,
                       const float* __restrict__ hA, const float* __restrict__ hB,
                       int FA, int F, const float* __restrict__ epsp,
                       unsigned int* __restrict__ ph, unsigned int* __restrict__ pl) {
    int warp = (blockIdx.x * blockDim.x + threadIdx.x) >> 5;
    if (warp >= NN) return;
    int lane = threadIdx.x & 31;
    int beg = rowptr[warp], end = rowptr[warp + 1];
    float e = 1.f + epsp[0];
    int FB = F - FA;
    for (int f = lane * 4; f < F; f += 128) {
        const float* base = (f < FA) ? (hA + (size_t)warp * FA + f)
                                     : (hB + (size_t)warp * FB + (f - FA));
        float4 hv = *(const float4*)base;
        float4 a = make_float4(e * hv.x, e * hv.y, e * hv.z, e * hv.w);
        if (f < FA) {
            for (int i = beg; i < end; i++) {
                int s = csrc[i];
                float4 v = *(const float4*)(hA + (size_t)s * FA + f);
                a.x += v.x; a.y += v.y; a.z += v.z; a.w += v.w;
            }
        } else {
            for (int i = beg; i < end; i++) {
                int s = csrc[i];
                float4 v = *(const float4*)(hB + (size_t)s * FB + (f - FA));
                a.x += v.x; a.y += v.y; a.z += v.z; a.w += v.w;
            }
        }
        unsigned int hp[2], lp[2];
        split4(a, hp, lp);
        *(uint2*)(ph + (size_t)warp * (F / 2) + (f >> 1)) = make_uint2(hp[0], hp[1]);
        *(uint2*)(pl + (size_t)warp * (F / 2) + (f >> 1)) = make_uint2(lp[0], lp[1]);
    }
}

// ---------------- BN pieces -------------------------------------------------
__global__ void stats_kernel(const float* __restrict__ y, float* __restrict__ stats) {
    int col = threadIdx.x;
    float s = 0.f, s2 = 0.f;
    for (int r = blockIdx.x; r < NN; r += gridDim.x) {
        float v = y[(size_t)r * HIDD + col];
        s += v; s2 += v * v;
    }
    atomicAdd(&stats[col], s);
    atomicAdd(&stats[HIDD + col], s2);
}

__global__ void bnfin_kernel(const float* __restrict__ g1, const float* __restrict__ be1,
                             const float* __restrict__ stats,
                             float* __restrict__ scale, float* __restrict__ shift) {
    int c = threadIdx.x;
    float inv = 1.f / (float)NN;
    float mu = stats[c] * inv;
    float var = stats[HIDD + c] * inv - mu * mu;
    float rstd = rsqrtf(var + 1e-5f);
    float sc = g1[c] * rstd;
    scale[c] = sc;
    shift[c] = be1[c] - mu * sc;
}

// y -> relu(y*scale+shift), emitted ONLY as packed bf16 hi/lo
__global__ void bnrelu_kernel(const float* __restrict__ y, const float* __restrict__ scale,
                              const float* __restrict__ shift,
                              unsigned int* __restrict__ ph, unsigned int* __restrict__ pl) {
    int idx = blockIdx.x * blockDim.x + threadIdx.x;
    int i4 = idx * 4;
    if (i4 >= NN * HIDD) return;
    int c = i4 & (HIDD - 1);
    float4 v = *(const float4*)(y + i4);
    float4 sc = *(const float4*)(scale + c);
    float4 sh = *(const float4*)(shift + c);
    v.x = fmaxf(v.x * sc.x + sh.x, 0.f);
    v.y = fmaxf(v.y * sc.y + sh.y, 0.f);
    v.z = fmaxf(v.z * sc.z + sh.z, 0.f);
    v.w = fmaxf(v.w * sc.w + sh.w, 0.f);
    unsigned int hp[2], lp[2];
    split4(v, hp, lp);
    *(uint2*)(ph + (size_t)idx * 2) = make_uint2(hp[0], hp[1]);
    *(uint2*)(pl + (size_t)idx * 2) = make_uint2(lp[0], lp[1]);
}

__global__ void zero_kernel(float* __restrict__ p, int n) {
    int idx = blockIdx.x * blockDim.x + threadIdx.x;
    int i4 = idx * 4;
    if (i4 >= n) return;
    *(float4*)(p + i4) = make_float4(0.f, 0.f, 0.f, 0.f);
}

// ---------------- host orchestration ---------------------------------------
static inline int blk4(int n) { return (n / 4 + 255) / 256; }
#define NODE_WARP_BLOCKS ((NN * 32 + 255) / 256)

struct TypeCtx {
    float *z, *h, *el, *er, *stats, *scale, *shift;
    unsigned int *wh, *wl, *pah, *pal;
    int *cnt, *rowptr, *cur, *csrc;
    cudaStream_t st;
};

static void gemm(const TypeCtx& c, const unsigned int* AH, const unsigned int* AL,
                 const float* Wsrc, const float* b, float* C,
                 int K, int relu, int ldc = HIDD, int coff = 0) {
    int wtot = HIDD * (K / 2);
    wconv_kernel<<<(wtot + 255) / 256, 256, 0, c.st>>>(Wsrc, K, c.wh, c.wl);
    dim3 grid(HIDD / 128, (NN + 127) / 128);
    gemm_tc_kernel<<<grid, 256, 0, c.st>>>(AH, AL, c.wh, c.wl, b, C, NN, K / 2, ldc, coff, relu);
}

extern "C" void kernel_launch(void* const* d_in, const int* in_sizes, int n_in,
                              void* d_out, int out_size) {
    const float* feats = (const float*)d_in[0];
    const int* src[2] = { (const int*)d_in[1], (const int*)d_in[3] };
    const int* dst[2] = { (const int*)d_in[2], (const int*)d_in[4] };
    const float* gat0_W   = (const float*)d_in[5];
    const float* gat0_al  = (const float*)d_in[6];
    const float* gat0_ar  = (const float*)d_in[7];
    const float* gat0_b   = (const float*)d_in[8];
    const float* gat1_W   = (const float*)d_in[9];
    const float* gat1_al  = (const float*)d_in[10];
    const float* gat1_ar  = (const float*)d_in[11];
    const float* gat1_b   = (const float*)d_in[12];
    const float* gin0_eps = (const float*)d_in[13];
    const float* gin0_W1  = (const float*)d_in[14];
    const float* gin0_b1  = (const float*)d_in[15];
    const float* gin0_g1  = (const float*)d_in[16];
    const float* gin0_be1 = (const float*)d_in[17];
    const float* gin0_W2  = (const float*)d_in[18];
    const float* gin0_b2  = (const float*)d_in[19];
    const float* gin1_eps = (const float*)d_in[20];
    const float* gin1_W1  = (const float*)d_in[21];
    const float* gin1_b1  = (const float*)d_in[22];
    const float* gin1_g1  = (const float*)d_in[23];
    const float* gin1_be1 = (const float*)d_in[24];
    const float* gin1_W2  = (const float*)d_in[25];
    const float* gin1_b2  = (const float*)d_in[26];
    float* out = (float*)d_out;

    float *zb, *hb, *elb, *erb, *stb, *scb, *shb;
    unsigned int *whb, *wlb, *pahb, *palb, *fh, *fl;
    int *cntb, *rpb, *curb, *csb;
    cudaGetSymbolAddress((void**)&zb, g_z);
    cudaGetSymbolAddress((void**)&hb, g_h);
    cudaGetSymbolAddress((void**)&elb, g_el);
    cudaGetSymbolAddress((void**)&erb, g_er);
    cudaGetSymbolAddress((void**)&stb, g_stats);
    cudaGetSymbolAddress((void**)&scb, g_scale);
    cudaGetSymbolAddress((void**)&shb, g_shift);
    cudaGetSymbolAddress((void**)&whb, g_wh);
    cudaGetSymbolAddress((void**)&wlb, g_wl);
    cudaGetSymbolAddress((void**)&pahb, g_pah);
    cudaGetSymbolAddress((void**)&palb, g_pal);
    cudaGetSymbolAddress((void**)&fh, g_fh);
    cudaGetSymbolAddress((void**)&fl, g_fl);
    cudaGetSymbolAddress((void**)&cntb, g_cnt);
    cudaGetSymbolAddress((void**)&rpb, g_rowptr);
    cudaGetSymbolAddress((void**)&curb, g_cur);
    cudaGetSymbolAddress((void**)&csb, g_csrc);

    // feats -> packed once (shared by both types), on the capture stream pre-fork
    aconv_kernel<<<blk4(NN * FIN), 256>>>(feats, fh, fl, NN * FIN / 4);

    // fork
    cudaEventRecord(g_si.e0, 0);
    cudaStreamWaitEvent(g_si.s[0], g_si.e0, 0);
    cudaStreamWaitEvent(g_si.s[1], g_si.e0, 0);

    for (int t = 0; t < TTYP; t++) {
        TypeCtx c;
        c.z   = zb   + (size_t)t * NN * HIDD;
        c.h   = hb   + (size_t)t * NN * HIDD;
        c.el  = elb  + (size_t)t * NN * NHD;
        c.er  = erb  + (size_t)t * NN * NHD;
        c.stats = stb + (size_t)t * 2 * HIDD;
        c.scale = scb + (size_t)t * HIDD;
        c.shift = shb + (size_t)t * HIDD;
        c.wh  = whb  + (size_t)t * HIDD * KWMAX;
        c.wl  = wlb  + (size_t)t * HIDD * KWMAX;
        c.pah = pahb + (size_t)t * NN * PKW;
        c.pal = palb + (size_t)t * NN * PKW;
        c.cnt = cntb + (size_t)t * NN;
        c.rowptr = rpb + (size_t)t * (NN + 1);
        c.cur = curb + (size_t)t * NN;
        c.csrc = csb + (size_t)t * NE;
        c.st  = g_si.s[t];

        // ---- CSR build ----
        zero_int_kernel<<<(NN + 255) / 256, 256, 0, c.st>>>(c.cnt, NN);
        count_kernel<<<(NE + 255) / 256, 256, 0, c.st>>>(dst[t], c.cnt);
        scan_kernel<<<1, SCANT, 0, c.st>>>(c.cnt, c.rowptr, c.cur);
        fill_kernel<<<(NE + 255) / 256, 256, 0, c.st>>>(src[t], dst[t], c.cur, c.csrc);

        // ---- GAT layer 0: z = feats @ W; gather -> packed h0 ----
        gemm(c, fh, fl, gat0_W + (size_t)t * FIN * HIDD, nullptr, c.z, FIN, 0);
        elz_kernel<<<NODE_WARP_BLOCKS, 256, 0, c.st>>>(c.z, gat0_al + t * NHD * DH,
                                                       gat0_ar + t * NHD * DH, c.el, c.er);
        gat_gather_kernel<1><<<NODE_WARP_BLOCKS, 256, 0, c.st>>>(
            c.csrc, c.rowptr, c.el, c.er, c.z, gat0_b + t * HIDD, nullptr, c.pah, c.pal);

        // ---- GAT layer 1: z = h0 @ W; gather -> fp32 h ----
        gemm(c, c.pah, c.pal, gat1_W + (size_t)t * HIDD * HIDD, nullptr, c.z, HIDD, 0);
        elz_kernel<<<NODE_WARP_BLOCKS, 256, 0, c.st>>>(c.z, gat1_al + t * NHD * DH,
                                                       gat1_ar + t * NHD * DH, c.el, c.er);
        gat_gather_kernel<0><<<NODE_WARP_BLOCKS, 256, 0, c.st>>>(
            c.csrc, c.rowptr, c.el, c.er, c.z, gat1_b + t * HIDD, c.h, nullptr, nullptr);

        // ---- GIN layer 0 (F=384, implicit concat [h | feats]) ----
        gin_gather_kernel<<<NODE_WARP_BLOCKS, 256, 0, c.st>>>(
            c.csrc, c.rowptr, c.h, feats, HIDD, CATF, gin0_eps + t, c.pah, c.pal);
        gemm(c, c.pah, c.pal, gin0_W1 + (size_t)t * CATF * HIDD, gin0_b1 + t * HIDD,
             c.z, CATF, 0);
        zero_kernel<<<1, 128, 0, c.st>>>(c.stats, 2 * HIDD);
        stats_kernel<<<512, HIDD, 0, c.st>>>(c.z, c.stats);
        bnfin_kernel<<<1, HIDD, 0, c.st>>>(gin0_g1 + t * HIDD, gin0_be1 + t * HIDD,
                                           c.stats, c.scale, c.shift);
        bnrelu_kernel<<<blk4(NN * HIDD), 256, 0, c.st>>>(c.z, c.scale, c.shift, c.pah, c.pal);
        gemm(c, c.pah, c.pal, gin0_W2 + (size_t)t * HIDD * HIDD, gin0_b2 + t * HIDD,
             c.h, HIDD, 1);

        // ---- GIN layer 1 (F=256) ----
        gin_gather_kernel<<<NODE_WARP_BLOCKS, 256, 0, c.st>>>(
            c.csrc, c.rowptr, c.h, nullptr, HIDD, HIDD, gin1_eps + t, c.pah, c.pal);
        gemm(c, c.pah, c.pal, gin1_W1 + (size_t)t * HIDD * HIDD, gin1_b1 + t * HIDD,
             c.z, HIDD, 0);
        zero_kernel<<<1, 128, 0, c.st>>>(c.stats, 2 * HIDD);
        stats_kernel<<<512, HIDD, 0, c.st>>>(c.z, c.stats);
        bnfin_kernel<<<1, HIDD, 0, c.st>>>(gin1_g1 + t * HIDD, gin1_be1 + t * HIDD,
                                           c.stats, c.scale, c.shift);
        bnrelu_kernel<<<blk4(NN * HIDD), 256, 0, c.st>>>(c.z, c.scale, c.shift, c.pah, c.pal);
        gemm(c, c.pah, c.pal, gin1_W2 + (size_t)t * HIDD * HIDD, gin1_b2 + t * HIDD,
             out, HIDD, 1, TTYP * HIDD, t * HIDD);
    }

    // join
    cudaEventRecord(g_si.e1, g_si.s[0]);
    cudaEventRecord(g_si.e2, g_si.s[1]);
    cudaStreamWaitEvent((cudaStream_t)0, g_si.e1, 0);
    cudaStreamWaitEvent((cudaStream_t)0, g_si.e2, 0);
}

// round 9
// speedup vs baseline: 2.0029x; 1.1483x over previous
#include <cuda_runtime.h>
#include <cuda_bf16.h>
#include <math.h>

#define NN   50000
#define FIN  128
#define HIDD 256
#define NHD  4
#define DH   64
#define NE   400000
#define CATF 384
#define TTYP 2
#define KWMAX (CATF/2)
#define PKW   (CATF/2)
#define NSLOT 6
#define SCB   196            /* scan blocks: 196*256 >= NN */

// ---------------- per-type scratch (device globals) ------------------------
static __device__ float g_z  [TTYP][(size_t)NN*HIDD];
static __device__ float g_h  [TTYP][(size_t)NN*HIDD];
static __device__ float g_el [TTYP][NN*NHD];
static __device__ float g_er [TTYP][NN*NHD];
static __device__ float g_stats[TTYP][2*HIDD];
static __device__ float g_scale[TTYP][HIDD];
static __device__ float g_shift[TTYP][HIDD];
static __device__ unsigned int g_wh[TTYP][NSLOT][HIDD*KWMAX];
static __device__ unsigned int g_wl[TTYP][NSLOT][HIDD*KWMAX];
static __device__ unsigned int g_pah[TTYP][(size_t)NN*PKW];
static __device__ unsigned int g_pal[TTYP][(size_t)NN*PKW];
static __device__ unsigned int g_fh[(size_t)NN*(FIN/2)];
static __device__ unsigned int g_fl[(size_t)NN*(FIN/2)];
// CSR
static __device__ int g_cnt[TTYP][NN];
static __device__ int g_rowptr[TTYP][NN+1];
static __device__ int g_cur[TTYP][NN];
static __device__ int g_csrc[TTYP][NE];
static __device__ int g_bsum[TTYP][SCB];
static __device__ int g_boff[TTYP][SCB];

#define SSTR 20
#define GEMM_SMEM (2 * 4 * 128 * SSTR * 4)   /* 2 stages x 4 bufs x 128xSSTR uints */

__global__ void gemm_tc_kernel(const unsigned int*, const unsigned int*,
                               const unsigned int*, const unsigned int*,
                               const float*, float*, int, int, int, int, int);

// ---------------- streams/events (created once, statically) ----------------
namespace {
struct SI {
    cudaStream_t s[TTYP];
    cudaEvent_t e0, e1, e2;
    SI() {
        cudaStreamCreateWithFlags(&s[0], cudaStreamNonBlocking);
        cudaStreamCreateWithFlags(&s[1], cudaStreamNonBlocking);
        cudaEventCreateWithFlags(&e0, cudaEventDisableTiming);
        cudaEventCreateWithFlags(&e1, cudaEventDisableTiming);
        cudaEventCreateWithFlags(&e2, cudaEventDisableTiming);
        cudaFuncSetAttribute(gemm_tc_kernel,
                             cudaFuncAttributeMaxDynamicSharedMemorySize, GEMM_SMEM);
    }
};
SI g_si;
}

// ---------------- helpers --------------------------------------------------
__device__ __forceinline__ float lrelu(float v) { return v >= 0.f ? v : 0.2f * v; }

__device__ __forceinline__ unsigned int pack2(__nv_bfloat16 a, __nv_bfloat16 b) {
    return (unsigned int)__bfloat16_as_ushort(a) |
           ((unsigned int)__bfloat16_as_ushort(b) << 16);
}

__device__ __forceinline__ void split_bf(float v, __nv_bfloat16& h, __nv_bfloat16& l) {
    h = __float2bfloat16_rn(v);
    l = __float2bfloat16_rn(v - __bfloat162float(h));
}

__device__ __forceinline__ void split4(float4 v, unsigned int* hp, unsigned int* lp) {
    __nv_bfloat16 h0, h1, h2, h3, l0, l1, l2, l3;
    split_bf(v.x, h0, l0); split_bf(v.y, h1, l1);
    split_bf(v.z, h2, l2); split_bf(v.w, h3, l3);
    hp[0] = pack2(h0, h1); hp[1] = pack2(h2, h3);
    lp[0] = pack2(l0, l1); lp[1] = pack2(l2, l3);
}

__device__ __forceinline__ void mma16816(float* c, const unsigned int* a, const unsigned int* b) {
    asm volatile(
        "mma.sync.aligned.m16n8k16.row.col.f32.bf16.bf16.f32 "
        "{%0,%1,%2,%3}, {%4,%5,%6,%7}, {%8,%9}, {%0,%1,%2,%3};"
        : "+f"(c[0]), "+f"(c[1]), "+f"(c[2]), "+f"(c[3])
        : "r"(a[0]), "r"(a[1]), "r"(a[2]), "r"(a[3]), "r"(b[0]), "r"(b[1]));
}

__device__ __forceinline__ void cp16(unsigned int* dst, const unsigned int* src, int sz) {
    unsigned int d = (unsigned int)__cvta_generic_to_shared(dst);
    asm volatile("cp.async.cg.shared.global [%0], [%1], 16, %2;"
                 :: "r"(d), "l"(src), "r"(sz) : "memory");
}
__device__ __forceinline__ void cp_commit() {
    asm volatile("cp.async.commit_group;" ::: "memory");
}
template <int N>
__device__ __forceinline__ void cp_wait() {
    asm volatile("cp.async.wait_group %0;" :: "n"(N) : "memory");
}

// ---------------- CSR build -------------------------------------------------
__global__ void zero_int_kernel(int* __restrict__ p, int n) {
    int i = blockIdx.x * blockDim.x + threadIdx.x;
    if (i < n) p[i] = 0;
}

__global__ void count_kernel(const int* __restrict__ dst, int* __restrict__ cnt) {
    int e = blockIdx.x * blockDim.x + threadIdx.x;
    if (e < NE) atomicAdd(&cnt[dst[e]], 1);
}

// block partial sums
__global__ void scan1_kernel(const int* __restrict__ cnt, int* __restrict__ bsum) {
    __shared__ int sh[256];
    int i = blockIdx.x * 256 + threadIdx.x;
    sh[threadIdx.x] = (i < NN) ? cnt[i] : 0;
    __syncthreads();
    for (int off = 128; off; off >>= 1) {
        if (threadIdx.x < off) sh[threadIdx.x] += sh[threadIdx.x + off];
        __syncthreads();
    }
    if (threadIdx.x == 0) bsum[blockIdx.x] = sh[0];
}

// exclusive scan of SCB block sums (1 block); writes rowptr[NN] = total
__global__ void scan2_kernel(const int* __restrict__ bsum, int* __restrict__ boff,
                             int* __restrict__ rowptr) {
    __shared__ int sh[256];
    int tid = threadIdx.x;
    int v = (tid < SCB) ? bsum[tid] : 0;
    sh[tid] = v;
    __syncthreads();
    for (int off = 1; off < 256; off <<= 1) {
        int u = (tid >= off) ? sh[tid - off] : 0;
        __syncthreads();
        sh[tid] += u;
        __syncthreads();
    }
    if (tid < SCB) boff[tid] = sh[tid] - v;   // exclusive
    if (tid == SCB - 1) rowptr[NN] = sh[tid];
}

// per-element exclusive prefix within block + block offset
__global__ void scan3_kernel(const int* __restrict__ cnt, const int* __restrict__ boff,
                             int* __restrict__ rowptr, int* __restrict__ cur) {
    __shared__ int sh[256];
    int tid = threadIdx.x;
    int i = blockIdx.x * 256 + tid;
    int v = (i < NN) ? cnt[i] : 0;
    sh[tid] = v;
    __syncthreads();
    for (int off = 1; off < 256; off <<= 1) {
        int u = (tid >= off) ? sh[tid - off] : 0;
        __syncthreads();
        sh[tid] += u;
        __syncthreads();
    }
    if (i < NN) {
        int r = boff[blockIdx.x] + sh[tid] - v;
        rowptr[i] = r;
        cur[i] = r;
    }
}

__global__ void fill_kernel(const int* __restrict__ src, const int* __restrict__ dst,
                            int* __restrict__ cur, int* __restrict__ csrc) {
    int e = blockIdx.x * blockDim.x + threadIdx.x;
    if (e >= NE) return;
    int pos = atomicAdd(&cur[dst[e]], 1);
    csrc[pos] = src[e];
}

// ---------------- converters ------------------------------------------------
__global__ void aconv_kernel(const float* __restrict__ A, unsigned int* __restrict__ H,
                             unsigned int* __restrict__ L, int n4) {
    int idx = blockIdx.x * blockDim.x + threadIdx.x;
    if (idx >= n4) return;
    float4 v = *(const float4*)(A + (size_t)idx * 4);
    unsigned int hp[2], lp[2];
    split4(v, hp, lp);
    *(uint2*)(H + (size_t)idx * 2) = make_uint2(hp[0], hp[1]);
    *(uint2*)(L + (size_t)idx * 2) = make_uint2(lp[0], lp[1]);
}

__global__ void wconv_kernel(const float* __restrict__ W, int K,
                             unsigned int* __restrict__ wh, unsigned int* __restrict__ wl) {
    int idx = blockIdx.x * blockDim.x + threadIdx.x;
    int Kw = K / 2;
    if (idx >= HIDD * Kw) return;
    int n = idx / Kw;
    int kp = idx - n * Kw;
    float v0 = W[(size_t)(2 * kp) * HIDD + n];
    float v1 = W[(size_t)(2 * kp + 1) * HIDD + n];
    __nv_bfloat16 h0, h1, l0, l1;
    split_bf(v0, h0, l0); split_bf(v1, h1, l1);
    wh[idx] = pack2(h0, h1);
    wl[idx] = pack2(l0, l1);
}

// ---------------- tensor-core GEMM: cp.async double-buffered ----------------
__global__ __launch_bounds__(256, 2)
void gemm_tc_kernel(const unsigned int* __restrict__ AHg, const unsigned int* __restrict__ ALg,
                    const unsigned int* __restrict__ BHg, const unsigned int* __restrict__ BLg,
                    const float* __restrict__ bias, float* __restrict__ C,
                    int M, int Kw, int ldc, int coff, int relu_flag) {
    extern __shared__ unsigned int smem[];
    const int BUF = 128 * SSTR;
    unsigned int* AH = smem;
    unsigned int* AL = AH + 2 * BUF;
    unsigned int* BH = AL + 2 * BUF;
    unsigned int* BL = BH + 2 * BUF;

    int tid = threadIdx.x;
    int lane = tid & 31, wid = tid >> 5;
    int lm = lane >> 2, lc = lane & 3;
    int m0 = (wid >> 2) * 64;
    int n0w = (wid & 3) * 32;
    int rowBase = blockIdx.y * 128;
    int colBase = blockIdx.x * 128;

    float acc[16][4];
#pragma unroll
    for (int i = 0; i < 16; i++)
#pragma unroll
        for (int j = 0; j < 4; j++) acc[i][j] = 0.f;

    int nkt = Kw / 16;

    // staging map (fixed per thread)
    int sm_ = (tid >> 2);            // 0..63 -> two rows via i*64... (m = p>>2, p=tid+i*256)
    // stage loader
    auto stage = [&](int sidx, int kt) {
        int k0w = kt * 16;
        int off = sidx * BUF;
#pragma unroll
        for (int i = 0; i < 2; i++) {
            int p = tid + i * 256;
            int m = p >> 2;
            int cc = (p & 3) * 4;
            int row = rowBase + m;
            int sz = (row < M) ? 16 : 0;
            cp16(&AH[off + m * SSTR + cc], AHg + (size_t)row * Kw + k0w + cc, sz);
            cp16(&AL[off + m * SSTR + cc], ALg + (size_t)row * Kw + k0w + cc, sz);
            int n = colBase + m;
            cp16(&BH[off + m * SSTR + cc], BHg + (size_t)n * Kw + k0w + cc, 16);
            cp16(&BL[off + m * SSTR + cc], BLg + (size_t)n * Kw + k0w + cc, 16);
        }
        cp_commit();
    };
    (void)sm_;

    stage(0, 0);

    for (int kt = 0; kt < nkt; kt++) {
        int cur = kt & 1;
        if (kt + 1 < nkt) {
            stage(cur ^ 1, kt + 1);
            cp_wait<1>();
        } else {
            cp_wait<0>();
        }
        __syncthreads();
        int off = cur * BUF;
#pragma unroll
        for (int kk = 0; kk < 2; kk++) {
            int kw = kk * 8;
            unsigned int ah[4][4], al[4][4], bh[4][2], bl[4][2];
#pragma unroll
            for (int mi = 0; mi < 4; mi++) {
                int r = m0 + mi * 16 + lm;
                int w0 = off + r * SSTR + kw + lc;
                int w1 = off + (r + 8) * SSTR + kw + lc;
                ah[mi][0] = AH[w0]; ah[mi][1] = AH[w1];
                ah[mi][2] = AH[w0 + 4]; ah[mi][3] = AH[w1 + 4];
                al[mi][0] = AL[w0]; al[mi][1] = AL[w1];
                al[mi][2] = AL[w0 + 4]; al[mi][3] = AL[w1 + 4];
            }
#pragma unroll
            for (int ni = 0; ni < 4; ni++) {
                int n = n0w + ni * 8 + lm;
                int w0 = off + n * SSTR + kw + lc;
                bh[ni][0] = BH[w0]; bh[ni][1] = BH[w0 + 4];
                bl[ni][0] = BL[w0]; bl[ni][1] = BL[w0 + 4];
            }
#pragma unroll
            for (int mi = 0; mi < 4; mi++)
#pragma unroll
                for (int ni = 0; ni < 4; ni++) {
                    float* c = acc[mi * 4 + ni];
                    mma16816(c, ah[mi], bh[ni]);
                    mma16816(c, ah[mi], bl[ni]);
                    mma16816(c, al[mi], bh[ni]);
                }
        }
        __syncthreads();
    }

#pragma unroll
    for (int mi = 0; mi < 4; mi++) {
#pragma unroll
        for (int ni = 0; ni < 4; ni++) {
            float* c = acc[mi * 4 + ni];
            int r0 = rowBase + m0 + mi * 16 + lm;
            int r1 = r0 + 8;
            int col = colBase + n0w + ni * 8 + lc * 2;
            float b0 = bias ? bias[col] : 0.f;
            float b1 = bias ? bias[col + 1] : 0.f;
            float v0 = c[0] + b0, v1 = c[1] + b1;
            float v2 = c[2] + b0, v3 = c[3] + b1;
            if (relu_flag) {
                v0 = fmaxf(v0, 0.f); v1 = fmaxf(v1, 0.f);
                v2 = fmaxf(v2, 0.f); v3 = fmaxf(v3, 0.f);
            }
            if (r0 < M) *(float2*)(C + (size_t)r0 * ldc + coff + col) = make_float2(v0, v1);
            if (r1 < M) *(float2*)(C + (size_t)r1 * ldc + coff + col) = make_float2(v2, v3);
        }
    }
}

// ---------------- GAT pieces ------------------------------------------------
__global__ __launch_bounds__(256)
void elz_kernel(const float* __restrict__ z,
                const float* __restrict__ al, const float* __restrict__ ar,
                float* __restrict__ elp, float* __restrict__ erp) {
    int warp = (blockIdx.x * blockDim.x + threadIdx.x) >> 5;
    if (warp >= NN) return;
    int lane = threadIdx.x & 31;
    const float4* zp = (const float4*)(z + (size_t)warp * HIDD + lane * 8);
    float4 z0 = zp[0], z1 = zp[1];
    const float4* ap = (const float4*)(al + lane * 8);
    float4 a0 = ap[0], a1 = ap[1];
    const float4* bp = (const float4*)(ar + lane * 8);
    float4 b0 = bp[0], b1 = bp[1];
    float el = z0.x*a0.x + z0.y*a0.y + z0.z*a0.z + z0.w*a0.w
             + z1.x*a1.x + z1.y*a1.y + z1.z*a1.z + z1.w*a1.w;
    float er = z0.x*b0.x + z0.y*b0.y + z0.z*b0.z + z0.w*b0.w
             + z1.x*b1.x + z1.y*b1.y + z1.z*b1.z + z1.w*b1.w;
#pragma unroll
    for (int off = 4; off; off >>= 1) {
        el += __shfl_xor_sync(0xffffffffu, el, off);
        er += __shfl_xor_sync(0xffffffffu, er, off);
    }
    if ((lane & 7) == 0) {
        int head = lane >> 3;
        elp[warp * NHD + head] = el;
        erp[warp * NHD + head] = er;
    }
}

template <int PACKED>
__global__ __launch_bounds__(256)
void gat_gather_kernel(const int* __restrict__ csrc, const int* __restrict__ rowptr,
                       const float* __restrict__ elp, const float* __restrict__ erp,
                       const float* __restrict__ z, const float* __restrict__ bias,
                       float* __restrict__ hout,
                       unsigned int* __restrict__ pah, unsigned int* __restrict__ pal) {
    int warp = (blockIdx.x * blockDim.x + threadIdx.x) >> 5;
    if (warp >= NN) return;
    int lane = threadIdx.x & 31;
    int head = lane >> 3;
    int beg = rowptr[warp], end = rowptr[warp + 1];
    float erh = erp[warp * NHD + head];

    float m = -INFINITY;
    for (int i = beg; i < end; i++) {
        int s = csrc[i];
        m = fmaxf(m, lrelu(elp[s * NHD + head] + erh));
    }
    if (m < -3.0e38f) m = 0.f;

    float den = 0.f;
    float msg[8] = {0.f, 0.f, 0.f, 0.f, 0.f, 0.f, 0.f, 0.f};
    for (int i = beg; i < end; i++) {
        int s = csrc[i];
        float p = __expf(lrelu(elp[s * NHD + head] + erh) - m);
        den += p;
        const float4* zp = (const float4*)(z + (size_t)s * HIDD + lane * 8);
        float4 a = zp[0], b = zp[1];
        msg[0] += p * a.x; msg[1] += p * a.y; msg[2] += p * a.z; msg[3] += p * a.w;
        msg[4] += p * b.x; msg[5] += p * b.y; msg[6] += p * b.z; msg[7] += p * b.w;
    }
    float inv = 1.f / fmaxf(den, 1e-9f);
    const float4* bp = (const float4*)(bias + lane * 8);
    float4 b0 = bp[0], b1 = bp[1];
    float4 o0, o1;
    o0.x = fmaxf(msg[0] * inv + b0.x, 0.f);
    o0.y = fmaxf(msg[1] * inv + b0.y, 0.f);
    o0.z = fmaxf(msg[2] * inv + b0.z, 0.f);
    o0.w = fmaxf(msg[3] * inv + b0.w, 0.f);
    o1.x = fmaxf(msg[4] * inv + b1.x, 0.f);
    o1.y = fmaxf(msg[5] * inv + b1.y, 0.f);
    o1.z = fmaxf(msg[6] * inv + b1.z, 0.f);
    o1.w = fmaxf(msg[7] * inv + b1.w, 0.f);
    if (PACKED) {
        unsigned int hp[4], lp[4];
        split4(o0, hp, lp);
        split4(o1, hp + 2, lp + 2);
        *(uint4*)(pah + (size_t)warp * (HIDD / 2) + lane * 4) = make_uint4(hp[0], hp[1], hp[2], hp[3]);
        *(uint4*)(pal + (size_t)warp * (HIDD / 2) + lane * 4) = make_uint4(lp[0], lp[1], lp[2], lp[3]);
    } else {
        float4* op = (float4*)(hout + (size_t)warp * HIDD + lane * 8);
        op[0] = o0; op[1] = o1;
    }
}

__global__ __launch_bounds__(256)
void gin_gather_kernel(const int* __restrict__ csrc, const int* __restrict__ rowptr,
                       const float* __restrict__ hA, const float* __restrict__ hB,
                       int FA, int F, const float* __restrict__ epsp,
                       unsigned int* __restrict__ ph, unsigned int* __restrict__ pl) {
    int warp = (blockIdx.x * blockDim.x + threadIdx.x) >> 5;
    if (warp >= NN) return;
    int lane = threadIdx.x & 31;
    int beg = rowptr[warp], end = rowptr[warp + 1];
    float e = 1.f + epsp[0];
    int FB = F - FA;
    for (int f = lane * 4; f < F; f += 128) {
        const float* base = (f < FA) ? (hA + (size_t)warp * FA + f)
                                     : (hB + (size_t)warp * FB + (f - FA));
        float4 hv = *(const float4*)base;
        float4 a = make_float4(e * hv.x, e * hv.y, e * hv.z, e * hv.w);
        if (f < FA) {
            for (int i = beg; i < end; i++) {
                int s = csrc[i];
                float4 v = *(const float4*)(hA + (size_t)s * FA + f);
                a.x += v.x; a.y += v.y; a.z += v.z; a.w += v.w;
            }
        } else {
            for (int i = beg; i < end; i++) {
                int s = csrc[i];
                float4 v = *(const float4*)(hB + (size_t)s * FB + (f - FA));
                a.x += v.x; a.y += v.y; a.z += v.z; a.w += v.w;
            }
        }
        unsigned int hp[2], lp[2];
        split4(a, hp, lp);
        *(uint2*)(ph + (size_t)warp * (F / 2) + (f >> 1)) = make_uint2(hp[0], hp[1]);
        *(uint2*)(pl + (size_t)warp * (F / 2) + (f >> 1)) = make_uint2(lp[0], lp[1]);
    }
}

// ---------------- BN pieces -------------------------------------------------
__global__ void stats_kernel(const float* __restrict__ y, float* __restrict__ stats) {
    int col = threadIdx.x;
    float s = 0.f, s2 = 0.f;
    for (int r = blockIdx.x; r < NN; r += gridDim.x) {
        float v = y[(size_t)r * HIDD + col];
        s += v; s2 += v * v;
    }
    atomicAdd(&stats[col], s);
    atomicAdd(&stats[HIDD + col], s2);
}

__global__ void bnfin_kernel(const float* __restrict__ g1, const float* __restrict__ be1,
                             const float* __restrict__ stats,
                             float* __restrict__ scale, float* __restrict__ shift) {
    int c = threadIdx.x;
    float inv = 1.f / (float)NN;
    float mu = stats[c] * inv;
    float var = stats[HIDD + c] * inv - mu * mu;
    float rstd = rsqrtf(var + 1e-5f);
    float sc = g1[c] * rstd;
    scale[c] = sc;
    shift[c] = be1[c] - mu * sc;
}

__global__ void bnrelu_kernel(const float* __restrict__ y, const float* __restrict__ scale,
                              const float* __restrict__ shift,
                              unsigned int* __restrict__ ph, unsigned int* __restrict__ pl) {
    int idx = blockIdx.x * blockDim.x + threadIdx.x;
    int i4 = idx * 4;
    if (i4 >= NN * HIDD) return;
    int c = i4 & (HIDD - 1);
    float4 v = *(const float4*)(y + i4);
    float4 sc = *(const float4*)(scale + c);
    float4 sh = *(const float4*)(shift + c);
    v.x = fmaxf(v.x * sc.x + sh.x, 0.f);
    v.y = fmaxf(v.y * sc.y + sh.y, 0.f);
    v.z = fmaxf(v.z * sc.z + sh.z, 0.f);
    v.w = fmaxf(v.w * sc.w + sh.w, 0.f);
    unsigned int hp[2], lp[2];
    split4(v, hp, lp);
    *(uint2*)(ph + (size_t)idx * 2) = make_uint2(hp[0], hp[1]);
    *(uint2*)(pl + (size_t)idx * 2) = make_uint2(lp[0], lp[1]);
}

__global__ void zero_kernel(float* __restrict__ p, int n) {
    int idx = blockIdx.x * blockDim.x + threadIdx.x;
    int i4 = idx * 4;
    if (i4 >= n) return;
    *(float4*)(p + i4) = make_float4(0.f, 0.f, 0.f, 0.f);
}

// ---------------- host orchestration ---------------------------------------
static inline int blk4(int n) { return (n / 4 + 255) / 256; }
#define NODE_WARP_BLOCKS ((NN * 32 + 255) / 256)

struct TypeCtx {
    float *z, *h, *el, *er, *stats, *scale, *shift;
    unsigned int *pah, *pal;
    unsigned int *wh[NSLOT], *wl[NSLOT];
    int *cnt, *rowptr, *cur, *csrc, *bsum, *boff;
    cudaStream_t st;
};

static void gemm(const TypeCtx& c, const unsigned int* AH, const unsigned int* AL,
                 int slot, const float* b, float* C,
                 int K, int relu, int ldc = HIDD, int coff = 0) {
    dim3 grid(HIDD / 128, (NN + 127) / 128);
    gemm_tc_kernel<<<grid, 256, GEMM_SMEM, c.st>>>(AH, AL, c.wh[slot], c.wl[slot],
                                                   b, C, NN, K / 2, ldc, coff, relu);
}

extern "C" void kernel_launch(void* const* d_in, const int* in_sizes, int n_in,
                              void* d_out, int out_size) {
    const float* feats = (const float*)d_in[0];
    const int* src[2] = { (const int*)d_in[1], (const int*)d_in[3] };
    const int* dst[2] = { (const int*)d_in[2], (const int*)d_in[4] };
    const float* gat0_W   = (const float*)d_in[5];
    const float* gat0_al  = (const float*)d_in[6];
    const float* gat0_ar  = (const float*)d_in[7];
    const float* gat0_b   = (const float*)d_in[8];
    const float* gat1_W   = (const float*)d_in[9];
    const float* gat1_al  = (const float*)d_in[10];
    const float* gat1_ar  = (const float*)d_in[11];
    const float* gat1_b   = (const float*)d_in[12];
    const float* gin0_eps = (const float*)d_in[13];
    const float* gin0_W1  = (const float*)d_in[14];
    const float* gin0_b1  = (const float*)d_in[15];
    const float* gin0_g1  = (const float*)d_in[16];
    const float* gin0_be1 = (const float*)d_in[17];
    const float* gin0_W2  = (const float*)d_in[18];
    const float* gin0_b2  = (const float*)d_in[19];
    const float* gin1_eps = (const float*)d_in[20];
    const float* gin1_W1  = (const float*)d_in[21];
    const float* gin1_b1  = (const float*)d_in[22];
    const float* gin1_g1  = (const float*)d_in[23];
    const float* gin1_be1 = (const float*)d_in[24];
    const float* gin1_W2  = (const float*)d_in[25];
    const float* gin1_b2  = (const float*)d_in[26];
    float* out = (float*)d_out;

    float *zb, *hb, *elb, *erb, *stb, *scb, *shb;
    unsigned int *whb, *wlb, *pahb, *palb, *fh, *fl;
    int *cntb, *rpb, *curb, *csb, *bsb, *bob;
    cudaGetSymbolAddress((void**)&zb, g_z);
    cudaGetSymbolAddress((void**)&hb, g_h);
    cudaGetSymbolAddress((void**)&elb, g_el);
    cudaGetSymbolAddress((void**)&erb, g_er);
    cudaGetSymbolAddress((void**)&stb, g_stats);
    cudaGetSymbolAddress((void**)&scb, g_scale);
    cudaGetSymbolAddress((void**)&shb, g_shift);
    cudaGetSymbolAddress((void**)&whb, g_wh);
    cudaGetSymbolAddress((void**)&wlb, g_wl);
    cudaGetSymbolAddress((void**)&pahb, g_pah);
    cudaGetSymbolAddress((void**)&palb, g_pal);
    cudaGetSymbolAddress((void**)&fh, g_fh);
    cudaGetSymbolAddress((void**)&fl, g_fl);
    cudaGetSymbolAddress((void**)&cntb, g_cnt);
    cudaGetSymbolAddress((void**)&rpb, g_rowptr);
    cudaGetSymbolAddress((void**)&curb, g_cur);
    cudaGetSymbolAddress((void**)&csb, g_csrc);
    cudaGetSymbolAddress((void**)&bsb, g_bsum);
    cudaGetSymbolAddress((void**)&bob, g_boff);

    aconv_kernel<<<blk4(NN * FIN), 256>>>(feats, fh, fl, NN * FIN / 4);

    cudaEventRecord(g_si.e0, 0);
    cudaStreamWaitEvent(g_si.s[0], g_si.e0, 0);
    cudaStreamWaitEvent(g_si.s[1], g_si.e0, 0);

    const float* Wsrc[TTYP][NSLOT];
    const int Wk[NSLOT] = { FIN, HIDD, CATF, HIDD, HIDD, HIDD };
    for (int t = 0; t < TTYP; t++) {
        Wsrc[t][0] = gat0_W + (size_t)t * FIN * HIDD;
        Wsrc[t][1] = gat1_W + (size_t)t * HIDD * HIDD;
        Wsrc[t][2] = gin0_W1 + (size_t)t * CATF * HIDD;
        Wsrc[t][3] = gin0_W2 + (size_t)t * HIDD * HIDD;
        Wsrc[t][4] = gin1_W1 + (size_t)t * HIDD * HIDD;
        Wsrc[t][5] = gin1_W2 + (size_t)t * HIDD * HIDD;
    }

    for (int t = 0; t < TTYP; t++) {
        TypeCtx c;
        c.z   = zb   + (size_t)t * NN * HIDD;
        c.h   = hb   + (size_t)t * NN * HIDD;
        c.el  = elb  + (size_t)t * NN * NHD;
        c.er  = erb  + (size_t)t * NN * NHD;
        c.stats = stb + (size_t)t * 2 * HIDD;
        c.scale = scb + (size_t)t * HIDD;
        c.shift = shb + (size_t)t * HIDD;
        for (int s = 0; s < NSLOT; s++) {
            c.wh[s] = whb + ((size_t)t * NSLOT + s) * HIDD * KWMAX;
            c.wl[s] = wlb + ((size_t)t * NSLOT + s) * HIDD * KWMAX;
        }
        c.pah = pahb + (size_t)t * NN * PKW;
        c.pal = palb + (size_t)t * NN * PKW;
        c.cnt = cntb + (size_t)t * NN;
        c.rowptr = rpb + (size_t)t * (NN + 1);
        c.cur = curb + (size_t)t * NN;
        c.csrc = csb + (size_t)t * NE;
        c.bsum = bsb + (size_t)t * SCB;
        c.boff = bob + (size_t)t * SCB;
        c.st  = g_si.s[t];

        // ---- all weight conversions up front ----
        for (int s = 0; s < NSLOT; s++) {
            int wtot = HIDD * (Wk[s] / 2);
            wconv_kernel<<<(wtot + 255) / 256, 256, 0, c.st>>>(Wsrc[t][s], Wk[s],
                                                               c.wh[s], c.wl[s]);
        }

        // ---- CSR build (parallel scan) ----
        zero_int_kernel<<<(NN + 255) / 256, 256, 0, c.st>>>(c.cnt, NN);
        count_kernel<<<(NE + 255) / 256, 256, 0, c.st>>>(dst[t], c.cnt);
        scan1_kernel<<<SCB, 256, 0, c.st>>>(c.cnt, c.bsum);
        scan2_kernel<<<1, 256, 0, c.st>>>(c.bsum, c.boff, c.rowptr);
        scan3_kernel<<<SCB, 256, 0, c.st>>>(c.cnt, c.boff, c.rowptr, c.cur);
        fill_kernel<<<(NE + 255) / 256, 256, 0, c.st>>>(src[t], dst[t], c.cur, c.csrc);

        // ---- GAT layer 0 ----
        gemm(c, fh, fl, 0, nullptr, c.z, FIN, 0);
        elz_kernel<<<NODE_WARP_BLOCKS, 256, 0, c.st>>>(c.z, gat0_al + t * NHD * DH,
                                                       gat0_ar + t * NHD * DH, c.el, c.er);
        gat_gather_kernel<1><<<NODE_WARP_BLOCKS, 256, 0, c.st>>>(
            c.csrc, c.rowptr, c.el, c.er, c.z, gat0_b + t * HIDD, nullptr, c.pah, c.pal);

        // ---- GAT layer 1 ----
        gemm(c, c.pah, c.pal, 1, nullptr, c.z, HIDD, 0);
        elz_kernel<<<NODE_WARP_BLOCKS, 256, 0, c.st>>>(c.z, gat1_al + t * NHD * DH,
                                                       gat1_ar + t * NHD * DH, c.el, c.er);
        gat_gather_kernel<0><<<NODE_WARP_BLOCKS, 256, 0, c.st>>>(
            c.csrc, c.rowptr, c.el, c.er, c.z, gat1_b + t * HIDD, c.h, nullptr, nullptr);

        // ---- GIN layer 0 (F=384, implicit concat [h | feats]) ----
        gin_gather_kernel<<<NODE_WARP_BLOCKS, 256, 0, c.st>>>(
            c.csrc, c.rowptr, c.h, feats, HIDD, CATF, gin0_eps + t, c.pah, c.pal);
        gemm(c, c.pah, c.pal, 2, gin0_b1 + t * HIDD, c.z, CATF, 0);
        zero_kernel<<<1, 128, 0, c.st>>>(c.stats, 2 * HIDD);
        stats_kernel<<<512, HIDD, 0, c.st>>>(c.z, c.stats);
        bnfin_kernel<<<1, HIDD, 0, c.st>>>(gin0_g1 + t * HIDD, gin0_be1 + t * HIDD,
                                           c.stats, c.scale, c.shift);
        bnrelu_kernel<<<blk4(NN * HIDD), 256, 0, c.st>>>(c.z, c.scale, c.shift, c.pah, c.pal);
        gemm(c, c.pah, c.pal, 3, gin0_b2 + t * HIDD, c.h, HIDD, 1);

        // ---- GIN layer 1 (F=256) ----
        gin_gather_kernel<<<NODE_WARP_BLOCKS, 256, 0, c.st>>>(
            c.csrc, c.rowptr, c.h, nullptr, HIDD, HIDD, gin1_eps + t, c.pah, c.pal);
        gemm(c, c.pah, c.pal, 4, gin1_b1 + t * HIDD, c.z, HIDD, 0);
        zero_kernel<<<1, 128, 0, c.st>>>(c.stats, 2 * HIDD);
        stats_kernel<<<512, HIDD, 0, c.st>>>(c.z, c.stats);
        bnfin_kernel<<<1, HIDD, 0, c.st>>>(gin1_g1 + t * HIDD, gin1_be1 + t * HIDD,
                                           c.stats, c.scale, c.shift);
        bnrelu_kernel<<<blk4(NN * HIDD), 256, 0, c.st>>>(c.z, c.scale, c.shift, c.pah, c.pal);
        gemm(c, c.pah, c.pal, 5, gin1_b2 + t * HIDD, out, HIDD, 1, TTYP * HIDD, t * HIDD);
    }

    cudaEventRecord(g_si.e1, g_si.s[0]);
    cudaEventRecord(g_si.e2, g_si.s[1]);
    cudaStreamWaitEvent((cudaStream_t)0, g_si.e1, 0);
    cudaStreamWaitEvent((cudaStream_t)0, g_si.e2, 0);
}

// round 10
// speedup vs baseline: 2.1248x; 1.0609x over previous
#include <cuda_runtime.h>
#include <cuda_bf16.h>
#include <math.h>

#define NN   50000
#define FIN  128
#define HIDD 256
#define NHD  4
#define DH   64
#define NE   400000
#define CATF 384
#define TTYP 2
#define KWMAX (CATF/2)
#define PKW   (CATF/2)
#define NSLOT 6
#define SCB   196

// ---------------- per-type scratch (device globals) ------------------------
static __device__ float g_z  [TTYP][(size_t)NN*HIDD];
static __device__ float g_h  [TTYP][(size_t)NN*HIDD];
static __device__ float g_el [TTYP][NN*NHD];
static __device__ float g_er [TTYP][NN*NHD];
static __device__ float g_stats[TTYP][2*HIDD];
static __device__ float g_scale[TTYP][HIDD];
static __device__ float g_shift[TTYP][HIDD];
static __device__ unsigned int g_wh[TTYP][NSLOT][HIDD*KWMAX];
static __device__ unsigned int g_wl[TTYP][NSLOT][HIDD*KWMAX];
static __device__ unsigned int g_pah[TTYP][(size_t)NN*PKW];
static __device__ unsigned int g_pal[TTYP][(size_t)NN*PKW];
static __device__ unsigned int g_fh[(size_t)NN*(FIN/2)];
static __device__ unsigned int g_fl[(size_t)NN*(FIN/2)];
// CSR
static __device__ int g_cnt[TTYP][NN];
static __device__ int g_rowptr[TTYP][NN+1];
static __device__ int g_cur[TTYP][NN];
static __device__ int g_csrc[TTYP][NE];
static __device__ int g_bsum[TTYP][SCB];
static __device__ int g_boff[TTYP][SCB];

#define SSTR 20
#define AFSTR 36
#define GEMM_SMEM (2 * 4 * 128 * SSTR * 4)
#define GEMM_AFF_SMEM (2*128*AFSTR*4 + 2*128*SSTR*4 + 2*2*128*SSTR*4)

__global__ void gemm_tc_kernel(const unsigned int*, const unsigned int*,
                               const unsigned int*, const unsigned int*,
                               const float*, float*, float*, int, int, int, int, int);
__global__ void gemm_aff_kernel(const float*, const float*, const float*,
                                const unsigned int*, const unsigned int*,
                                const float*, float*, int, int, int, int);

// ---------------- streams/events (created once, statically) ----------------
namespace {
struct SI {
    cudaStream_t s[TTYP];
    cudaEvent_t e0, e1, e2;
    SI() {
        cudaStreamCreateWithFlags(&s[0], cudaStreamNonBlocking);
        cudaStreamCreateWithFlags(&s[1], cudaStreamNonBlocking);
        cudaEventCreateWithFlags(&e0, cudaEventDisableTiming);
        cudaEventCreateWithFlags(&e1, cudaEventDisableTiming);
        cudaEventCreateWithFlags(&e2, cudaEventDisableTiming);
        cudaFuncSetAttribute(gemm_tc_kernel,
                             cudaFuncAttributeMaxDynamicSharedMemorySize, GEMM_SMEM);
        cudaFuncSetAttribute(gemm_aff_kernel,
                             cudaFuncAttributeMaxDynamicSharedMemorySize, GEMM_AFF_SMEM);
    }
};
SI g_si;
}

// ---------------- helpers --------------------------------------------------
__device__ __forceinline__ float lrelu(float v) { return v >= 0.f ? v : 0.2f * v; }

__device__ __forceinline__ unsigned int pack2(__nv_bfloat16 a, __nv_bfloat16 b) {
    return (unsigned int)__bfloat16_as_ushort(a) |
           ((unsigned int)__bfloat16_as_ushort(b) << 16);
}

__device__ __forceinline__ void split_bf(float v, __nv_bfloat16& h, __nv_bfloat16& l) {
    h = __float2bfloat16_rn(v);
    l = __float2bfloat16_rn(v - __bfloat162float(h));
}

__device__ __forceinline__ void split4(float4 v, unsigned int* hp, unsigned int* lp) {
    __nv_bfloat16 h0, h1, h2, h3, l0, l1, l2, l3;
    split_bf(v.x, h0, l0); split_bf(v.y, h1, l1);
    split_bf(v.z, h2, l2); split_bf(v.w, h3, l3);
    hp[0] = pack2(h0, h1); hp[1] = pack2(h2, h3);
    lp[0] = pack2(l0, l1); lp[1] = pack2(l2, l3);
}

__device__ __forceinline__ void mma16816(float* c, const unsigned int* a, const unsigned int* b) {
    asm volatile(
        "mma.sync.aligned.m16n8k16.row.col.f32.bf16.bf16.f32 "
        "{%0,%1,%2,%3}, {%4,%5,%6,%7}, {%8,%9}, {%0,%1,%2,%3};"
        : "+f"(c[0]), "+f"(c[1]), "+f"(c[2]), "+f"(c[3])
        : "r"(a[0]), "r"(a[1]), "r"(a[2]), "r"(a[3]), "r"(b[0]), "r"(b[1]));
}

__device__ __forceinline__ void cp16(void* dst, const void* src, int sz) {
    unsigned int d = (unsigned int)__cvta_generic_to_shared(dst);
    asm volatile("cp.async.cg.shared.global [%0], [%1], 16, %2;"
                 :: "r"(d), "l"(src), "r"(sz) : "memory");
}
__device__ __forceinline__ void cp_commit() {
    asm volatile("cp.async.commit_group;" ::: "memory");
}
template <int N>
__device__ __forceinline__ void cp_wait() {
    asm volatile("cp.async.wait_group %0;" :: "n"(N) : "memory");
}

// ---------------- CSR build -------------------------------------------------
__global__ void zero_int_kernel(int* __restrict__ p, int n) {
    int i = blockIdx.x * blockDim.x + threadIdx.x;
    if (i < n) p[i] = 0;
}

__global__ void count_kernel(const int* __restrict__ dst, int* __restrict__ cnt) {
    int e = blockIdx.x * blockDim.x + threadIdx.x;
    if (e < NE) atomicAdd(&cnt[dst[e]], 1);
}

__global__ void scan1_kernel(const int* __restrict__ cnt, int* __restrict__ bsum) {
    __shared__ int sh[256];
    int i = blockIdx.x * 256 + threadIdx.x;
    sh[threadIdx.x] = (i < NN) ? cnt[i] : 0;
    __syncthreads();
    for (int off = 128; off; off >>= 1) {
        if (threadIdx.x < off) sh[threadIdx.x] += sh[threadIdx.x + off];
        __syncthreads();
    }
    if (threadIdx.x == 0) bsum[blockIdx.x] = sh[0];
}

__global__ void scan2_kernel(const int* __restrict__ bsum, int* __restrict__ boff,
                             int* __restrict__ rowptr) {
    __shared__ int sh[256];
    int tid = threadIdx.x;
    int v = (tid < SCB) ? bsum[tid] : 0;
    sh[tid] = v;
    __syncthreads();
    for (int off = 1; off < 256; off <<= 1) {
        int u = (tid >= off) ? sh[tid - off] : 0;
        __syncthreads();
        sh[tid] += u;
        __syncthreads();
    }
    if (tid < SCB) boff[tid] = sh[tid] - v;
    if (tid == SCB - 1) rowptr[NN] = sh[tid];
}

__global__ void scan3_kernel(const int* __restrict__ cnt, const int* __restrict__ boff,
                             int* __restrict__ rowptr, int* __restrict__ cur) {
    __shared__ int sh[256];
    int tid = threadIdx.x;
    int i = blockIdx.x * 256 + tid;
    int v = (i < NN) ? cnt[i] : 0;
    sh[tid] = v;
    __syncthreads();
    for (int off = 1; off < 256; off <<= 1) {
        int u = (tid >= off) ? sh[tid - off] : 0;
        __syncthreads();
        sh[tid] += u;
        __syncthreads();
    }
    if (i < NN) {
        int r = boff[blockIdx.x] + sh[tid] - v;
        rowptr[i] = r;
        cur[i] = r;
    }
}

__global__ void fill_kernel(const int* __restrict__ src, const int* __restrict__ dst,
                            int* __restrict__ cur, int* __restrict__ csrc) {
    int e = blockIdx.x * blockDim.x + threadIdx.x;
    if (e >= NE) return;
    int pos = atomicAdd(&cur[dst[e]], 1);
    csrc[pos] = src[e];
}

// ---------------- converters ------------------------------------------------
__global__ void aconv_kernel(const float* __restrict__ A, unsigned int* __restrict__ H,
                             unsigned int* __restrict__ L, int n4) {
    int idx = blockIdx.x * blockDim.x + threadIdx.x;
    if (idx >= n4) return;
    float4 v = *(const float4*)(A + (size_t)idx * 4);
    unsigned int hp[2], lp[2];
    split4(v, hp, lp);
    *(uint2*)(H + (size_t)idx * 2) = make_uint2(hp[0], hp[1]);
    *(uint2*)(L + (size_t)idx * 2) = make_uint2(lp[0], lp[1]);
}

__global__ void wconv_kernel(const float* __restrict__ W, int K,
                             unsigned int* __restrict__ wh, unsigned int* __restrict__ wl) {
    int idx = blockIdx.x * blockDim.x + threadIdx.x;
    int Kw = K / 2;
    if (idx >= HIDD * Kw) return;
    int n = idx / Kw;
    int kp = idx - n * Kw;
    float v0 = W[(size_t)(2 * kp) * HIDD + n];
    float v1 = W[(size_t)(2 * kp + 1) * HIDD + n];
    __nv_bfloat16 h0, h1, l0, l1;
    split_bf(v0, h0, l0); split_bf(v1, h1, l1);
    wh[idx] = pack2(h0, h1);
    wl[idx] = pack2(l0, l1);
}

// ---------------- tensor-core GEMM (packed A), optional fused BN stats ------
__global__ __launch_bounds__(256, 2)
void gemm_tc_kernel(const unsigned int* __restrict__ AHg, const unsigned int* __restrict__ ALg,
                    const unsigned int* __restrict__ BHg, const unsigned int* __restrict__ BLg,
                    const float* __restrict__ bias, float* __restrict__ C,
                    float* __restrict__ stats,
                    int M, int Kw, int ldc, int coff, int relu_flag) {
    extern __shared__ unsigned int smem[];
    const int BUF = 128 * SSTR;
    unsigned int* AH = smem;
    unsigned int* AL = AH + 2 * BUF;
    unsigned int* BH = AL + 2 * BUF;
    unsigned int* BL = BH + 2 * BUF;

    int tid = threadIdx.x;
    int lane = tid & 31, wid = tid >> 5;
    int lm = lane >> 2, lc = lane & 3;
    int m0 = (wid >> 2) * 64;
    int n0w = (wid & 3) * 32;
    int rowBase = blockIdx.y * 128;
    int colBase = blockIdx.x * 128;

    float acc[16][4];
#pragma unroll
    for (int i = 0; i < 16; i++)
#pragma unroll
        for (int j = 0; j < 4; j++) acc[i][j] = 0.f;

    int nkt = Kw / 16;

    auto stage = [&](int sidx, int kt) {
        int k0w = kt * 16;
        int off = sidx * BUF;
#pragma unroll
        for (int i = 0; i < 2; i++) {
            int p = tid + i * 256;
            int m = p >> 2;
            int cc = (p & 3) * 4;
            int row = rowBase + m;
            int sz = (row < M) ? 16 : 0;
            cp16(&AH[off + m * SSTR + cc], AHg + (size_t)row * Kw + k0w + cc, sz);
            cp16(&AL[off + m * SSTR + cc], ALg + (size_t)row * Kw + k0w + cc, sz);
            int n = colBase + m;
            cp16(&BH[off + m * SSTR + cc], BHg + (size_t)n * Kw + k0w + cc, 16);
            cp16(&BL[off + m * SSTR + cc], BLg + (size_t)n * Kw + k0w + cc, 16);
        }
        cp_commit();
    };

    stage(0, 0);

    for (int kt = 0; kt < nkt; kt++) {
        int cur = kt & 1;
        if (kt + 1 < nkt) {
            stage(cur ^ 1, kt + 1);
            cp_wait<1>();
        } else {
            cp_wait<0>();
        }
        __syncthreads();
        int off = cur * BUF;
#pragma unroll
        for (int kk = 0; kk < 2; kk++) {
            int kw = kk * 8;
            unsigned int ah[4][4], al[4][4], bh[4][2], bl[4][2];
#pragma unroll
            for (int mi = 0; mi < 4; mi++) {
                int r = m0 + mi * 16 + lm;
                int w0 = off + r * SSTR + kw + lc;
                int w1 = off + (r + 8) * SSTR + kw + lc;
                ah[mi][0] = AH[w0]; ah[mi][1] = AH[w1];
                ah[mi][2] = AH[w0 + 4]; ah[mi][3] = AH[w1 + 4];
                al[mi][0] = AL[w0]; al[mi][1] = AL[w1];
                al[mi][2] = AL[w0 + 4]; al[mi][3] = AL[w1 + 4];
            }
#pragma unroll
            for (int ni = 0; ni < 4; ni++) {
                int n = n0w + ni * 8 + lm;
                int w0 = off + n * SSTR + kw + lc;
                bh[ni][0] = BH[w0]; bh[ni][1] = BH[w0 + 4];
                bl[ni][0] = BL[w0]; bl[ni][1] = BL[w0 + 4];
            }
#pragma unroll
            for (int mi = 0; mi < 4; mi++)
#pragma unroll
                for (int ni = 0; ni < 4; ni++) {
                    float* c = acc[mi * 4 + ni];
                    mma16816(c, ah[mi], bh[ni]);
                    mma16816(c, ah[mi], bl[ni]);
                    mma16816(c, al[mi], bh[ni]);
                }
        }
        __syncthreads();
    }

    float cs[8] = {0.f,0.f,0.f,0.f,0.f,0.f,0.f,0.f};
    float cq[8] = {0.f,0.f,0.f,0.f,0.f,0.f,0.f,0.f};
#pragma unroll
    for (int mi = 0; mi < 4; mi++) {
#pragma unroll
        for (int ni = 0; ni < 4; ni++) {
            float* c = acc[mi * 4 + ni];
            int r0 = rowBase + m0 + mi * 16 + lm;
            int r1 = r0 + 8;
            int col = colBase + n0w + ni * 8 + lc * 2;
            float b0 = bias ? bias[col] : 0.f;
            float b1 = bias ? bias[col + 1] : 0.f;
            float v0 = c[0] + b0, v1 = c[1] + b1;
            float v2 = c[2] + b0, v3 = c[3] + b1;
            if (relu_flag) {
                v0 = fmaxf(v0, 0.f); v1 = fmaxf(v1, 0.f);
                v2 = fmaxf(v2, 0.f); v3 = fmaxf(v3, 0.f);
            }
            if (r0 < M) *(float2*)(C + (size_t)r0 * ldc + coff + col) = make_float2(v0, v1);
            if (r1 < M) *(float2*)(C + (size_t)r1 * ldc + coff + col) = make_float2(v2, v3);
            if (stats) {
                if (r0 < M) { cs[ni*2] += v0; cq[ni*2] += v0*v0;
                              cs[ni*2+1] += v1; cq[ni*2+1] += v1*v1; }
                if (r1 < M) { cs[ni*2] += v2; cq[ni*2] += v2*v2;
                              cs[ni*2+1] += v3; cq[ni*2+1] += v3*v3; }
            }
        }
    }
    if (stats) {
#pragma unroll
        for (int j = 0; j < 8; j++) {
#pragma unroll
            for (int off = 4; off < 32; off <<= 1) {
                cs[j] += __shfl_xor_sync(0xffffffffu, cs[j], off);
                cq[j] += __shfl_xor_sync(0xffffffffu, cq[j], off);
            }
        }
        if (lm == 0) {
#pragma unroll
            for (int j = 0; j < 8; j++) {
                int col = colBase + n0w + (j >> 1) * 8 + lc * 2 + (j & 1);
                atomicAdd(&stats[col], cs[j]);
                atomicAdd(&stats[HIDD + col], cq[j]);
            }
        }
    }
}

// ---------------- affine GEMM: A = relu(z*scale[k]+shift[k]), split in-kernel
__global__ __launch_bounds__(256, 2)
void gemm_aff_kernel(const float* __restrict__ Ag, const float* __restrict__ scale,
                     const float* __restrict__ shift,
                     const unsigned int* __restrict__ BHg, const unsigned int* __restrict__ BLg,
                     const float* __restrict__ bias, float* __restrict__ C,
                     int M, int Kw, int ldc, int coff) {
    extern __shared__ unsigned int smem[];
    const int BUF = 128 * SSTR;
    const int ABUF = 128 * AFSTR;
    float* AsF = (float*)smem;
    unsigned int* AH = smem + 2 * ABUF;
    unsigned int* AL = AH + BUF;
    unsigned int* BH = AL + BUF;
    unsigned int* BL = BH + 2 * BUF;

    int tid = threadIdx.x;
    int lane = tid & 31, wid = tid >> 5;
    int lm = lane >> 2, lc = lane & 3;
    int m0 = (wid >> 2) * 64;
    int n0w = (wid & 3) * 32;
    int rowBase = blockIdx.y * 128;
    int colBase = blockIdx.x * 128;
    int K = Kw * 2;

    float acc[16][4];
#pragma unroll
    for (int i = 0; i < 16; i++)
#pragma unroll
        for (int j = 0; j < 4; j++) acc[i][j] = 0.f;

    int nkt = Kw / 16;

    auto stage = [&](int sidx, int kt) {
        int k0 = kt * 32;
        int k0w = kt * 16;
        int offF = sidx * ABUF;
#pragma unroll
        for (int i = 0; i < 4; i++) {
            int p = tid + i * 256;
            int m = p >> 3;
            int k4 = (p & 7) * 4;
            int row = rowBase + m;
            int sz = (row < M) ? 16 : 0;
            cp16(&AsF[offF + m * AFSTR + k4], Ag + (size_t)row * K + k0 + k4, sz);
        }
        int offB = sidx * BUF;
#pragma unroll
        for (int i = 0; i < 2; i++) {
            int p = tid + i * 256;
            int n = p >> 2;
            int cc = (p & 3) * 4;
            cp16(&BH[offB + n * SSTR + cc], BHg + (size_t)(colBase + n) * Kw + k0w + cc, 16);
            cp16(&BL[offB + n * SSTR + cc], BLg + (size_t)(colBase + n) * Kw + k0w + cc, 16);
        }
        cp_commit();
    };

    stage(0, 0);

    for (int kt = 0; kt < nkt; kt++) {
        int cur = kt & 1;
        if (kt + 1 < nkt) {
            stage(cur ^ 1, kt + 1);
            cp_wait<1>();
        } else {
            cp_wait<0>();
        }
        __syncthreads();
        // convert phase: fp32 -> affine+relu -> packed hi/lo (single buffer)
        {
            int offF = cur * ABUF;
#pragma unroll
            for (int i = 0; i < 4; i++) {
                int p = tid + i * 256;
                int m = p >> 3;
                int k4 = (p & 7) * 4;
                float4 v = *(float4*)&AsF[offF + m * AFSTR + k4];
                int kg = kt * 32 + k4;
                float4 sc = *(const float4*)(scale + kg);
                float4 sh = *(const float4*)(shift + kg);
                v.x = fmaxf(v.x * sc.x + sh.x, 0.f);
                v.y = fmaxf(v.y * sc.y + sh.y, 0.f);
                v.z = fmaxf(v.z * sc.z + sh.z, 0.f);
                v.w = fmaxf(v.w * sc.w + sh.w, 0.f);
                unsigned int hp[2], lp[2];
                split4(v, hp, lp);
                int w = m * SSTR + (k4 >> 1);
                AH[w] = hp[0]; AH[w + 1] = hp[1];
                AL[w] = lp[0]; AL[w + 1] = lp[1];
            }
        }
        __syncthreads();
        int offB = cur * BUF;
#pragma unroll
        for (int kk = 0; kk < 2; kk++) {
            int kw = kk * 8;
            unsigned int ah[4][4], al[4][4], bh[4][2], bl[4][2];
#pragma unroll
            for (int mi = 0; mi < 4; mi++) {
                int r = m0 + mi * 16 + lm;
                int w0 = r * SSTR + kw + lc;
                int w1 = (r + 8) * SSTR + kw + lc;
                ah[mi][0] = AH[w0]; ah[mi][1] = AH[w1];
                ah[mi][2] = AH[w0 + 4]; ah[mi][3] = AH[w1 + 4];
                al[mi][0] = AL[w0]; al[mi][1] = AL[w1];
                al[mi][2] = AL[w0 + 4]; al[mi][3] = AL[w1 + 4];
            }
#pragma unroll
            for (int ni = 0; ni < 4; ni++) {
                int n = n0w + ni * 8 + lm;
                int w0 = offB + n * SSTR + kw + lc;
                bh[ni][0] = BH[w0]; bh[ni][1] = BH[w0 + 4];
                bl[ni][0] = BL[w0]; bl[ni][1] = BL[w0 + 4];
            }
#pragma unroll
            for (int mi = 0; mi < 4; mi++)
#pragma unroll
                for (int ni = 0; ni < 4; ni++) {
                    float* c = acc[mi * 4 + ni];
                    mma16816(c, ah[mi], bh[ni]);
                    mma16816(c, ah[mi], bl[ni]);
                    mma16816(c, al[mi], bh[ni]);
                }
        }
        __syncthreads();
    }

#pragma unroll
    for (int mi = 0; mi < 4; mi++) {
#pragma unroll
        for (int ni = 0; ni < 4; ni++) {
            float* c = acc[mi * 4 + ni];
            int r0 = rowBase + m0 + mi * 16 + lm;
            int r1 = r0 + 8;
            int col = colBase + n0w + ni * 8 + lc * 2;
            float b0 = bias[col], b1 = bias[col + 1];
            float v0 = fmaxf(c[0] + b0, 0.f), v1 = fmaxf(c[1] + b1, 0.f);
            float v2 = fmaxf(c[2] + b0, 0.f), v3 = fmaxf(c[3] + b1, 0.f);
            if (r0 < M) *(float2*)(C + (size_t)r0 * ldc + coff + col) = make_float2(v0, v1);
            if (r1 < M) *(float2*)(C + (size_t)r1 * ldc + coff + col) = make_float2(v2, v3);
        }
    }
}

// ---------------- GAT pieces ------------------------------------------------
__global__ __launch_bounds__(256)
void elz_kernel(const float* __restrict__ z,
                const float* __restrict__ al, const float* __restrict__ ar,
                float* __restrict__ elp, float* __restrict__ erp) {
    int warp = (blockIdx.x * blockDim.x + threadIdx.x) >> 5;
    if (warp >= NN) return;
    int lane = threadIdx.x & 31;
    const float4* zp = (const float4*)(z + (size_t)warp * HIDD + lane * 8);
    float4 z0 = zp[0], z1 = zp[1];
    const float4* ap = (const float4*)(al + lane * 8);
    float4 a0 = ap[0], a1 = ap[1];
    const float4* bp = (const float4*)(ar + lane * 8);
    float4 b0 = bp[0], b1 = bp[1];
    float el = z0.x*a0.x + z0.y*a0.y + z0.z*a0.z + z0.w*a0.w
             + z1.x*a1.x + z1.y*a1.y + z1.z*a1.z + z1.w*a1.w;
    float er = z0.x*b0.x + z0.y*b0.y + z0.z*b0.z + z0.w*b0.w
             + z1.x*b1.x + z1.y*b1.y + z1.z*b1.z + z1.w*b1.w;
#pragma unroll
    for (int off = 4; off; off >>= 1) {
        el += __shfl_xor_sync(0xffffffffu, el, off);
        er += __shfl_xor_sync(0xffffffffu, er, off);
    }
    if ((lane & 7) == 0) {
        int head = lane >> 3;
        elp[warp * NHD + head] = el;
        erp[warp * NHD + head] = er;
    }
}

template <int PACKED>
__global__ __launch_bounds__(256)
void gat_gather_kernel(const int* __restrict__ csrc, const int* __restrict__ rowptr,
                       const float* __restrict__ elp, const float* __restrict__ erp,
                       const float* __restrict__ z, const float* __restrict__ bias,
                       float* __restrict__ hout,
                       unsigned int* __restrict__ pah, unsigned int* __restrict__ pal) {
    int warp = (blockIdx.x * blockDim.x + threadIdx.x) >> 5;
    if (warp >= NN) return;
    int lane = threadIdx.x & 31;
    int head = lane >> 3;
    int beg = rowptr[warp], end = rowptr[warp + 1];
    float erh = erp[warp * NHD + head];

    float m = -INFINITY;
    for (int i = beg; i < end; i++) {
        int s = csrc[i];
        m = fmaxf(m, lrelu(elp[s * NHD + head] + erh));
    }
    if (m < -3.0e38f) m = 0.f;

    float den = 0.f;
    float msg[8] = {0.f, 0.f, 0.f, 0.f, 0.f, 0.f, 0.f, 0.f};
    for (int i = beg; i < end; i++) {
        int s = csrc[i];
        float p = __expf(lrelu(elp[s * NHD + head] + erh) - m);
        den += p;
        const float4* zp = (const float4*)(z + (size_t)s * HIDD + lane * 8);
        float4 a = zp[0], b = zp[1];
        msg[0] += p * a.x; msg[1] += p * a.y; msg[2] += p * a.z; msg[3] += p * a.w;
        msg[4] += p * b.x; msg[5] += p * b.y; msg[6] += p * b.z; msg[7] += p * b.w;
    }
    float inv = 1.f / fmaxf(den, 1e-9f);
    const float4* bp = (const float4*)(bias + lane * 8);
    float4 b0 = bp[0], b1 = bp[1];
    float4 o0, o1;
    o0.x = fmaxf(msg[0] * inv + b0.x, 0.f);
    o0.y = fmaxf(msg[1] * inv + b0.y, 0.f);
    o0.z = fmaxf(msg[2] * inv + b0.z, 0.f);
    o0.w = fmaxf(msg[3] * inv + b0.w, 0.f);
    o1.x = fmaxf(msg[4] * inv + b1.x, 0.f);
    o1.y = fmaxf(msg[5] * inv + b1.y, 0.f);
    o1.z = fmaxf(msg[6] * inv + b1.z, 0.f);
    o1.w = fmaxf(msg[7] * inv + b1.w, 0.f);
    if (PACKED) {
        unsigned int hp[4], lp[4];
        split4(o0, hp, lp);
        split4(o1, hp + 2, lp + 2);
        *(uint4*)(pah + (size_t)warp * (HIDD / 2) + lane * 4) = make_uint4(hp[0], hp[1], hp[2], hp[3]);
        *(uint4*)(pal + (size_t)warp * (HIDD / 2) + lane * 4) = make_uint4(lp[0], lp[1], lp[2], lp[3]);
    } else {
        float4* op = (float4*)(hout + (size_t)warp * HIDD + lane * 8);
        op[0] = o0; op[1] = o1;
    }
}

__global__ __launch_bounds__(256)
void gin_gather_kernel(const int* __restrict__ csrc, const int* __restrict__ rowptr,
                       const float* __restrict__ hA, const float* __restrict__ hB,
                       int FA, int F, const float* __restrict__ epsp,
                       unsigned int* __restrict__ ph, unsigned int* __restrict__ pl) {
    int warp = (blockIdx.x * blockDim.x + threadIdx.x) >> 5;
    if (warp >= NN) return;
    int lane = threadIdx.x & 31;
    int beg = rowptr[warp], end = rowptr[warp + 1];
    float e = 1.f + epsp[0];
    int FB = F - FA;
    for (int f = lane * 4; f < F; f += 128) {
        const float* base = (f < FA) ? (hA + (size_t)warp * FA + f)
                                     : (hB + (size_t)warp * FB + (f - FA));
        float4 hv = *(const float4*)base;
        float4 a = make_float4(e * hv.x, e * hv.y, e * hv.z, e * hv.w);
        if (f < FA) {
            for (int i = beg; i < end; i++) {
                int s = csrc[i];
                float4 v = *(const float4*)(hA + (size_t)s * FA + f);
                a.x += v.x; a.y += v.y; a.z += v.z; a.w += v.w;
            }
        } else {
            for (int i = beg; i < end; i++) {
                int s = csrc[i];
                float4 v = *(const float4*)(hB + (size_t)s * FB + (f - FA));
                a.x += v.x; a.y += v.y; a.z += v.z; a.w += v.w;
            }
        }
        unsigned int hp[2], lp[2];
        split4(a, hp, lp);
        *(uint2*)(ph + (size_t)warp * (F / 2) + (f >> 1)) = make_uint2(hp[0], hp[1]);
        *(uint2*)(pl + (size_t)warp * (F / 2) + (f >> 1)) = make_uint2(lp[0], lp[1]);
    }
}

// ---------------- BN finalize ------------------------------------------------
__global__ void bnfin_kernel(const float* __restrict__ g1, const float* __restrict__ be1,
                             const float* __restrict__ stats,
                             float* __restrict__ scale, float* __restrict__ shift) {
    int c = threadIdx.x;
    float inv = 1.f / (float)NN;
    float mu = stats[c] * inv;
    float var = stats[HIDD + c] * inv - mu * mu;
    float rstd = rsqrtf(var + 1e-5f);
    float sc = g1[c] * rstd;
    scale[c] = sc;
    shift[c] = be1[c] - mu * sc;
}

__global__ void zero_kernel(float* __restrict__ p, int n) {
    int idx = blockIdx.x * blockDim.x + threadIdx.x;
    int i4 = idx * 4;
    if (i4 >= n) return;
    *(float4*)(p + i4) = make_float4(0.f, 0.f, 0.f, 0.f);
}

// ---------------- host orchestration ---------------------------------------
static inline int blk4(int n) { return (n / 4 + 255) / 256; }
#define NODE_WARP_BLOCKS ((NN * 32 + 255) / 256)

struct TypeCtx {
    float *z, *h, *el, *er, *stats, *scale, *shift;
    unsigned int *pah, *pal;
    unsigned int *wh[NSLOT], *wl[NSLOT];
    int *cnt, *rowptr, *cur, *csrc, *bsum, *boff;
    cudaStream_t st;
};

static void gemm(const TypeCtx& c, const unsigned int* AH, const unsigned int* AL,
                 int slot, const float* b, float* C, float* stats,
                 int K, int relu, int ldc = HIDD, int coff = 0) {
    dim3 grid(HIDD / 128, (NN + 127) / 128);
    gemm_tc_kernel<<<grid, 256, GEMM_SMEM, c.st>>>(AH, AL, c.wh[slot], c.wl[slot],
                                                   b, C, stats, NN, K / 2, ldc, coff, relu);
}

static void gemm_aff(const TypeCtx& c, const float* A, int slot, const float* b,
                     float* C, int K, int ldc = HIDD, int coff = 0) {
    dim3 grid(HIDD / 128, (NN + 127) / 128);
    gemm_aff_kernel<<<grid, 256, GEMM_AFF_SMEM, c.st>>>(A, c.scale, c.shift,
                                                        c.wh[slot], c.wl[slot],
                                                        b, C, NN, K / 2, ldc, coff);
}

extern "C" void kernel_launch(void* const* d_in, const int* in_sizes, int n_in,
                              void* d_out, int out_size) {
    const float* feats = (const float*)d_in[0];
    const int* src[2] = { (const int*)d_in[1], (const int*)d_in[3] };
    const int* dst[2] = { (const int*)d_in[2], (const int*)d_in[4] };
    const float* gat0_W   = (const float*)d_in[5];
    const float* gat0_al  = (const float*)d_in[6];
    const float* gat0_ar  = (const float*)d_in[7];
    const float* gat0_b   = (const float*)d_in[8];
    const float* gat1_W   = (const float*)d_in[9];
    const float* gat1_al  = (const float*)d_in[10];
    const float* gat1_ar  = (const float*)d_in[11];
    const float* gat1_b   = (const float*)d_in[12];
    const float* gin0_eps = (const float*)d_in[13];
    const float* gin0_W1  = (const float*)d_in[14];
    const float* gin0_b1  = (const float*)d_in[15];
    const float* gin0_g1  = (const float*)d_in[16];
    const float* gin0_be1 = (const float*)d_in[17];
    const float* gin0_W2  = (const float*)d_in[18];
    const float* gin0_b2  = (const float*)d_in[19];
    const float* gin1_eps = (const float*)d_in[20];
    const float* gin1_W1  = (const float*)d_in[21];
    const float* gin1_b1  = (const float*)d_in[22];
    const float* gin1_g1  = (const float*)d_in[23];
    const float* gin1_be1 = (const float*)d_in[24];
    const float* gin1_W2  = (const float*)d_in[25];
    const float* gin1_b2  = (const float*)d_in[26];
    float* out = (float*)d_out;

    float *zb, *hb, *elb, *erb, *stb, *scb, *shb;
    unsigned int *whb, *wlb, *pahb, *palb, *fh, *fl;
    int *cntb, *rpb, *curb, *csb, *bsb, *bob;
    cudaGetSymbolAddress((void**)&zb, g_z);
    cudaGetSymbolAddress((void**)&hb, g_h);
    cudaGetSymbolAddress((void**)&elb, g_el);
    cudaGetSymbolAddress((void**)&erb, g_er);
    cudaGetSymbolAddress((void**)&stb, g_stats);
    cudaGetSymbolAddress((void**)&scb, g_scale);
    cudaGetSymbolAddress((void**)&shb, g_shift);
    cudaGetSymbolAddress((void**)&whb, g_wh);
    cudaGetSymbolAddress((void**)&wlb, g_wl);
    cudaGetSymbolAddress((void**)&pahb, g_pah);
    cudaGetSymbolAddress((void**)&palb, g_pal);
    cudaGetSymbolAddress((void**)&fh, g_fh);
    cudaGetSymbolAddress((void**)&fl, g_fl);
    cudaGetSymbolAddress((void**)&cntb, g_cnt);
    cudaGetSymbolAddress((void**)&rpb, g_rowptr);
    cudaGetSymbolAddress((void**)&curb, g_cur);
    cudaGetSymbolAddress((void**)&csb, g_csrc);
    cudaGetSymbolAddress((void**)&bsb, g_bsum);
    cudaGetSymbolAddress((void**)&bob, g_boff);

    aconv_kernel<<<blk4(NN * FIN), 256>>>(feats, fh, fl, NN * FIN / 4);

    cudaEventRecord(g_si.e0, 0);
    cudaStreamWaitEvent(g_si.s[0], g_si.e0, 0);
    cudaStreamWaitEvent(g_si.s[1], g_si.e0, 0);

    const float* Wsrc[TTYP][NSLOT];
    const int Wk[NSLOT] = { FIN, HIDD, CATF, HIDD, HIDD, HIDD };
    for (int t = 0; t < TTYP; t++) {
        Wsrc[t][0] = gat0_W + (size_t)t * FIN * HIDD;
        Wsrc[t][1] = gat1_W + (size_t)t * HIDD * HIDD;
        Wsrc[t][2] = gin0_W1 + (size_t)t * CATF * HIDD;
        Wsrc[t][3] = gin0_W2 + (size_t)t * HIDD * HIDD;
        Wsrc[t][4] = gin1_W1 + (size_t)t * HIDD * HIDD;
        Wsrc[t][5] = gin1_W2 + (size_t)t * HIDD * HIDD;
    }

    for (int t = 0; t < TTYP; t++) {
        TypeCtx c;
        c.z   = zb   + (size_t)t * NN * HIDD;
        c.h   = hb   + (size_t)t * NN * HIDD;
        c.el  = elb  + (size_t)t * NN * NHD;
        c.er  = erb  + (size_t)t * NN * NHD;
        c.stats = stb + (size_t)t * 2 * HIDD;
        c.scale = scb + (size_t)t * HIDD;
        c.shift = shb + (size_t)t * HIDD;
        for (int s = 0; s < NSLOT; s++) {
            c.wh[s] = whb + ((size_t)t * NSLOT + s) * HIDD * KWMAX;
            c.wl[s] = wlb + ((size_t)t * NSLOT + s) * HIDD * KWMAX;
        }
        c.pah = pahb + (size_t)t * NN * PKW;
        c.pal = palb + (size_t)t * NN * PKW;
        c.cnt = cntb + (size_t)t * NN;
        c.rowptr = rpb + (size_t)t * (NN + 1);
        c.cur = curb + (size_t)t * NN;
        c.csrc = csb + (size_t)t * NE;
        c.bsum = bsb + (size_t)t * SCB;
        c.boff = bob + (size_t)t * SCB;
        c.st  = g_si.s[t];

        for (int s = 0; s < NSLOT; s++) {
            int wtot = HIDD * (Wk[s] / 2);
            wconv_kernel<<<(wtot + 255) / 256, 256, 0, c.st>>>(Wsrc[t][s], Wk[s],
                                                               c.wh[s], c.wl[s]);
        }

        // ---- CSR build ----
        zero_int_kernel<<<(NN + 255) / 256, 256, 0, c.st>>>(c.cnt, NN);
        count_kernel<<<(NE + 255) / 256, 256, 0, c.st>>>(dst[t], c.cnt);
        scan1_kernel<<<SCB, 256, 0, c.st>>>(c.cnt, c.bsum);
        scan2_kernel<<<1, 256, 0, c.st>>>(c.bsum, c.boff, c.rowptr);
        scan3_kernel<<<SCB, 256, 0, c.st>>>(c.cnt, c.boff, c.rowptr, c.cur);
        fill_kernel<<<(NE + 255) / 256, 256, 0, c.st>>>(src[t], dst[t], c.cur, c.csrc);

        // ---- GAT layer 0 ----
        gemm(c, fh, fl, 0, nullptr, c.z, nullptr, FIN, 0);
        elz_kernel<<<NODE_WARP_BLOCKS, 256, 0, c.st>>>(c.z, gat0_al + t * NHD * DH,
                                                       gat0_ar + t * NHD * DH, c.el, c.er);
        gat_gather_kernel<1><<<NODE_WARP_BLOCKS, 256, 0, c.st>>>(
            c.csrc, c.rowptr, c.el, c.er, c.z, gat0_b + t * HIDD, nullptr, c.pah, c.pal);

        // ---- GAT layer 1 ----
        gemm(c, c.pah, c.pal, 1, nullptr, c.z, nullptr, HIDD, 0);
        elz_kernel<<<NODE_WARP_BLOCKS, 256, 0, c.st>>>(c.z, gat1_al + t * NHD * DH,
                                                       gat1_ar + t * NHD * DH, c.el, c.er);
        gat_gather_kernel<0><<<NODE_WARP_BLOCKS, 256, 0, c.st>>>(
            c.csrc, c.rowptr, c.el, c.er, c.z, gat1_b + t * HIDD, c.h, nullptr, nullptr);

        // ---- GIN layer 0 (F=384, implicit concat [h | feats]) ----
        gin_gather_kernel<<<NODE_WARP_BLOCKS, 256, 0, c.st>>>(
            c.csrc, c.rowptr, c.h, feats, HIDD, CATF, gin0_eps + t, c.pah, c.pal);
        zero_kernel<<<1, 128, 0, c.st>>>(c.stats, 2 * HIDD);
        gemm(c, c.pah, c.pal, 2, gin0_b1 + t * HIDD, c.z, c.stats, CATF, 0);
        bnfin_kernel<<<1, HIDD, 0, c.st>>>(gin0_g1 + t * HIDD, gin0_be1 + t * HIDD,
                                           c.stats, c.scale, c.shift);
        gemm_aff(c, c.z, 3, gin0_b2 + t * HIDD, c.h, HIDD);

        // ---- GIN layer 1 (F=256) ----
        gin_gather_kernel<<<NODE_WARP_BLOCKS, 256, 0, c.st>>>(
            c.csrc, c.rowptr, c.h, nullptr, HIDD, HIDD, gin1_eps + t, c.pah, c.pal);
        zero_kernel<<<1, 128, 0, c.st>>>(c.stats, 2 * HIDD);
        gemm(c, c.pah, c.pal, 4, gin1_b1 + t * HIDD, c.z, c.stats, HIDD, 0);
        bnfin_kernel<<<1, HIDD, 0, c.st>>>(gin1_g1 + t * HIDD, gin1_be1 + t * HIDD,
                                           c.stats, c.scale, c.shift);
        gemm_aff(c, c.z, 5, gin1_b2 + t * HIDD, out, HIDD, TTYP * HIDD, t * HIDD);
    }

    cudaEventRecord(g_si.e1, g_si.s[0]);
    cudaEventRecord(g_si.e2, g_si.s[1]);
    cudaStreamWaitEvent((cudaStream_t)0, g_si.e1, 0);
    cudaStreamWaitEvent((cudaStream_t)0, g_si.e2, 0);
}

// round 11
// speedup vs baseline: 2.2002x; 1.0355x over previous
#include <cuda_runtime.h>
#include <cuda_bf16.h>
#include <math.h>

#define NN   50000
#define FIN  128
#define HIDD 256
#define NHD  4
#define DH   64
#define NE   400000
#define CATF 384
#define TTYP 2
#define KWMAX (CATF/2)
#define PKW   (CATF/2)
#define NSLOT 6
#define SCB   196

// ---------------- per-type scratch (device globals) ------------------------
static __device__ float g_z  [TTYP][(size_t)NN*HIDD];
static __device__ float g_h  [TTYP][(size_t)NN*HIDD];
static __device__ float g_el [TTYP][NN*NHD];
static __device__ float g_er [TTYP][NN*NHD];
static __device__ float g_stats[TTYP][2*HIDD];
static __device__ float g_scale[TTYP][HIDD];
static __device__ float g_shift[TTYP][HIDD];
static __device__ unsigned int g_wh[TTYP][NSLOT][HIDD*KWMAX];
static __device__ unsigned int g_wl[TTYP][NSLOT][HIDD*KWMAX];
static __device__ unsigned int g_pah[TTYP][(size_t)NN*PKW];
static __device__ unsigned int g_pal[TTYP][(size_t)NN*PKW];
static __device__ unsigned int g_fh[(size_t)NN*(FIN/2)];
static __device__ unsigned int g_fl[(size_t)NN*(FIN/2)];
// CSR
static __device__ int g_cnt[TTYP][NN];
static __device__ int g_rowptr[TTYP][NN+1];
static __device__ int g_cur[TTYP][NN];
static __device__ int g_csrc[TTYP][NE];
static __device__ int g_bsum[TTYP][SCB];
static __device__ int g_boff[TTYP][SCB];

#define SSTR 20
#define AFSTR 36
#define GEMM_SMEM (2 * 4 * 128 * SSTR * 4)
#define GEMM_AFF_SMEM (2*128*AFSTR*4 + 2*128*SSTR*4 + 2*2*128*SSTR*4)

__global__ void gemm_tc_kernel(const unsigned int*, const unsigned int*,
                               const unsigned int*, const unsigned int*,
                               const float*, float*, float*,
                               const float*, const float*, float*, float*,
                               int, int, int, int, int);
__global__ void gemm_aff_kernel(const float*, const float*, const float*,
                                const unsigned int*, const unsigned int*,
                                const float*, float*, int, int, int, int);

// ---------------- streams/events (created once, statically) ----------------
namespace {
struct SI {
    cudaStream_t s[TTYP], s2[TTYP];
    cudaEvent_t e0, e1, e2, eC[TTYP];
    SI() {
        for (int t = 0; t < TTYP; t++) {
            cudaStreamCreateWithFlags(&s[t], cudaStreamNonBlocking);
            cudaStreamCreateWithFlags(&s2[t], cudaStreamNonBlocking);
            cudaEventCreateWithFlags(&eC[t], cudaEventDisableTiming);
        }
        cudaEventCreateWithFlags(&e0, cudaEventDisableTiming);
        cudaEventCreateWithFlags(&e1, cudaEventDisableTiming);
        cudaEventCreateWithFlags(&e2, cudaEventDisableTiming);
        cudaFuncSetAttribute(gemm_tc_kernel,
                             cudaFuncAttributeMaxDynamicSharedMemorySize, GEMM_SMEM);
        cudaFuncSetAttribute(gemm_aff_kernel,
                             cudaFuncAttributeMaxDynamicSharedMemorySize, GEMM_AFF_SMEM);
    }
};
SI g_si;
}

// ---------------- helpers --------------------------------------------------
__device__ __forceinline__ float lrelu(float v) { return v >= 0.f ? v : 0.2f * v; }

__device__ __forceinline__ unsigned int pack2(__nv_bfloat16 a, __nv_bfloat16 b) {
    return (unsigned int)__bfloat16_as_ushort(a) |
           ((unsigned int)__bfloat16_as_ushort(b) << 16);
}

__device__ __forceinline__ void split_bf(float v, __nv_bfloat16& h, __nv_bfloat16& l) {
    h = __float2bfloat16_rn(v);
    l = __float2bfloat16_rn(v - __bfloat162float(h));
}

__device__ __forceinline__ void split4(float4 v, unsigned int* hp, unsigned int* lp) {
    __nv_bfloat16 h0, h1, h2, h3, l0, l1, l2, l3;
    split_bf(v.x, h0, l0); split_bf(v.y, h1, l1);
    split_bf(v.z, h2, l2); split_bf(v.w, h3, l3);
    hp[0] = pack2(h0, h1); hp[1] = pack2(h2, h3);
    lp[0] = pack2(l0, l1); lp[1] = pack2(l2, l3);
}

__device__ __forceinline__ void mma16816(float* c, const unsigned int* a, const unsigned int* b) {
    asm volatile(
        "mma.sync.aligned.m16n8k16.row.col.f32.bf16.bf16.f32 "
        "{%0,%1,%2,%3}, {%4,%5,%6,%7}, {%8,%9}, {%0,%1,%2,%3};"
        : "+f"(c[0]), "+f"(c[1]), "+f"(c[2]), "+f"(c[3])
        : "r"(a[0]), "r"(a[1]), "r"(a[2]), "r"(a[3]), "r"(b[0]), "r"(b[1]));
}

__device__ __forceinline__ void cp16(void* dst, const void* src, int sz) {
    unsigned int d = (unsigned int)__cvta_generic_to_shared(dst);
    asm volatile("cp.async.cg.shared.global [%0], [%1], 16, %2;"
                 :: "r"(d), "l"(src), "r"(sz) : "memory");
}
__device__ __forceinline__ void cp_commit() {
    asm volatile("cp.async.commit_group;" ::: "memory");
}
template <int N>
__device__ __forceinline__ void cp_wait() {
    asm volatile("cp.async.wait_group %0;" :: "n"(N) : "memory");
}

// ---------------- CSR build -------------------------------------------------
__global__ void zero_int_kernel(int* __restrict__ p, int n) {
    int i = blockIdx.x * blockDim.x + threadIdx.x;
    if (i < n) p[i] = 0;
}

__global__ void count_kernel(const int* __restrict__ dst, int* __restrict__ cnt) {
    int e = blockIdx.x * blockDim.x + threadIdx.x;
    if (e < NE) atomicAdd(&cnt[dst[e]], 1);
}

__global__ void scan1_kernel(const int* __restrict__ cnt, int* __restrict__ bsum) {
    __shared__ int sh[256];
    int i = blockIdx.x * 256 + threadIdx.x;
    sh[threadIdx.x] = (i < NN) ? cnt[i] : 0;
    __syncthreads();
    for (int off = 128; off; off >>= 1) {
        if (threadIdx.x < off) sh[threadIdx.x] += sh[threadIdx.x + off];
        __syncthreads();
    }
    if (threadIdx.x == 0) bsum[blockIdx.x] = sh[0];
}

__global__ void scan2_kernel(const int* __restrict__ bsum, int* __restrict__ boff,
                             int* __restrict__ rowptr) {
    __shared__ int sh[256];
    int tid = threadIdx.x;
    int v = (tid < SCB) ? bsum[tid] : 0;
    sh[tid] = v;
    __syncthreads();
    for (int off = 1; off < 256; off <<= 1) {
        int u = (tid >= off) ? sh[tid - off] : 0;
        __syncthreads();
        sh[tid] += u;
        __syncthreads();
    }
    if (tid < SCB) boff[tid] = sh[tid] - v;
    if (tid == SCB - 1) rowptr[NN] = sh[tid];
}

__global__ void scan3_kernel(const int* __restrict__ cnt, const int* __restrict__ boff,
                             int* __restrict__ rowptr, int* __restrict__ cur) {
    __shared__ int sh[256];
    int tid = threadIdx.x;
    int i = blockIdx.x * 256 + tid;
    int v = (i < NN) ? cnt[i] : 0;
    sh[tid] = v;
    __syncthreads();
    for (int off = 1; off < 256; off <<= 1) {
        int u = (tid >= off) ? sh[tid - off] : 0;
        __syncthreads();
        sh[tid] += u;
        __syncthreads();
    }
    if (i < NN) {
        int r = boff[blockIdx.x] + sh[tid] - v;
        rowptr[i] = r;
        cur[i] = r;
    }
}

__global__ void fill_kernel(const int* __restrict__ src, const int* __restrict__ dst,
                            int* __restrict__ cur, int* __restrict__ csrc) {
    int e = blockIdx.x * blockDim.x + threadIdx.x;
    if (e >= NE) return;
    int pos = atomicAdd(&cur[dst[e]], 1);
    csrc[pos] = src[e];
}

// ---------------- converters ------------------------------------------------
__global__ void aconv_kernel(const float* __restrict__ A, unsigned int* __restrict__ H,
                             unsigned int* __restrict__ L, int n4) {
    int idx = blockIdx.x * blockDim.x + threadIdx.x;
    if (idx >= n4) return;
    float4 v = *(const float4*)(A + (size_t)idx * 4);
    unsigned int hp[2], lp[2];
    split4(v, hp, lp);
    *(uint2*)(H + (size_t)idx * 2) = make_uint2(hp[0], hp[1]);
    *(uint2*)(L + (size_t)idx * 2) = make_uint2(lp[0], lp[1]);
}

// coalesced-read mapping: consecutive threads -> consecutive n
__global__ void wconv_kernel(const float* __restrict__ W, int K,
                             unsigned int* __restrict__ wh, unsigned int* __restrict__ wl) {
    int idx = blockIdx.x * blockDim.x + threadIdx.x;
    int Kw = K / 2;
    if (idx >= HIDD * Kw) return;
    int kp = idx / HIDD;
    int n = idx - kp * HIDD;
    float v0 = W[(size_t)(2 * kp) * HIDD + n];
    float v1 = W[(size_t)(2 * kp + 1) * HIDD + n];
    __nv_bfloat16 h0, h1, l0, l1;
    split_bf(v0, h0, l0); split_bf(v1, h1, l1);
    wh[(size_t)n * Kw + kp] = pack2(h0, h1);
    wl[(size_t)n * Kw + kp] = pack2(l0, l1);
}

// zero two float arrays (el/er)
__global__ void zero2_kernel(float* __restrict__ a, float* __restrict__ b, int n) {
    int i4 = (blockIdx.x * blockDim.x + threadIdx.x) * 4;
    if (i4 >= n) return;
    *(float4*)(a + i4) = make_float4(0.f, 0.f, 0.f, 0.f);
    *(float4*)(b + i4) = make_float4(0.f, 0.f, 0.f, 0.f);
}

// ---------------- tensor-core GEMM (packed A), fused BN-stats / el-er -------
__global__ __launch_bounds__(256, 2)
void gemm_tc_kernel(const unsigned int* __restrict__ AHg, const unsigned int* __restrict__ ALg,
                    const unsigned int* __restrict__ BHg, const unsigned int* __restrict__ BLg,
                    const float* __restrict__ bias, float* __restrict__ C,
                    float* __restrict__ stats,
                    const float* __restrict__ alv, const float* __restrict__ arv,
                    float* __restrict__ elp, float* __restrict__ erp,
                    int M, int Kw, int ldc, int coff, int relu_flag) {
    extern __shared__ unsigned int smem[];
    const int BUF = 128 * SSTR;
    unsigned int* AH = smem;
    unsigned int* AL = AH + 2 * BUF;
    unsigned int* BH = AL + 2 * BUF;
    unsigned int* BL = BH + 2 * BUF;

    int tid = threadIdx.x;
    int lane = tid & 31, wid = tid >> 5;
    int lm = lane >> 2, lc = lane & 3;
    int m0 = (wid >> 2) * 64;
    int n0w = (wid & 3) * 32;
    int rowBase = blockIdx.y * 128;
    int colBase = blockIdx.x * 128;

    float acc[16][4];
#pragma unroll
    for (int i = 0; i < 16; i++)
#pragma unroll
        for (int j = 0; j < 4; j++) acc[i][j] = 0.f;

    int nkt = Kw / 16;

    auto stage = [&](int sidx, int kt) {
        int k0w = kt * 16;
        int off = sidx * BUF;
#pragma unroll
        for (int i = 0; i < 2; i++) {
            int p = tid + i * 256;
            int m = p >> 2;
            int cc = (p & 3) * 4;
            int row = rowBase + m;
            int sz = (row < M) ? 16 : 0;
            cp16(&AH[off + m * SSTR + cc], AHg + (size_t)row * Kw + k0w + cc, sz);
            cp16(&AL[off + m * SSTR + cc], ALg + (size_t)row * Kw + k0w + cc, sz);
            int n = colBase + m;
            cp16(&BH[off + m * SSTR + cc], BHg + (size_t)n * Kw + k0w + cc, 16);
            cp16(&BL[off + m * SSTR + cc], BLg + (size_t)n * Kw + k0w + cc, 16);
        }
        cp_commit();
    };

    stage(0, 0);

    for (int kt = 0; kt < nkt; kt++) {
        int cur = kt & 1;
        if (kt + 1 < nkt) {
            stage(cur ^ 1, kt + 1);
            cp_wait<1>();
        } else {
            cp_wait<0>();
        }
        __syncthreads();
        int off = cur * BUF;
#pragma unroll
        for (int kk = 0; kk < 2; kk++) {
            int kw = kk * 8;
            unsigned int ah[4][4], al[4][4], bh[4][2], bl[4][2];
#pragma unroll
            for (int mi = 0; mi < 4; mi++) {
                int r = m0 + mi * 16 + lm;
                int w0 = off + r * SSTR + kw + lc;
                int w1 = off + (r + 8) * SSTR + kw + lc;
                ah[mi][0] = AH[w0]; ah[mi][1] = AH[w1];
                ah[mi][2] = AH[w0 + 4]; ah[mi][3] = AH[w1 + 4];
                al[mi][0] = AL[w0]; al[mi][1] = AL[w1];
                al[mi][2] = AL[w0 + 4]; al[mi][3] = AL[w1 + 4];
            }
#pragma unroll
            for (int ni = 0; ni < 4; ni++) {
                int n = n0w + ni * 8 + lm;
                int w0 = off + n * SSTR + kw + lc;
                bh[ni][0] = BH[w0]; bh[ni][1] = BH[w0 + 4];
                bl[ni][0] = BL[w0]; bl[ni][1] = BL[w0 + 4];
            }
#pragma unroll
            for (int mi = 0; mi < 4; mi++)
#pragma unroll
                for (int ni = 0; ni < 4; ni++) {
                    float* c = acc[mi * 4 + ni];
                    mma16816(c, ah[mi], bh[ni]);
                    mma16816(c, ah[mi], bl[ni]);
                    mma16816(c, al[mi], bh[ni]);
                }
        }
        __syncthreads();
    }

    float cs[8] = {0.f,0.f,0.f,0.f,0.f,0.f,0.f,0.f};
    float cq[8] = {0.f,0.f,0.f,0.f,0.f,0.f,0.f,0.f};
    float pel[8] = {0.f,0.f,0.f,0.f,0.f,0.f,0.f,0.f};
    float per[8] = {0.f,0.f,0.f,0.f,0.f,0.f,0.f,0.f};
#pragma unroll
    for (int mi = 0; mi < 4; mi++) {
#pragma unroll
        for (int ni = 0; ni < 4; ni++) {
            float* c = acc[mi * 4 + ni];
            int r0 = rowBase + m0 + mi * 16 + lm;
            int r1 = r0 + 8;
            int col = colBase + n0w + ni * 8 + lc * 2;
            float b0 = bias ? bias[col] : 0.f;
            float b1 = bias ? bias[col + 1] : 0.f;
            float v0 = c[0] + b0, v1 = c[1] + b1;
            float v2 = c[2] + b0, v3 = c[3] + b1;
            if (relu_flag) {
                v0 = fmaxf(v0, 0.f); v1 = fmaxf(v1, 0.f);
                v2 = fmaxf(v2, 0.f); v3 = fmaxf(v3, 0.f);
            }
            if (r0 < M) *(float2*)(C + (size_t)r0 * ldc + coff + col) = make_float2(v0, v1);
            if (r1 < M) *(float2*)(C + (size_t)r1 * ldc + coff + col) = make_float2(v2, v3);
            if (stats) {
                if (r0 < M) { cs[ni*2] += v0; cq[ni*2] += v0*v0;
                              cs[ni*2+1] += v1; cq[ni*2+1] += v1*v1; }
                if (r1 < M) { cs[ni*2] += v2; cq[ni*2] += v2*v2;
                              cs[ni*2+1] += v3; cq[ni*2+1] += v3*v3; }
            }
            if (elp) {
                float2 av = *(const float2*)(alv + col);
                float2 bv = *(const float2*)(arv + col);
                pel[mi*2]   += v0 * av.x + v1 * av.y;
                per[mi*2]   += v0 * bv.x + v1 * bv.y;
                pel[mi*2+1] += v2 * av.x + v3 * av.y;
                per[mi*2+1] += v2 * bv.x + v3 * bv.y;
            }
        }
    }
    if (stats) {
#pragma unroll
        for (int j = 0; j < 8; j++) {
#pragma unroll
            for (int off = 4; off < 32; off <<= 1) {
                cs[j] += __shfl_xor_sync(0xffffffffu, cs[j], off);
                cq[j] += __shfl_xor_sync(0xffffffffu, cq[j], off);
            }
        }
        if (lm == 0) {
#pragma unroll
            for (int j = 0; j < 8; j++) {
                int col = colBase + n0w + (j >> 1) * 8 + lc * 2 + (j & 1);
                atomicAdd(&stats[col], cs[j]);
                atomicAdd(&stats[HIDD + col], cq[j]);
            }
        }
    }
    if (elp) {
#pragma unroll
        for (int j = 0; j < 8; j++) {
            pel[j] += __shfl_xor_sync(0xffffffffu, pel[j], 1);
            pel[j] += __shfl_xor_sync(0xffffffffu, pel[j], 2);
            per[j] += __shfl_xor_sync(0xffffffffu, per[j], 1);
            per[j] += __shfl_xor_sync(0xffffffffu, per[j], 2);
        }
        if (lc == 0) {
            int head = (colBase + n0w) >> 6;
#pragma unroll
            for (int mi = 0; mi < 4; mi++) {
                int r0 = rowBase + m0 + mi * 16 + lm;
                int r1 = r0 + 8;
                if (r0 < M) {
                    atomicAdd(&elp[r0 * NHD + head], pel[mi*2]);
                    atomicAdd(&erp[r0 * NHD + head], per[mi*2]);
                }
                if (r1 < M) {
                    atomicAdd(&elp[r1 * NHD + head], pel[mi*2+1]);
                    atomicAdd(&erp[r1 * NHD + head], per[mi*2+1]);
                }
            }
        }
    }
}

// ---------------- affine GEMM: A = relu(z*scale[k]+shift[k]) ----------------
__global__ __launch_bounds__(256, 2)
void gemm_aff_kernel(const float* __restrict__ Ag, const float* __restrict__ scale,
                     const float* __restrict__ shift,
                     const unsigned int* __restrict__ BHg, const unsigned int* __restrict__ BLg,
                     const float* __restrict__ bias, float* __restrict__ C,
                     int M, int Kw, int ldc, int coff) {
    extern __shared__ unsigned int smem[];
    const int BUF = 128 * SSTR;
    const int ABUF = 128 * AFSTR;
    float* AsF = (float*)smem;
    unsigned int* AH = smem + 2 * ABUF;
    unsigned int* AL = AH + BUF;
    unsigned int* BH = AL + BUF;
    unsigned int* BL = BH + 2 * BUF;

    int tid = threadIdx.x;
    int lane = tid & 31, wid = tid >> 5;
    int lm = lane >> 2, lc = lane & 3;
    int m0 = (wid >> 2) * 64;
    int n0w = (wid & 3) * 32;
    int rowBase = blockIdx.y * 128;
    int colBase = blockIdx.x * 128;
    int K = Kw * 2;

    float acc[16][4];
#pragma unroll
    for (int i = 0; i < 16; i++)
#pragma unroll
        for (int j = 0; j < 4; j++) acc[i][j] = 0.f;

    int nkt = Kw / 16;

    auto stage = [&](int sidx, int kt) {
        int k0 = kt * 32;
        int k0w = kt * 16;
        int offF = sidx * ABUF;
#pragma unroll
        for (int i = 0; i < 4; i++) {
            int p = tid + i * 256;
            int m = p >> 3;
            int k4 = (p & 7) * 4;
            int row = rowBase + m;
            int sz = (row < M) ? 16 : 0;
            cp16(&AsF[offF + m * AFSTR + k4], Ag + (size_t)row * K + k0 + k4, sz);
        }
        int offB = sidx * BUF;
#pragma unroll
        for (int i = 0; i < 2; i++) {
            int p = tid + i * 256;
            int n = p >> 2;
            int cc = (p & 3) * 4;
            cp16(&BH[offB + n * SSTR + cc], BHg + (size_t)(colBase + n) * Kw + k0w + cc, 16);
            cp16(&BL[offB + n * SSTR + cc], BLg + (size_t)(colBase + n) * Kw + k0w + cc, 16);
        }
        cp_commit();
    };

    stage(0, 0);

    for (int kt = 0; kt < nkt; kt++) {
        int cur = kt & 1;
        if (kt + 1 < nkt) {
            stage(cur ^ 1, kt + 1);
            cp_wait<1>();
        } else {
            cp_wait<0>();
        }
        __syncthreads();
        {
            int offF = cur * ABUF;
#pragma unroll
            for (int i = 0; i < 4; i++) {
                int p = tid + i * 256;
                int m = p >> 3;
                int k4 = (p & 7) * 4;
                float4 v = *(float4*)&AsF[offF + m * AFSTR + k4];
                int kg = kt * 32 + k4;
                float4 sc = *(const float4*)(scale + kg);
                float4 sh = *(const float4*)(shift + kg);
                v.x = fmaxf(v.x * sc.x + sh.x, 0.f);
                v.y = fmaxf(v.y * sc.y + sh.y, 0.f);
                v.z = fmaxf(v.z * sc.z + sh.z, 0.f);
                v.w = fmaxf(v.w * sc.w + sh.w, 0.f);
                unsigned int hp[2], lp[2];
                split4(v, hp, lp);
                int w = m * SSTR + (k4 >> 1);
                AH[w] = hp[0]; AH[w + 1] = hp[1];
                AL[w] = lp[0]; AL[w + 1] = lp[1];
            }
        }
        __syncthreads();
        int offB = cur * BUF;
#pragma unroll
        for (int kk = 0; kk < 2; kk++) {
            int kw = kk * 8;
            unsigned int ah[4][4], al[4][4], bh[4][2], bl[4][2];
#pragma unroll
            for (int mi = 0; mi < 4; mi++) {
                int r = m0 + mi * 16 + lm;
                int w0 = r * SSTR + kw + lc;
                int w1 = (r + 8) * SSTR + kw + lc;
                ah[mi][0] = AH[w0]; ah[mi][1] = AH[w1];
                ah[mi][2] = AH[w0 + 4]; ah[mi][3] = AH[w1 + 4];
                al[mi][0] = AL[w0]; al[mi][1] = AL[w1];
                al[mi][2] = AL[w0 + 4]; al[mi][3] = AL[w1 + 4];
            }
#pragma unroll
            for (int ni = 0; ni < 4; ni++) {
                int n = n0w + ni * 8 + lm;
                int w0 = offB + n * SSTR + kw + lc;
                bh[ni][0] = BH[w0]; bh[ni][1] = BH[w0 + 4];
                bl[ni][0] = BL[w0]; bl[ni][1] = BL[w0 + 4];
            }
#pragma unroll
            for (int mi = 0; mi < 4; mi++)
#pragma unroll
                for (int ni = 0; ni < 4; ni++) {
                    float* c = acc[mi * 4 + ni];
                    mma16816(c, ah[mi], bh[ni]);
                    mma16816(c, ah[mi], bl[ni]);
                    mma16816(c, al[mi], bh[ni]);
                }
        }
        __syncthreads();
    }

#pragma unroll
    for (int mi = 0; mi < 4; mi++) {
#pragma unroll
        for (int ni = 0; ni < 4; ni++) {
            float* c = acc[mi * 4 + ni];
            int r0 = rowBase + m0 + mi * 16 + lm;
            int r1 = r0 + 8;
            int col = colBase + n0w + ni * 8 + lc * 2;
            float b0 = bias[col], b1 = bias[col + 1];
            float v0 = fmaxf(c[0] + b0, 0.f), v1 = fmaxf(c[1] + b1, 0.f);
            float v2 = fmaxf(c[2] + b0, 0.f), v3 = fmaxf(c[3] + b1, 0.f);
            if (r0 < M) *(float2*)(C + (size_t)r0 * ldc + coff + col) = make_float2(v0, v1);
            if (r1 < M) *(float2*)(C + (size_t)r1 * ldc + coff + col) = make_float2(v2, v3);
        }
    }
}

// ---------------- fused GAT gather ------------------------------------------
template <int PACKED>
__global__ __launch_bounds__(256)
void gat_gather_kernel(const int* __restrict__ csrc, const int* __restrict__ rowptr,
                       const float* __restrict__ elp, const float* __restrict__ erp,
                       const float* __restrict__ z, const float* __restrict__ bias,
                       float* __restrict__ hout,
                       unsigned int* __restrict__ pah, unsigned int* __restrict__ pal) {
    int warp = (blockIdx.x * blockDim.x + threadIdx.x) >> 5;
    if (warp >= NN) return;
    int lane = threadIdx.x & 31;
    int head = lane >> 3;
    int beg = rowptr[warp], end = rowptr[warp + 1];
    float erh = erp[warp * NHD + head];

    float m = -INFINITY;
    for (int i = beg; i < end; i++) {
        int s = csrc[i];
        m = fmaxf(m, lrelu(elp[s * NHD + head] + erh));
    }
    if (m < -3.0e38f) m = 0.f;

    float den = 0.f;
    float msg[8] = {0.f, 0.f, 0.f, 0.f, 0.f, 0.f, 0.f, 0.f};
    for (int i = beg; i < end; i++) {
        int s = csrc[i];
        float p = __expf(lrelu(elp[s * NHD + head] + erh) - m);
        den += p;
        const float4* zp = (const float4*)(z + (size_t)s * HIDD + lane * 8);
        float4 a = zp[0], b = zp[1];
        msg[0] += p * a.x; msg[1] += p * a.y; msg[2] += p * a.z; msg[3] += p * a.w;
        msg[4] += p * b.x; msg[5] += p * b.y; msg[6] += p * b.z; msg[7] += p * b.w;
    }
    float inv = 1.f / fmaxf(den, 1e-9f);
    const float4* bp = (const float4*)(bias + lane * 8);
    float4 b0 = bp[0], b1 = bp[1];
    float4 o0, o1;
    o0.x = fmaxf(msg[0] * inv + b0.x, 0.f);
    o0.y = fmaxf(msg[1] * inv + b0.y, 0.f);
    o0.z = fmaxf(msg[2] * inv + b0.z, 0.f);
    o0.w = fmaxf(msg[3] * inv + b0.w, 0.f);
    o1.x = fmaxf(msg[4] * inv + b1.x, 0.f);
    o1.y = fmaxf(msg[5] * inv + b1.y, 0.f);
    o1.z = fmaxf(msg[6] * inv + b1.z, 0.f);
    o1.w = fmaxf(msg[7] * inv + b1.w, 0.f);
    if (PACKED) {
        unsigned int hp[4], lp[4];
        split4(o0, hp, lp);
        split4(o1, hp + 2, lp + 2);
        *(uint4*)(pah + (size_t)warp * (HIDD / 2) + lane * 4) = make_uint4(hp[0], hp[1], hp[2], hp[3]);
        *(uint4*)(pal + (size_t)warp * (HIDD / 2) + lane * 4) = make_uint4(lp[0], lp[1], lp[2], lp[3]);
    } else {
        float4* op = (float4*)(hout + (size_t)warp * HIDD + lane * 8);
        op[0] = o0; op[1] = o1;
    }
}

__global__ __launch_bounds__(256)
void gin_gather_kernel(const int* __restrict__ csrc, const int* __restrict__ rowptr,
                       const float* __restrict__ hA, const float* __restrict__ hB,
                       int FA, int F, const float* __restrict__ epsp,
                       unsigned int* __restrict__ ph, unsigned int* __restrict__ pl) {
    int warp = (blockIdx.x * blockDim.x + threadIdx.x) >> 5;
    if (warp >= NN) return;
    int lane = threadIdx.x & 31;
    int beg = rowptr[warp], end = rowptr[warp + 1];
    float e = 1.f + epsp[0];
    int FB = F - FA;
    for (int f = lane * 4; f < F; f += 128) {
        const float* base = (f < FA) ? (hA + (size_t)warp * FA + f)
                                     : (hB + (size_t)warp * FB + (f - FA));
        float4 hv = *(const float4*)base;
        float4 a = make_float4(e * hv.x, e * hv.y, e * hv.z, e * hv.w);
        if (f < FA) {
            for (int i = beg; i < end; i++) {
                int s = csrc[i];
                float4 v = *(const float4*)(hA + (size_t)s * FA + f);
                a.x += v.x; a.y += v.y; a.z += v.z; a.w += v.w;
            }
        } else {
            for (int i = beg; i < end; i++) {
                int s = csrc[i];
                float4 v = *(const float4*)(hB + (size_t)s * FB + (f - FA));
                a.x += v.x; a.y += v.y; a.z += v.z; a.w += v.w;
            }
        }
        unsigned int hp[2], lp[2];
        split4(a, hp, lp);
        *(uint2*)(ph + (size_t)warp * (F / 2) + (f >> 1)) = make_uint2(hp[0], hp[1]);
        *(uint2*)(pl + (size_t)warp * (F / 2) + (f >> 1)) = make_uint2(lp[0], lp[1]);
    }
}

// ---------------- BN finalize ------------------------------------------------
__global__ void bnfin_kernel(const float* __restrict__ g1, const float* __restrict__ be1,
                             const float* __restrict__ stats,
                             float* __restrict__ scale, float* __restrict__ shift) {
    int c = threadIdx.x;
    float inv = 1.f / (float)NN;
    float mu = stats[c] * inv;
    float var = stats[HIDD + c] * inv - mu * mu;
    float rstd = rsqrtf(var + 1e-5f);
    float sc = g1[c] * rstd;
    scale[c] = sc;
    shift[c] = be1[c] - mu * sc;
}

__global__ void zero_kernel(float* __restrict__ p, int n) {
    int idx = blockIdx.x * blockDim.x + threadIdx.x;
    int i4 = idx * 4;
    if (i4 >= n) return;
    *(float4*)(p + i4) = make_float4(0.f, 0.f, 0.f, 0.f);
}

// ---------------- host orchestration ---------------------------------------
static inline int blk4(int n) { return (n / 4 + 255) / 256; }
#define NODE_WARP_BLOCKS ((NN * 32 + 255) / 256)

struct TypeCtx {
    float *z, *h, *el, *er, *stats, *scale, *shift;
    unsigned int *pah, *pal;
    unsigned int *wh[NSLOT], *wl[NSLOT];
    int *cnt, *rowptr, *cur, *csrc, *bsum, *boff;
    cudaStream_t st, st2;
};

static void gemm(const TypeCtx& c, const unsigned int* AH, const unsigned int* AL,
                 int slot, const float* b, float* C, float* stats,
                 const float* alv, const float* arv, float* elp, float* erp,
                 int K, int relu, int ldc = HIDD, int coff = 0) {
    dim3 grid(HIDD / 128, (NN + 127) / 128);
    gemm_tc_kernel<<<grid, 256, GEMM_SMEM, c.st>>>(AH, AL, c.wh[slot], c.wl[slot],
                                                   b, C, stats, alv, arv, elp, erp,
                                                   NN, K / 2, ldc, coff, relu);
}

static void gemm_aff(const TypeCtx& c, const float* A, int slot, const float* b,
                     float* C, int K, int ldc = HIDD, int coff = 0) {
    dim3 grid(HIDD / 128, (NN + 127) / 128);
    gemm_aff_kernel<<<grid, 256, GEMM_AFF_SMEM, c.st>>>(A, c.scale, c.shift,
                                                        c.wh[slot], c.wl[slot],
                                                        b, C, NN, K / 2, ldc, coff);
}

extern "C" void kernel_launch(void* const* d_in, const int* in_sizes, int n_in,
                              void* d_out, int out_size) {
    const float* feats = (const float*)d_in[0];
    const int* src[2] = { (const int*)d_in[1], (const int*)d_in[3] };
    const int* dst[2] = { (const int*)d_in[2], (const int*)d_in[4] };
    const float* gat0_W   = (const float*)d_in[5];
    const float* gat0_al  = (const float*)d_in[6];
    const float* gat0_ar  = (const float*)d_in[7];
    const float* gat0_b   = (const float*)d_in[8];
    const float* gat1_W   = (const float*)d_in[9];
    const float* gat1_al  = (const float*)d_in[10];
    const float* gat1_ar  = (const float*)d_in[11];
    const float* gat1_b   = (const float*)d_in[12];
    const float* gin0_eps = (const float*)d_in[13];
    const float* gin0_W1  = (const float*)d_in[14];
    const float* gin0_b1  = (const float*)d_in[15];
    const float* gin0_g1  = (const float*)d_in[16];
    const float* gin0_be1 = (const float*)d_in[17];
    const float* gin0_W2  = (const float*)d_in[18];
    const float* gin0_b2  = (const float*)d_in[19];
    const float* gin1_eps = (const float*)d_in[20];
    const float* gin1_W1  = (const float*)d_in[21];
    const float* gin1_b1  = (const float*)d_in[22];
    const float* gin1_g1  = (const float*)d_in[23];
    const float* gin1_be1 = (const float*)d_in[24];
    const float* gin1_W2  = (const float*)d_in[25];
    const float* gin1_b2  = (const float*)d_in[26];
    float* out = (float*)d_out;

    float *zb, *hb, *elb, *erb, *stb, *scb, *shb;
    unsigned int *whb, *wlb, *pahb, *palb, *fh, *fl;
    int *cntb, *rpb, *curb, *csb, *bsb, *bob;
    cudaGetSymbolAddress((void**)&zb, g_z);
    cudaGetSymbolAddress((void**)&hb, g_h);
    cudaGetSymbolAddress((void**)&elb, g_el);
    cudaGetSymbolAddress((void**)&erb, g_er);
    cudaGetSymbolAddress((void**)&stb, g_stats);
    cudaGetSymbolAddress((void**)&scb, g_scale);
    cudaGetSymbolAddress((void**)&shb, g_shift);
    cudaGetSymbolAddress((void**)&whb, g_wh);
    cudaGetSymbolAddress((void**)&wlb, g_wl);
    cudaGetSymbolAddress((void**)&pahb, g_pah);
    cudaGetSymbolAddress((void**)&palb, g_pal);
    cudaGetSymbolAddress((void**)&fh, g_fh);
    cudaGetSymbolAddress((void**)&fl, g_fl);
    cudaGetSymbolAddress((void**)&cntb, g_cnt);
    cudaGetSymbolAddress((void**)&rpb, g_rowptr);
    cudaGetSymbolAddress((void**)&curb, g_cur);
    cudaGetSymbolAddress((void**)&csb, g_csrc);
    cudaGetSymbolAddress((void**)&bsb, g_bsum);
    cudaGetSymbolAddress((void**)&bob, g_boff);

    aconv_kernel<<<blk4(NN * FIN), 256>>>(feats, fh, fl, NN * FIN / 4);

    cudaEventRecord(g_si.e0, 0);
    for (int t = 0; t < TTYP; t++) {
        cudaStreamWaitEvent(g_si.s[t], g_si.e0, 0);
        cudaStreamWaitEvent(g_si.s2[t], g_si.e0, 0);
    }

    const float* Wsrc[TTYP][NSLOT];
    const int Wk[NSLOT] = { FIN, HIDD, CATF, HIDD, HIDD, HIDD };
    for (int t = 0; t < TTYP; t++) {
        Wsrc[t][0] = gat0_W + (size_t)t * FIN * HIDD;
        Wsrc[t][1] = gat1_W + (size_t)t * HIDD * HIDD;
        Wsrc[t][2] = gin0_W1 + (size_t)t * CATF * HIDD;
        Wsrc[t][3] = gin0_W2 + (size_t)t * HIDD * HIDD;
        Wsrc[t][4] = gin1_W1 + (size_t)t * HIDD * HIDD;
        Wsrc[t][5] = gin1_W2 + (size_t)t * HIDD * HIDD;
    }

    for (int t = 0; t < TTYP; t++) {
        TypeCtx c;
        c.z   = zb   + (size_t)t * NN * HIDD;
        c.h   = hb   + (size_t)t * NN * HIDD;
        c.el  = elb  + (size_t)t * NN * NHD;
        c.er  = erb  + (size_t)t * NN * NHD;
        c.stats = stb + (size_t)t * 2 * HIDD;
        c.scale = scb + (size_t)t * HIDD;
        c.shift = shb + (size_t)t * HIDD;
        for (int s = 0; s < NSLOT; s++) {
            c.wh[s] = whb + ((size_t)t * NSLOT + s) * HIDD * KWMAX;
            c.wl[s] = wlb + ((size_t)t * NSLOT + s) * HIDD * KWMAX;
        }
        c.pah = pahb + (size_t)t * NN * PKW;
        c.pal = palb + (size_t)t * NN * PKW;
        c.cnt = cntb + (size_t)t * NN;
        c.rowptr = rpb + (size_t)t * (NN + 1);
        c.cur = curb + (size_t)t * NN;
        c.csrc = csb + (size_t)t * NE;
        c.bsum = bsb + (size_t)t * SCB;
        c.boff = bob + (size_t)t * SCB;
        c.st  = g_si.s[t];
        c.st2 = g_si.s2[t];

        // ---- side stream: wconv slots 1-5 + CSR build ----
        for (int s = 1; s < NSLOT; s++) {
            int wtot = HIDD * (Wk[s] / 2);
            wconv_kernel<<<(wtot + 255) / 256, 256, 0, c.st2>>>(Wsrc[t][s], Wk[s],
                                                                c.wh[s], c.wl[s]);
        }
        zero_int_kernel<<<(NN + 255) / 256, 256, 0, c.st2>>>(c.cnt, NN);
        count_kernel<<<(NE + 255) / 256, 256, 0, c.st2>>>(dst[t], c.cnt);
        scan1_kernel<<<SCB, 256, 0, c.st2>>>(c.cnt, c.bsum);
        scan2_kernel<<<1, 256, 0, c.st2>>>(c.bsum, c.boff, c.rowptr);
        scan3_kernel<<<SCB, 256, 0, c.st2>>>(c.cnt, c.boff, c.rowptr, c.cur);
        fill_kernel<<<(NE + 255) / 256, 256, 0, c.st2>>>(src[t], dst[t], c.cur, c.csrc);
        cudaEventRecord(g_si.eC[t], c.st2);

        // ---- main stream ----
        {
            int wtot = HIDD * (Wk[0] / 2);
            wconv_kernel<<<(wtot + 255) / 256, 256, 0, c.st>>>(Wsrc[t][0], Wk[0],
                                                               c.wh[0], c.wl[0]);
        }
        // GAT layer 0: GEMM with fused el/er
        zero2_kernel<<<(NN * NHD / 4 + 255) / 256, 256, 0, c.st>>>(c.el, c.er, NN * NHD);
        gemm(c, fh, fl, 0, nullptr, c.z, nullptr,
             gat0_al + t * NHD * DH, gat0_ar + t * NHD * DH, c.el, c.er, FIN, 0);
        cudaStreamWaitEvent(c.st, g_si.eC[t], 0);
        gat_gather_kernel<1><<<NODE_WARP_BLOCKS, 256, 0, c.st>>>(
            c.csrc, c.rowptr, c.el, c.er, c.z, gat0_b + t * HIDD, nullptr, c.pah, c.pal);

        // GAT layer 1
        zero2_kernel<<<(NN * NHD / 4 + 255) / 256, 256, 0, c.st>>>(c.el, c.er, NN * NHD);
        gemm(c, c.pah, c.pal, 1, nullptr, c.z, nullptr,
             gat1_al + t * NHD * DH, gat1_ar + t * NHD * DH, c.el, c.er, HIDD, 0);
        gat_gather_kernel<0><<<NODE_WARP_BLOCKS, 256, 0, c.st>>>(
            c.csrc, c.rowptr, c.el, c.er, c.z, gat1_b + t * HIDD, c.h, nullptr, nullptr);

        // GIN layer 0 (F=384, implicit concat [h | feats])
        gin_gather_kernel<<<NODE_WARP_BLOCKS, 256, 0, c.st>>>(
            c.csrc, c.rowptr, c.h, feats, HIDD, CATF, gin0_eps + t, c.pah, c.pal);
        zero_kernel<<<1, 128, 0, c.st>>>(c.stats, 2 * HIDD);
        gemm(c, c.pah, c.pal, 2, gin0_b1 + t * HIDD, c.z, c.stats,
             nullptr, nullptr, nullptr, nullptr, CATF, 0);
        bnfin_kernel<<<1, HIDD, 0, c.st>>>(gin0_g1 + t * HIDD, gin0_be1 + t * HIDD,
                                           c.stats, c.scale, c.shift);
        gemm_aff(c, c.z, 3, gin0_b2 + t * HIDD, c.h, HIDD);

        // GIN layer 1 (F=256)
        gin_gather_kernel<<<NODE_WARP_BLOCKS, 256, 0, c.st>>>(
            c.csrc, c.rowptr, c.h, nullptr, HIDD, HIDD, gin1_eps + t, c.pah, c.pal);
        zero_kernel<<<1, 128, 0, c.st>>>(c.stats, 2 * HIDD);
        gemm(c, c.pah, c.pal, 4, gin1_b1 + t * HIDD, c.z, c.stats,
             nullptr, nullptr, nullptr, nullptr, HIDD, 0);
        bnfin_kernel<<<1, HIDD, 0, c.st>>>(gin1_g1 + t * HIDD, gin1_be1 + t * HIDD,
                                           c.stats, c.scale, c.shift);
        gemm_aff(c, c.z, 5, gin1_b2 + t * HIDD, out, HIDD, TTYP * HIDD, t * HIDD);
    }

    cudaEventRecord(g_si.e1, g_si.s[0]);
    cudaEventRecord(g_si.e2, g_si.s[1]);
    cudaStreamWaitEvent((cudaStream_t)0, g_si.e1, 0);
    cudaStreamWaitEvent((cudaStream_t)0, g_si.e2, 0);
}

// round 13
// speedup vs baseline: 2.3616x; 1.0734x over previous
#include <cuda_runtime.h>
#include <cuda_bf16.h>
#include <math.h>

#define NN   50000
#define FIN  128
#define HIDD 256
#define NHD  4
#define DH   64
#define NE   400000
#define CATF 384
#define TTYP 2
#define KWMAX (CATF/2)
#define PKW   (CATF/2)
#define NSLOT 6
#define SCB   196

// ---------------- per-type scratch (device globals) ------------------------
static __device__ float g_z  [TTYP][(size_t)NN*HIDD];
static __device__ float g_h  [TTYP][(size_t)NN*HIDD];
static __device__ float g_el [TTYP][NN*NHD];
static __device__ float g_er [TTYP][NN*NHD];
static __device__ float g_stats[TTYP][2*HIDD];
static __device__ float g_scale[TTYP][HIDD];
static __device__ float g_shift[TTYP][HIDD];
static __device__ unsigned int g_wh[TTYP][NSLOT][HIDD*KWMAX];
static __device__ unsigned int g_wl[TTYP][NSLOT][HIDD*KWMAX];
static __device__ unsigned int g_pah[TTYP][(size_t)NN*PKW];
static __device__ unsigned int g_pal[TTYP][(size_t)NN*PKW];
static __device__ unsigned int g_fh[(size_t)NN*(FIN/2)];
static __device__ unsigned int g_fl[(size_t)NN*(FIN/2)];
// CSR
static __device__ int g_cnt[TTYP][NN];
static __device__ int g_rowptr[TTYP][NN+1];
static __device__ int g_cur[TTYP][NN];
static __device__ int g_csrc[TTYP][NE];
static __device__ int g_bsum[TTYP][SCB];
static __device__ int g_boff[TTYP][SCB];

#define SSTR 20
#define AFSTR 36
#define GEMM_SMEM (2 * 4 * 128 * SSTR * 4)
#define GEMM_AFF_SMEM (2*128*AFSTR*4 + 2*128*SSTR*4 + 2*2*128*SSTR*4)

__global__ void gemm_tc_kernel(const unsigned int*, const unsigned int*,
                               const unsigned int*, const unsigned int*,
                               const float*, float*, float*,
                               const float*, const float*, float*, float*,
                               int, int, int, int, int);
__global__ void gemm_aff_kernel(const float*, const float*, const float*,
                                const unsigned int*, const unsigned int*,
                                const float*, float*, int, int, int, int);

// ---------------- streams/events (created once, statically) ----------------
namespace {
struct SI {
    cudaStream_t s[TTYP], s2[TTYP];
    cudaEvent_t e0, e1, e2, eC[TTYP];
    SI() {
        for (int t = 0; t < TTYP; t++) {
            cudaStreamCreateWithFlags(&s[t], cudaStreamNonBlocking);
            cudaStreamCreateWithFlags(&s2[t], cudaStreamNonBlocking);
            cudaEventCreateWithFlags(&eC[t], cudaEventDisableTiming);
        }
        cudaEventCreateWithFlags(&e0, cudaEventDisableTiming);
        cudaEventCreateWithFlags(&e1, cudaEventDisableTiming);
        cudaEventCreateWithFlags(&e2, cudaEventDisableTiming);
        cudaFuncSetAttribute(gemm_tc_kernel,
                             cudaFuncAttributeMaxDynamicSharedMemorySize, GEMM_SMEM);
        cudaFuncSetAttribute(gemm_aff_kernel,
                             cudaFuncAttributeMaxDynamicSharedMemorySize, GEMM_AFF_SMEM);
    }
};
SI g_si;
}

// ---------------- helpers --------------------------------------------------
__device__ __forceinline__ float lrelu(float v) { return v >= 0.f ? v : 0.2f * v; }

__device__ __forceinline__ unsigned int pack2(__nv_bfloat16 a, __nv_bfloat16 b) {
    return (unsigned int)__bfloat16_as_ushort(a) |
           ((unsigned int)__bfloat16_as_ushort(b) << 16);
}

__device__ __forceinline__ void split_bf(float v, __nv_bfloat16& h, __nv_bfloat16& l) {
    h = __float2bfloat16_rn(v);
    l = __float2bfloat16_rn(v - __bfloat162float(h));
}

__device__ __forceinline__ void split4(float4 v, unsigned int* hp, unsigned int* lp) {
    __nv_bfloat16 h0, h1, h2, h3, l0, l1, l2, l3;
    split_bf(v.x, h0, l0); split_bf(v.y, h1, l1);
    split_bf(v.z, h2, l2); split_bf(v.w, h3, l3);
    hp[0] = pack2(h0, h1); hp[1] = pack2(h2, h3);
    lp[0] = pack2(l0, l1); lp[1] = pack2(l2, l3);
}

__device__ __forceinline__ void mma16816(float* c, const unsigned int* a, const unsigned int* b) {
    asm volatile(
        "mma.sync.aligned.m16n8k16.row.col.f32.bf16.bf16.f32 "
        "{%0,%1,%2,%3}, {%4,%5,%6,%7}, {%8,%9}, {%0,%1,%2,%3};"
        : "+f"(c[0]), "+f"(c[1]), "+f"(c[2]), "+f"(c[3])
        : "r"(a[0]), "r"(a[1]), "r"(a[2]), "r"(a[3]), "r"(b[0]), "r"(b[1]));
}

__device__ __forceinline__ void cp16(void* dst, const void* src, int sz) {
    unsigned int d = (unsigned int)__cvta_generic_to_shared(dst);
    asm volatile("cp.async.cg.shared.global [%0], [%1], 16, %2;"
                 :: "r"(d), "l"(src), "r"(sz) : "memory");
}
__device__ __forceinline__ void cp_commit() {
    asm volatile("cp.async.commit_group;" ::: "memory");
}
template <int N>
__device__ __forceinline__ void cp_wait() {
    asm volatile("cp.async.wait_group %0;" :: "n"(N) : "memory");
}

// ---------------- CSR build -------------------------------------------------
__global__ void zero_int_kernel(int* __restrict__ p, int n) {
    int i = blockIdx.x * blockDim.x + threadIdx.x;
    if (i < n) p[i] = 0;
}

__global__ void count_kernel(const int* __restrict__ dst, int* __restrict__ cnt) {
    int e = blockIdx.x * blockDim.x + threadIdx.x;
    if (e < NE) atomicAdd(&cnt[dst[e]], 1);
}

__global__ void scan1_kernel(const int* __restrict__ cnt, int* __restrict__ bsum) {
    __shared__ int sh[256];
    int i = blockIdx.x * 256 + threadIdx.x;
    sh[threadIdx.x] = (i < NN) ? cnt[i] : 0;
    __syncthreads();
    for (int off = 128; off; off >>= 1) {
        if (threadIdx.x < off) sh[threadIdx.x] += sh[threadIdx.x + off];
        __syncthreads();
    }
    if (threadIdx.x == 0) bsum[blockIdx.x] = sh[0];
}

__global__ void scan2_kernel(const int* __restrict__ bsum, int* __restrict__ boff,
                             int* __restrict__ rowptr) {
    __shared__ int sh[256];
    int tid = threadIdx.x;
    int v = (tid < SCB) ? bsum[tid] : 0;
    sh[tid] = v;
    __syncthreads();
    for (int off = 1; off < 256; off <<= 1) {
        int u = (tid >= off) ? sh[tid - off] : 0;
        __syncthreads();
        sh[tid] += u;
        __syncthreads();
    }
    if (tid < SCB) boff[tid] = sh[tid] - v;
    if (tid == SCB - 1) rowptr[NN] = sh[tid];
}

__global__ void scan3_kernel(const int* __restrict__ cnt, const int* __restrict__ boff,
                             int* __restrict__ rowptr, int* __restrict__ cur) {
    __shared__ int sh[256];
    int tid = threadIdx.x;
    int i = blockIdx.x * 256 + tid;
    int v = (i < NN) ? cnt[i] : 0;
    sh[tid] = v;
    __syncthreads();
    for (int off = 1; off < 256; off <<= 1) {
        int u = (tid >= off) ? sh[tid - off] : 0;
        __syncthreads();
        sh[tid] += u;
        __syncthreads();
    }
    if (i < NN) {
        int r = boff[blockIdx.x] + sh[tid] - v;
        rowptr[i] = r;
        cur[i] = r;
    }
}

__global__ void fill_kernel(const int* __restrict__ src, const int* __restrict__ dst,
                            int* __restrict__ cur, int* __restrict__ csrc) {
    int e = blockIdx.x * blockDim.x + threadIdx.x;
    if (e >= NE) return;
    int pos = atomicAdd(&cur[dst[e]], 1);
    csrc[pos] = src[e];
}

// ---------------- converters ------------------------------------------------
__global__ void aconv_kernel(const float* __restrict__ A, unsigned int* __restrict__ H,
                             unsigned int* __restrict__ L, int n4) {
    int idx = blockIdx.x * blockDim.x + threadIdx.x;
    if (idx >= n4) return;
    float4 v = *(const float4*)(A + (size_t)idx * 4);
    unsigned int hp[2], lp[2];
    split4(v, hp, lp);
    *(uint2*)(H + (size_t)idx * 2) = make_uint2(hp[0], hp[1]);
    *(uint2*)(L + (size_t)idx * 2) = make_uint2(lp[0], lp[1]);
}

__global__ void wconv_kernel(const float* __restrict__ W, int K,
                             unsigned int* __restrict__ wh, unsigned int* __restrict__ wl) {
    int idx = blockIdx.x * blockDim.x + threadIdx.x;
    int Kw = K / 2;
    if (idx >= HIDD * Kw) return;
    int kp = idx / HIDD;
    int n = idx - kp * HIDD;
    float v0 = W[(size_t)(2 * kp) * HIDD + n];
    float v1 = W[(size_t)(2 * kp + 1) * HIDD + n];
    __nv_bfloat16 h0, h1, l0, l1;
    split_bf(v0, h0, l0); split_bf(v1, h1, l1);
    wh[(size_t)n * Kw + kp] = pack2(h0, h1);
    wl[(size_t)n * Kw + kp] = pack2(l0, l1);
}

__global__ void zero2_kernel(float* __restrict__ a, float* __restrict__ b, int n) {
    int i4 = (blockIdx.x * blockDim.x + threadIdx.x) * 4;
    if (i4 >= n) return;
    *(float4*)(a + i4) = make_float4(0.f, 0.f, 0.f, 0.f);
    *(float4*)(b + i4) = make_float4(0.f, 0.f, 0.f, 0.f);
}

// ---------------- tensor-core GEMM (packed A), fused BN-stats / el-er -------
__global__ __launch_bounds__(256, 2)
void gemm_tc_kernel(const unsigned int* __restrict__ AHg, const unsigned int* __restrict__ ALg,
                    const unsigned int* __restrict__ BHg, const unsigned int* __restrict__ BLg,
                    const float* __restrict__ bias, float* __restrict__ C,
                    float* __restrict__ stats,
                    const float* __restrict__ alv, const float* __restrict__ arv,
                    float* __restrict__ elp, float* __restrict__ erp,
                    int M, int Kw, int ldc, int coff, int relu_flag) {
    extern __shared__ unsigned int smem[];
    const int BUF = 128 * SSTR;
    unsigned int* AH = smem;
    unsigned int* AL = AH + 2 * BUF;
    unsigned int* BH = AL + 2 * BUF;
    unsigned int* BL = BH + 2 * BUF;

    int tid = threadIdx.x;
    int lane = tid & 31, wid = tid >> 5;
    int lm = lane >> 2, lc = lane & 3;
    int m0 = (wid >> 2) * 64;
    int n0w = (wid & 3) * 32;
    int rowBase = blockIdx.y * 128;
    int colBase = blockIdx.x * 128;

    float acc[16][4];
#pragma unroll
    for (int i = 0; i < 16; i++)
#pragma unroll
        for (int j = 0; j < 4; j++) acc[i][j] = 0.f;

    int nkt = Kw / 16;

    auto stage = [&](int sidx, int kt) {
        int k0w = kt * 16;
        int off = sidx * BUF;
#pragma unroll
        for (int i = 0; i < 2; i++) {
            int p = tid + i * 256;
            int m = p >> 2;
            int cc = (p & 3) * 4;
            int row = rowBase + m;
            int sz = (row < M) ? 16 : 0;
            cp16(&AH[off + m * SSTR + cc], AHg + (size_t)row * Kw + k0w + cc, sz);
            cp16(&AL[off + m * SSTR + cc], ALg + (size_t)row * Kw + k0w + cc, sz);
            int n = colBase + m;
            cp16(&BH[off + m * SSTR + cc], BHg + (size_t)n * Kw + k0w + cc, 16);
            cp16(&BL[off + m * SSTR + cc], BLg + (size_t)n * Kw + k0w + cc, 16);
        }
        cp_commit();
    };

    stage(0, 0);

    for (int kt = 0; kt < nkt; kt++) {
        int cur = kt & 1;
        if (kt + 1 < nkt) {
            stage(cur ^ 1, kt + 1);
            cp_wait<1>();
        } else {
            cp_wait<0>();
        }
        __syncthreads();
        int off = cur * BUF;
#pragma unroll
        for (int kk = 0; kk < 2; kk++) {
            int kw = kk * 8;
            unsigned int ah[4][4], al[4][4], bh[4][2], bl[4][2];
#pragma unroll
            for (int mi = 0; mi < 4; mi++) {
                int r = m0 + mi * 16 + lm;
                int w0 = off + r * SSTR + kw + lc;
                int w1 = off + (r + 8) * SSTR + kw + lc;
                ah[mi][0] = AH[w0]; ah[mi][1] = AH[w1];
                ah[mi][2] = AH[w0 + 4]; ah[mi][3] = AH[w1 + 4];
                al[mi][0] = AL[w0]; al[mi][1] = AL[w1];
                al[mi][2] = AL[w0 + 4]; al[mi][3] = AL[w1 + 4];
            }
#pragma unroll
            for (int ni = 0; ni < 4; ni++) {
                int n = n0w + ni * 8 + lm;
                int w0 = off + n * SSTR + kw + lc;
                bh[ni][0] = BH[w0]; bh[ni][1] = BH[w0 + 4];
                bl[ni][0] = BL[w0]; bl[ni][1] = BL[w0 + 4];
            }
#pragma unroll
            for (int mi = 0; mi < 4; mi++)
#pragma unroll
                for (int ni = 0; ni < 4; ni++) {
                    float* c = acc[mi * 4 + ni];
                    mma16816(c, ah[mi], bh[ni]);
                    mma16816(c, ah[mi], bl[ni]);
                    mma16816(c, al[mi], bh[ni]);
                }
        }
        __syncthreads();
    }

    float cs[8] = {0.f,0.f,0.f,0.f,0.f,0.f,0.f,0.f};
    float cq[8] = {0.f,0.f,0.f,0.f,0.f,0.f,0.f,0.f};
    float pel[8] = {0.f,0.f,0.f,0.f,0.f,0.f,0.f,0.f};
    float per[8] = {0.f,0.f,0.f,0.f,0.f,0.f,0.f,0.f};
#pragma unroll
    for (int mi = 0; mi < 4; mi++) {
#pragma unroll
        for (int ni = 0; ni < 4; ni++) {
            float* c = acc[mi * 4 + ni];
            int r0 = rowBase + m0 + mi * 16 + lm;
            int r1 = r0 + 8;
            int col = colBase + n0w + ni * 8 + lc * 2;
            float b0 = bias ? bias[col] : 0.f;
            float b1 = bias ? bias[col + 1] : 0.f;
            float v0 = c[0] + b0, v1 = c[1] + b1;
            float v2 = c[2] + b0, v3 = c[3] + b1;
            if (relu_flag) {
                v0 = fmaxf(v0, 0.f); v1 = fmaxf(v1, 0.f);
                v2 = fmaxf(v2, 0.f); v3 = fmaxf(v3, 0.f);
            }
            if (r0 < M) *(float2*)(C + (size_t)r0 * ldc + coff + col) = make_float2(v0, v1);
            if (r1 < M) *(float2*)(C + (size_t)r1 * ldc + coff + col) = make_float2(v2, v3);
            if (stats) {
                if (r0 < M) { cs[ni*2] += v0; cq[ni*2] += v0*v0;
                              cs[ni*2+1] += v1; cq[ni*2+1] += v1*v1; }
                if (r1 < M) { cs[ni*2] += v2; cq[ni*2] += v2*v2;
                              cs[ni*2+1] += v3; cq[ni*2+1] += v3*v3; }
            }
            if (elp) {
                float2 av = *(const float2*)(alv + col);
                float2 bv = *(const float2*)(arv + col);
                pel[mi*2]   += v0 * av.x + v1 * av.y;
                per[mi*2]   += v0 * bv.x + v1 * bv.y;
                pel[mi*2+1] += v2 * av.x + v3 * av.y;
                per[mi*2+1] += v2 * bv.x + v3 * bv.y;
            }
        }
    }
    if (stats) {
#pragma unroll
        for (int j = 0; j < 8; j++) {
#pragma unroll
            for (int off = 4; off < 32; off <<= 1) {
                cs[j] += __shfl_xor_sync(0xffffffffu, cs[j], off);
                cq[j] += __shfl_xor_sync(0xffffffffu, cq[j], off);
            }
        }
        if (lm == 0) {
#pragma unroll
            for (int j = 0; j < 8; j++) {
                int col = colBase + n0w + (j >> 1) * 8 + lc * 2 + (j & 1);
                atomicAdd(&stats[col], cs[j]);
                atomicAdd(&stats[HIDD + col], cq[j]);
            }
        }
    }
    if (elp) {
#pragma unroll
        for (int j = 0; j < 8; j++) {
            pel[j] += __shfl_xor_sync(0xffffffffu, pel[j], 1);
            pel[j] += __shfl_xor_sync(0xffffffffu, pel[j], 2);
            per[j] += __shfl_xor_sync(0xffffffffu, per[j], 1);
            per[j] += __shfl_xor_sync(0xffffffffu, per[j], 2);
        }
        if (lc == 0) {
            int head = (colBase + n0w) >> 6;
#pragma unroll
            for (int mi = 0; mi < 4; mi++) {
                int r0 = rowBase + m0 + mi * 16 + lm;
                int r1 = r0 + 8;
                if (r0 < M) {
                    atomicAdd(&elp[r0 * NHD + head], pel[mi*2]);
                    atomicAdd(&erp[r0 * NHD + head], per[mi*2]);
                }
                if (r1 < M) {
                    atomicAdd(&elp[r1 * NHD + head], pel[mi*2+1]);
                    atomicAdd(&erp[r1 * NHD + head], per[mi*2+1]);
                }
            }
        }
    }
}

// ---------------- affine GEMM: A = relu(z*scale[k]+shift[k]) ----------------
__global__ __launch_bounds__(256, 2)
void gemm_aff_kernel(const float* __restrict__ Ag, const float* __restrict__ scale,
                     const float* __restrict__ shift,
                     const unsigned int* __restrict__ BHg, const unsigned int* __restrict__ BLg,
                     const float* __restrict__ bias, float* __restrict__ C,
                     int M, int Kw, int ldc, int coff) {
    extern __shared__ unsigned int smem[];
    const int BUF = 128 * SSTR;
    const int ABUFA = 128 * AFSTR;
    float* AsF = (float*)smem;
    unsigned int* AH = smem + 2 * ABUFA;
    unsigned int* AL = AH + BUF;
    unsigned int* BH = AL + BUF;
    unsigned int* BL = BH + 2 * BUF;

    int tid = threadIdx.x;
    int lane = tid & 31, wid = tid >> 5;
    int lm = lane >> 2, lc = lane & 3;
    int m0 = (wid >> 2) * 64;
    int n0w = (wid & 3) * 32;
    int rowBase = blockIdx.y * 128;
    int colBase = blockIdx.x * 128;
    int K = Kw * 2;

    float acc[16][4];
#pragma unroll
    for (int i = 0; i < 16; i++)
#pragma unroll
        for (int j = 0; j < 4; j++) acc[i][j] = 0.f;

    int nkt = Kw / 16;

    auto stage = [&](int sidx, int kt) {
        int k0 = kt * 32;
        int k0w = kt * 16;
        int offF = sidx * ABUFA;
#pragma unroll
        for (int i = 0; i < 4; i++) {
            int p = tid + i * 256;
            int m = p >> 3;
            int k4 = (p & 7) * 4;
            int row = rowBase + m;
            int sz = (row < M) ? 16 : 0;
            cp16(&AsF[offF + m * AFSTR + k4], Ag + (size_t)row * K + k0 + k4, sz);
        }
        int offB = sidx * BUF;
#pragma unroll
        for (int i = 0; i < 2; i++) {
            int p = tid + i * 256;
            int n = p >> 2;
            int cc = (p & 3) * 4;
            cp16(&BH[offB + n * SSTR + cc], BHg + (size_t)(colBase + n) * Kw + k0w + cc, 16);
            cp16(&BL[offB + n * SSTR + cc], BLg + (size_t)(colBase + n) * Kw + k0w + cc, 16);
        }
        cp_commit();
    };

    stage(0, 0);

    for (int kt = 0; kt < nkt; kt++) {
        int cur = kt & 1;
        if (kt + 1 < nkt) {
            stage(cur ^ 1, kt + 1);
            cp_wait<1>();
        } else {
            cp_wait<0>();
        }
        __syncthreads();
        {
            int offF = cur * ABUFA;
#pragma unroll
            for (int i = 0; i < 4; i++) {
                int p = tid + i * 256;
                int m = p >> 3;
                int k4 = (p & 7) * 4;
                float4 v = *(float4*)&AsF[offF + m * AFSTR + k4];
                int kg = kt * 32 + k4;
                float4 sc = *(const float4*)(scale + kg);
                float4 sh = *(const float4*)(shift + kg);
                v.x = fmaxf(v.x * sc.x + sh.x, 0.f);
                v.y = fmaxf(v.y * sc.y + sh.y, 0.f);
                v.z = fmaxf(v.z * sc.z + sh.z, 0.f);
                v.w = fmaxf(v.w * sc.w + sh.w, 0.f);
                unsigned int hp[2], lp[2];
                split4(v, hp, lp);
                int w = m * SSTR + (k4 >> 1);
                AH[w] = hp[0]; AH[w + 1] = hp[1];
                AL[w] = lp[0]; AL[w + 1] = lp[1];
            }
        }
        __syncthreads();
        int offB = cur * BUF;
#pragma unroll
        for (int kk = 0; kk < 2; kk++) {
            int kw = kk * 8;
            unsigned int ah[4][4], al[4][4], bh[4][2], bl[4][2];
#pragma unroll
            for (int mi = 0; mi < 4; mi++) {
                int r = m0 + mi * 16 + lm;
                int w0 = r * SSTR + kw + lc;
                int w1 = (r + 8) * SSTR + kw + lc;
                ah[mi][0] = AH[w0]; ah[mi][1] = AH[w1];
                ah[mi][2] = AH[w0 + 4]; ah[mi][3] = AH[w1 + 4];
                al[mi][0] = AL[w0]; al[mi][1] = AL[w1];
                al[mi][2] = AL[w0 + 4]; al[mi][3] = AL[w1 + 4];
            }
#pragma unroll
            for (int ni = 0; ni < 4; ni++) {
                int n = n0w + ni * 8 + lm;
                int w0 = offB + n * SSTR + kw + lc;
                bh[ni][0] = BH[w0]; bh[ni][1] = BH[w0 + 4];
                bl[ni][0] = BL[w0]; bl[ni][1] = BL[w0 + 4];
            }
#pragma unroll
            for (int mi = 0; mi < 4; mi++)
#pragma unroll
                for (int ni = 0; ni < 4; ni++) {
                    float* c = acc[mi * 4 + ni];
                    mma16816(c, ah[mi], bh[ni]);
                    mma16816(c, ah[mi], bl[ni]);
                    mma16816(c, al[mi], bh[ni]);
                }
        }
        __syncthreads();
    }

#pragma unroll
    for (int mi = 0; mi < 4; mi++) {
#pragma unroll
        for (int ni = 0; ni < 4; ni++) {
            float* c = acc[mi * 4 + ni];
            int r0 = rowBase + m0 + mi * 16 + lm;
            int r1 = r0 + 8;
            int col = colBase + n0w + ni * 8 + lc * 2;
            float b0 = bias[col], b1 = bias[col + 1];
            float v0 = fmaxf(c[0] + b0, 0.f), v1 = fmaxf(c[1] + b1, 0.f);
            float v2 = fmaxf(c[2] + b0, 0.f), v3 = fmaxf(c[3] + b1, 0.f);
            if (r0 < M) *(float2*)(C + (size_t)r0 * ldc + coff + col) = make_float2(v0, v1);
            if (r1 < M) *(float2*)(C + (size_t)r1 * ldc + coff + col) = make_float2(v2, v3);
        }
    }
}

// ---------------- fused GAT gather (single pass, no max subtraction) --------
template <int PACKED>
__global__ __launch_bounds__(256)
void gat_gather_kernel(const int* __restrict__ csrc, const int* __restrict__ rowptr,
                       const float* __restrict__ elp, const float* __restrict__ erp,
                       const float* __restrict__ z, const float* __restrict__ bias,
                       float* __restrict__ hout,
                       unsigned int* __restrict__ pah, unsigned int* __restrict__ pal) {
    int warp = (blockIdx.x * blockDim.x + threadIdx.x) >> 5;
    if (warp >= NN) return;
    int lane = threadIdx.x & 31;
    int head = lane >> 3;
    int beg = rowptr[warp], end = rowptr[warp + 1];
    float erh = erp[warp * NHD + head];

    float den = 0.f;
    float msg[8] = {0.f, 0.f, 0.f, 0.f, 0.f, 0.f, 0.f, 0.f};
    for (int i = beg; i < end; i++) {
        int s = csrc[i];
        float p = __expf(lrelu(elp[s * NHD + head] + erh));
        den += p;
        const float4* zp = (const float4*)(z + (size_t)s * HIDD + lane * 8);
        float4 a = zp[0], b = zp[1];
        msg[0] += p * a.x; msg[1] += p * a.y; msg[2] += p * a.z; msg[3] += p * a.w;
        msg[4] += p * b.x; msg[5] += p * b.y; msg[6] += p * b.z; msg[7] += p * b.w;
    }
    float inv = 1.f / fmaxf(den, 1e-9f);
    const float4* bp = (const float4*)(bias + lane * 8);
    float4 b0 = bp[0], b1 = bp[1];
    float4 o0, o1;
    o0.x = fmaxf(msg[0] * inv + b0.x, 0.f);
    o0.y = fmaxf(msg[1] * inv + b0.y, 0.f);
    o0.z = fmaxf(msg[2] * inv + b0.z, 0.f);
    o0.w = fmaxf(msg[3] * inv + b0.w, 0.f);
    o1.x = fmaxf(msg[4] * inv + b1.x, 0.f);
    o1.y = fmaxf(msg[5] * inv + b1.y, 0.f);
    o1.z = fmaxf(msg[6] * inv + b1.z, 0.f);
    o1.w = fmaxf(msg[7] * inv + b1.w, 0.f);
    if (PACKED) {
        unsigned int hp[4], lp[4];
        split4(o0, hp, lp);
        split4(o1, hp + 2, lp + 2);
        *(uint4*)(pah + (size_t)warp * (HIDD / 2) + lane * 4) = make_uint4(hp[0], hp[1], hp[2], hp[3]);
        *(uint4*)(pal + (size_t)warp * (HIDD / 2) + lane * 4) = make_uint4(lp[0], lp[1], lp[2], lp[3]);
    } else {
        float4* op = (float4*)(hout + (size_t)warp * HIDD + lane * 8);
        op[0] = o0; op[1] = o1;
    }
}

// ---------------- fused GIN gather: edge-outer, register accumulators -------
// NCH chunks of 128 floats; chunk c covers cols [c*128, c*128+128).
// FA = 256 boundary: chunks 0..1 from hA, chunk 2 (if any) from hB.
template <int NCH>
__global__ __launch_bounds__(256)
void gin_gather_kernel(const int* __restrict__ csrc, const int* __restrict__ rowptr,
                       const float* __restrict__ hA, const float* __restrict__ hB,
                       const float* __restrict__ epsp,
                       unsigned int* __restrict__ ph, unsigned int* __restrict__ pl) {
    int warp = (blockIdx.x * blockDim.x + threadIdx.x) >> 5;
    if (warp >= NN) return;
    int lane = threadIdx.x & 31;
    int beg = rowptr[warp], end = rowptr[warp + 1];
    float e = 1.f + epsp[0];
    const int F = NCH * 128;
    const int lf = lane * 4;

    float4 a[NCH];
#pragma unroll
    for (int c = 0; c < NCH; c++) {
        int f = lf + c * 128;
        const float* base = (f < HIDD || NCH < 3) ? (hA + (size_t)warp * ((NCH < 3) ? F : HIDD) + f)
                                                  : (hB + (size_t)warp * FIN + (f - HIDD));
        float4 hv = *(const float4*)base;
        a[c] = make_float4(e * hv.x, e * hv.y, e * hv.z, e * hv.w);
    }
    for (int i = beg; i < end; i++) {
        int s = csrc[i];
#pragma unroll
        for (int c = 0; c < NCH; c++) {
            int f = lf + c * 128;
            const float* base = (f < HIDD || NCH < 3) ? (hA + (size_t)s * ((NCH < 3) ? F : HIDD) + f)
                                                      : (hB + (size_t)s * FIN + (f - HIDD));
            float4 v = *(const float4*)base;
            a[c].x += v.x; a[c].y += v.y; a[c].z += v.z; a[c].w += v.w;
        }
    }
#pragma unroll
    for (int c = 0; c < NCH; c++) {
        int f = lf + c * 128;
        unsigned int hp[2], lp[2];
        split4(a[c], hp, lp);
        *(uint2*)(ph + (size_t)warp * (F / 2) + (f >> 1)) = make_uint2(hp[0], hp[1]);
        *(uint2*)(pl + (size_t)warp * (F / 2) + (f >> 1)) = make_uint2(lp[0], lp[1]);
    }
}

// ---------------- BN finalize ------------------------------------------------
__global__ void bnfin_kernel(const float* __restrict__ g1, const float* __restrict__ be1,
                             const float* __restrict__ stats,
                             float* __restrict__ scale, float* __restrict__ shift) {
    int c = threadIdx.x;
    float inv = 1.f / (float)NN;
    float mu = stats[c] * inv;
    float var = stats[HIDD + c] * inv - mu * mu;
    float rstd = rsqrtf(var + 1e-5f);
    float sc = g1[c] * rstd;
    scale[c] = sc;
    shift[c] = be1[c] - mu * sc;
}

__global__ void zero_kernel(float* __restrict__ p, int n) {
    int idx = blockIdx.x * blockDim.x + threadIdx.x;
    int i4 = idx * 4;
    if (i4 >= n) return;
    *(float4*)(p + i4) = make_float4(0.f, 0.f, 0.f, 0.f);
}

// ---------------- host orchestration ---------------------------------------
static inline int blk4(int n) { return (n / 4 + 255) / 256; }
#define NODE_WARP_BLOCKS ((NN * 32 + 255) / 256)

struct TypeCtx {
    float *z, *h, *el, *er, *stats, *scale, *shift;
    unsigned int *pah, *pal;
    unsigned int *wh[NSLOT], *wl[NSLOT];
    int *cnt, *rowptr, *cur, *csrc, *bsum, *boff;
    cudaStream_t st, st2;
};

static void gemm(const TypeCtx& c, const unsigned int* AH, const unsigned int* AL,
                 int slot, const float* b, float* C, float* stats,
                 const float* alv, const float* arv, float* elp, float* erp,
                 int K, int relu, int ldc = HIDD, int coff = 0) {
    dim3 grid(HIDD / 128, (NN + 127) / 128);
    gemm_tc_kernel<<<grid, 256, GEMM_SMEM, c.st>>>(AH, AL, c.wh[slot], c.wl[slot],
                                                   b, C, stats, alv, arv, elp, erp,
                                                   NN, K / 2, ldc, coff, relu);
}

static void gemm_aff(const TypeCtx& c, const float* A, int slot, const float* b,
                     float* C, int K, int ldc = HIDD, int coff = 0) {
    dim3 grid(HIDD / 128, (NN + 127) / 128);
    gemm_aff_kernel<<<grid, 256, GEMM_AFF_SMEM, c.st>>>(A, c.scale, c.shift,
                                                        c.wh[slot], c.wl[slot],
                                                        b, C, NN, K / 2, ldc, coff);
}

extern "C" void kernel_launch(void* const* d_in, const int* in_sizes, int n_in,
                              void* d_out, int out_size) {
    const float* feats = (const float*)d_in[0];
    const int* src[2] = { (const int*)d_in[1], (const int*)d_in[3] };
    const int* dst[2] = { (const int*)d_in[2], (const int*)d_in[4] };
    const float* gat0_W   = (const float*)d_in[5];
    const float* gat0_al  = (const float*)d_in[6];
    const float* gat0_ar  = (const float*)d_in[7];
    const float* gat0_b   = (const float*)d_in[8];
    const float* gat1_W   = (const float*)d_in[9];
    const float* gat1_al  = (const float*)d_in[10];
    const float* gat1_ar  = (const float*)d_in[11];
    const float* gat1_b   = (const float*)d_in[12];
    const float* gin0_eps = (const float*)d_in[13];
    const float* gin0_W1  = (const float*)d_in[14];
    const float* gin0_b1  = (const float*)d_in[15];
    const float* gin0_g1  = (const float*)d_in[16];
    const float* gin0_be1 = (const float*)d_in[17];
    const float* gin0_W2  = (const float*)d_in[18];
    const float* gin0_b2  = (const float*)d_in[19];
    const float* gin1_eps = (const float*)d_in[20];
    const float* gin1_W1  = (const float*)d_in[21];
    const float* gin1_b1  = (const float*)d_in[22];
    const float* gin1_g1  = (const float*)d_in[23];
    const float* gin1_be1 = (const float*)d_in[24];
    const float* gin1_W2  = (const float*)d_in[25];
    const float* gin1_b2  = (const float*)d_in[26];
    float* out = (float*)d_out;

    float *zb, *hb, *elb, *erb, *stb, *scb, *shb;
    unsigned int *whb, *wlb, *pahb, *palb, *fh, *fl;
    int *cntb, *rpb, *curb, *csb, *bsb, *bob;
    cudaGetSymbolAddress((void**)&zb, g_z);
    cudaGetSymbolAddress((void**)&hb, g_h);
    cudaGetSymbolAddress((void**)&elb, g_el);
    cudaGetSymbolAddress((void**)&erb, g_er);
    cudaGetSymbolAddress((void**)&stb, g_stats);
    cudaGetSymbolAddress((void**)&scb, g_scale);
    cudaGetSymbolAddress((void**)&shb, g_shift);
    cudaGetSymbolAddress((void**)&whb, g_wh);
    cudaGetSymbolAddress((void**)&wlb, g_wl);
    cudaGetSymbolAddress((void**)&pahb, g_pah);
    cudaGetSymbolAddress((void**)&palb, g_pal);
    cudaGetSymbolAddress((void**)&fh, g_fh);
    cudaGetSymbolAddress((void**)&fl, g_fl);
    cudaGetSymbolAddress((void**)&cntb, g_cnt);
    cudaGetSymbolAddress((void**)&rpb, g_rowptr);
    cudaGetSymbolAddress((void**)&curb, g_cur);
    cudaGetSymbolAddress((void**)&csb, g_csrc);
    cudaGetSymbolAddress((void**)&bsb, g_bsum);
    cudaGetSymbolAddress((void**)&bob, g_boff);

    aconv_kernel<<<blk4(NN * FIN), 256>>>(feats, fh, fl, NN * FIN / 4);

    cudaEventRecord(g_si.e0, 0);
    for (int t = 0; t < TTYP; t++) {
        cudaStreamWaitEvent(g_si.s[t], g_si.e0, 0);
        cudaStreamWaitEvent(g_si.s2[t], g_si.e0, 0);
    }

    const float* Wsrc[TTYP][NSLOT];
    const int Wk[NSLOT] = { FIN, HIDD, CATF, HIDD, HIDD, HIDD };
    for (int t = 0; t < TTYP; t++) {
        Wsrc[t][0] = gat0_W + (size_t)t * FIN * HIDD;
        Wsrc[t][1] = gat1_W + (size_t)t * HIDD * HIDD;
        Wsrc[t][2] = gin0_W1 + (size_t)t * CATF * HIDD;
        Wsrc[t][3] = gin0_W2 + (size_t)t * HIDD * HIDD;
        Wsrc[t][4] = gin1_W1 + (size_t)t * HIDD * HIDD;
        Wsrc[t][5] = gin1_W2 + (size_t)t * HIDD * HIDD;
    }

    for (int t = 0; t < TTYP; t++) {
        TypeCtx c;
        c.z   = zb   + (size_t)t * NN * HIDD;
        c.h   = hb   + (size_t)t * NN * HIDD;
        c.el  = elb  + (size_t)t * NN * NHD;
        c.er  = erb  + (size_t)t * NN * NHD;
        c.stats = stb + (size_t)t * 2 * HIDD;
        c.scale = scb + (size_t)t * HIDD;
        c.shift = shb + (size_t)t * HIDD;
        for (int s = 0; s < NSLOT; s++) {
            c.wh[s] = whb + ((size_t)t * NSLOT + s) * HIDD * KWMAX;
            c.wl[s] = wlb + ((size_t)t * NSLOT + s) * HIDD * KWMAX;
        }
        c.pah = pahb + (size_t)t * NN * PKW;
        c.pal = palb + (size_t)t * NN * PKW;
        c.cnt = cntb + (size_t)t * NN;
        c.rowptr = rpb + (size_t)t * (NN + 1);
        c.cur = curb + (size_t)t * NN;
        c.csrc = csb + (size_t)t * NE;
        c.bsum = bsb + (size_t)t * SCB;
        c.boff = bob + (size_t)t * SCB;
        c.st  = g_si.s[t];
        c.st2 = g_si.s2[t];

        // ---- side stream: wconv slots 1-5 + CSR build ----
        for (int s = 1; s < NSLOT; s++) {
            int wtot = HIDD * (Wk[s] / 2);
            wconv_kernel<<<(wtot + 255) / 256, 256, 0, c.st2>>>(Wsrc[t][s], Wk[s],
                                                                c.wh[s], c.wl[s]);
        }
        zero_int_kernel<<<(NN + 255) / 256, 256, 0, c.st2>>>(c.cnt, NN);
        count_kernel<<<(NE + 255) / 256, 256, 0, c.st2>>>(dst[t], c.cnt);
        scan1_kernel<<<SCB, 256, 0, c.st2>>>(c.cnt, c.bsum);
        scan2_kernel<<<1, 256, 0, c.st2>>>(c.bsum, c.boff, c.rowptr);
        scan3_kernel<<<SCB, 256, 0, c.st2>>>(c.cnt, c.boff, c.rowptr, c.cur);
        fill_kernel<<<(NE + 255) / 256, 256, 0, c.st2>>>(src[t], dst[t], c.cur, c.csrc);
        cudaEventRecord(g_si.eC[t], c.st2);

        // ---- main stream ----
        {
            int wtot = HIDD * (Wk[0] / 2);
            wconv_kernel<<<(wtot + 255) / 256, 256, 0, c.st>>>(Wsrc[t][0], Wk[0],
                                                               c.wh[0], c.wl[0]);
        }
        // GAT layer 0: GEMM with fused el/er
        zero2_kernel<<<(NN * NHD / 4 + 255) / 256, 256, 0, c.st>>>(c.el, c.er, NN * NHD);
        gemm(c, fh, fl, 0, nullptr, c.z, nullptr,
             gat0_al + t * NHD * DH, gat0_ar + t * NHD * DH, c.el, c.er, FIN, 0);
        cudaStreamWaitEvent(c.st, g_si.eC[t], 0);
        gat_gather_kernel<1><<<NODE_WARP_BLOCKS, 256, 0, c.st>>>(
            c.csrc, c.rowptr, c.el, c.er, c.z, gat0_b + t * HIDD, nullptr, c.pah, c.pal);

        // GAT layer 1
        zero2_kernel<<<(NN * NHD / 4 + 255) / 256, 256, 0, c.st>>>(c.el, c.er, NN * NHD);
        gemm(c, c.pah, c.pal, 1, nullptr, c.z, nullptr,
             gat1_al + t * NHD * DH, gat1_ar + t * NHD * DH, c.el, c.er, HIDD, 0);
        gat_gather_kernel<0><<<NODE_WARP_BLOCKS, 256, 0, c.st>>>(
            c.csrc, c.rowptr, c.el, c.er, c.z, gat1_b + t * HIDD, c.h, nullptr, nullptr);

        // GIN layer 0 (F=384, implicit concat [h | feats])
        gin_gather_kernel<3><<<NODE_WARP_BLOCKS, 256, 0, c.st>>>(
            c.csrc, c.rowptr, c.h, feats, gin0_eps + t, c.pah, c.pal);
        zero_kernel<<<1, 128, 0, c.st>>>(c.stats, 2 * HIDD);
        gemm(c, c.pah, c.pal, 2, gin0_b1 + t * HIDD, c.z, c.stats,
             nullptr, nullptr, nullptr, nullptr, CATF, 0);
        bnfin_kernel<<<1, HIDD, 0, c.st>>>(gin0_g1 + t * HIDD, gin0_be1 + t * HIDD,
                                           c.stats, c.scale, c.shift);
        gemm_aff(c, c.z, 3, gin0_b2 + t * HIDD, c.h, HIDD);

        // GIN layer 1 (F=256)
        gin_gather_kernel<2><<<NODE_WARP_BLOCKS, 256, 0, c.st>>>(
            c.csrc, c.rowptr, c.h, nullptr, gin1_eps + t, c.pah, c.pal);
        zero_kernel<<<1, 128, 0, c.st>>>(c.stats, 2 * HIDD);
        gemm(c, c.pah, c.pal, 4, gin1_b1 + t * HIDD, c.z, c.stats,
             nullptr, nullptr, nullptr, nullptr, HIDD, 0);
        bnfin_kernel<<<1, HIDD, 0, c.st>>>(gin1_g1 + t * HIDD, gin1_be1 + t * HIDD,
                                           c.stats, c.scale, c.shift);
        gemm_aff(c, c.z, 5, gin1_b2 + t * HIDD, out, HIDD, TTYP * HIDD, t * HIDD);
    }

    cudaEventRecord(g_si.e1, g_si.s[0]);
    cudaEventRecord(g_si.e2, g_si.s[1]);
    cudaStreamWaitEvent((cudaStream_t)0, g_si.e1, 0);
    cudaStreamWaitEvent((cudaStream_t)0, g_si.e2, 0);
}